// round 1
// baseline (speedup 1.0000x reference)
#include <cuda_runtime.h>
#include <math.h>
#include <stdint.h>

#define SEQ   4096
#define DIM   2048
#define NH    32
#define NKV   8
#define HD    64
#define ESTQ  64
#define VSZ   300
#define SSZ   800
#define NKEY  1100
#define NKEYP 1152
#define SCALE 0.125f   // 1/sqrt(64)

// ---------------- device scratch (no allocation allowed) ----------------
__device__ float g_q[SEQ * DIM];            // 32 MB  [s][h*64+d]
__device__ float g_k[SEQ * NKV * HD];       //  8 MB  [s][kvh*64+d]
__device__ float g_v[SEQ * NKV * HD];       //  8 MB
__device__ float g_probs[NH * ESTQ * SEQ];  // 32 MB  [h][qi][kk]
__device__ float g_vert[NH * SEQ];
__device__ float g_diag[NH * SEQ];
__device__ int   g_keys[NH * NKEYP];
__device__ float g_ksp[NH * NKEYP * HD];    // 9.4 MB
__device__ float g_vsp[NH * NKEYP * HD];    // 9.4 MB
__device__ float g_att[SEQ * DIM];          // 32 MB  [s][h*64+d]

// ---------------- fp32 SIMT GEMM: C[M,N] = A[M,K] @ B[K,N] --------------
// 128x128 block tile, BK=8, 256 threads, 8x8 per thread. M,N,K all %128/%8.
__global__ void sgemm128(const float* __restrict__ A, const float* __restrict__ B,
                         float* __restrict__ C, int M, int N, int K) {
    __shared__ float As[8][128];
    __shared__ float Bs[8][128];
    int tid = threadIdx.x;
    int row0 = blockIdx.y * 128;
    int col0 = blockIdx.x * 128;
    int aRow = tid >> 1;
    int aCol = (tid & 1) << 2;
    int bRow = tid >> 5;
    int bCol = (tid & 31) << 2;
    int ty = tid >> 4, tx = tid & 15;

    float acc[8][8];
#pragma unroll
    for (int i = 0; i < 8; i++)
#pragma unroll
        for (int j = 0; j < 8; j++) acc[i][j] = 0.f;

    for (int k0 = 0; k0 < K; k0 += 8) {
        float4 av = *(const float4*)(A + (size_t)(row0 + aRow) * K + k0 + aCol);
        As[aCol + 0][aRow] = av.x;
        As[aCol + 1][aRow] = av.y;
        As[aCol + 2][aRow] = av.z;
        As[aCol + 3][aRow] = av.w;
        float4 bv = *(const float4*)(B + (size_t)(k0 + bRow) * N + col0 + bCol);
        *(float4*)&Bs[bRow][bCol] = bv;
        __syncthreads();
#pragma unroll
        for (int kk = 0; kk < 8; kk++) {
            float4 a0 = *(float4*)&As[kk][ty * 8];
            float4 a1 = *(float4*)&As[kk][ty * 8 + 4];
            float4 b0 = *(float4*)&Bs[kk][tx * 8];
            float4 b1 = *(float4*)&Bs[kk][tx * 8 + 4];
            float a[8] = {a0.x, a0.y, a0.z, a0.w, a1.x, a1.y, a1.z, a1.w};
            float b[8] = {b0.x, b0.y, b0.z, b0.w, b1.x, b1.y, b1.z, b1.w};
#pragma unroll
            for (int i = 0; i < 8; i++)
#pragma unroll
                for (int j = 0; j < 8; j++) acc[i][j] += a[i] * b[j];
        }
        __syncthreads();
    }
#pragma unroll
    for (int i = 0; i < 8; i++) {
        float* cp = C + (size_t)(row0 + ty * 8 + i) * N + col0 + tx * 8;
        float4 o0 = {acc[i][0], acc[i][1], acc[i][2], acc[i][3]};
        float4 o1 = {acc[i][4], acc[i][5], acc[i][6], acc[i][7]};
        *(float4*)(cp) = o0;
        *(float4*)(cp + 4) = o1;
    }
}

// ---------------- RoPE in place on [S][H][64] ----------------------------
__global__ void rope_kernel(float* t, const float* __restrict__ cosb,
                            const float* __restrict__ sinb, int H, int total) {
    int idx = blockIdx.x * blockDim.x + threadIdx.x;
    if (idx >= total) return;
    int d2 = idx & 31;
    int h = (idx >> 5) % H;
    int s = idx / (32 * H);
    float c = cosb[s * 32 + d2];
    float sn = sinb[s * 32 + d2];
    float* p = t + ((size_t)s * H + h) * 64 + 2 * d2;
    float xr = p[0], xi = p[1];
    p[0] = xr * c - xi * sn;
    p[1] = xr * sn + xi * c;
}

// ---------------- estimation scores + softmax per (h, qi) row ------------
__global__ void est_softmax_kernel(const float* __restrict__ q,
                                   const float* __restrict__ k,
                                   float* __restrict__ probs) {
    int qi = blockIdx.x;  // 0..63
    int h = blockIdx.y;   // 0..31
    __shared__ float sc[SEQ];
    __shared__ float qs[HD];
    __shared__ float red[8];
    int tid = threadIdx.x;  // 256

    if (tid < HD) qs[tid] = q[(size_t)qi * DIM + h * HD + tid];
    __syncthreads();

    int kvh = h >> 2;
    for (int kk = tid; kk < SEQ; kk += 256) {
        const float* kr = k + (size_t)kk * (NKV * HD) + kvh * HD;
        float dot = 0.f;
#pragma unroll
        for (int d = 0; d < HD; d += 4) {
            float4 kv4 = *(const float4*)(kr + d);
            dot += qs[d] * kv4.x + qs[d + 1] * kv4.y + qs[d + 2] * kv4.z + qs[d + 3] * kv4.w;
        }
        float val = dot * SCALE;
        if (kk >= SEQ - ESTQ && qi < kk - (SEQ - ESTQ)) val = -INFINITY;
        sc[kk] = val;
    }
    __syncthreads();

    // block max
    float m = -INFINITY;
    for (int kk = tid; kk < SEQ; kk += 256) m = fmaxf(m, sc[kk]);
#pragma unroll
    for (int o = 16; o; o >>= 1) m = fmaxf(m, __shfl_xor_sync(0xFFFFFFFFu, m, o));
    if ((tid & 31) == 0) red[tid >> 5] = m;
    __syncthreads();
    if (tid == 0) {
        float mm = red[0];
#pragma unroll
        for (int i = 1; i < 8; i++) mm = fmaxf(mm, red[i]);
        red[0] = mm;
    }
    __syncthreads();
    m = red[0];
    __syncthreads();

    // exp + sum
    float s = 0.f;
    for (int kk = tid; kk < SEQ; kk += 256) {
        float e = expf(sc[kk] - m);
        sc[kk] = e;
        s += e;
    }
#pragma unroll
    for (int o = 16; o; o >>= 1) s += __shfl_xor_sync(0xFFFFFFFFu, s, o);
    if ((tid & 31) == 0) red[tid >> 5] = s;
    __syncthreads();
    if (tid == 0) {
        float ss = 0.f;
#pragma unroll
        for (int i = 0; i < 8; i++) ss += red[i];
        red[0] = ss;
    }
    __syncthreads();
    float inv = 1.f / red[0];

    float* pr = probs + ((size_t)h * ESTQ + qi) * SEQ;
    for (int kk = tid; kk < SEQ; kk += 256) pr[kk] = sc[kk] * inv;
}

// ---------------- vertical column sums -----------------------------------
__global__ void vertical_kernel(const float* __restrict__ probs, float* __restrict__ vert) {
    int idx = blockIdx.x * 256 + threadIdx.x;  // NH*SEQ
    int h = idx >> 12;
    int kk = idx & (SEQ - 1);
    float s = 0.f;
    const float* base = probs + (size_t)h * ESTQ * SEQ + kk;
    for (int i = 0; i < ESTQ; i++) s += base[(size_t)i * SEQ];
    vert[idx] = s;
}

// ---------------- diagonal sums: diag[j'] = sum_i P[i, i+j'-63] ----------
__global__ void diag_kernel(const float* __restrict__ probs, float* __restrict__ dg) {
    int idx = blockIdx.x * 256 + threadIdx.x;  // NH*SEQ
    int h = idx >> 12;
    int jp = idx & (SEQ - 1);
    float s = 0.f;
    const float* base = probs + (size_t)h * ESTQ * SEQ;
    for (int i = 0; i < ESTQ; i++) {
        int col = i + jp - 63;
        if (col >= 0 && col < SEQ) s += base[(size_t)i * SEQ + col];
    }
    dg[idx] = s;
}

// ---------------- per-head top-k via bitonic sort of (val,idx) -----------
// mode 0: write top-kcount indices at keys[h][0..)  (vertical)
// mode 1: write (S-1 - idx) at keys[h][300..), then pad [1100..1152) = -1
__global__ void topk_kernel(const float* __restrict__ vals, int kcount, int mode,
                            int* __restrict__ keys) {
    int h = blockIdx.x;
    __shared__ unsigned long long a[SEQ];
    int tid = threadIdx.x;  // 512
    for (int i = tid; i < SEQ; i += 512) {
        unsigned u = __float_as_uint(vals[h * SEQ + i]);
        u = (u & 0x80000000u) ? ~u : (u | 0x80000000u);  // monotone-increasing map
        a[i] = ((unsigned long long)(~u) << 32) | (unsigned)i;  // asc sort => desc val, asc idx
    }
    __syncthreads();
    for (int k = 2; k <= SEQ; k <<= 1) {
        for (int j = k >> 1; j > 0; j >>= 1) {
            for (int i = tid; i < SEQ; i += 512) {
                int ixj = i ^ j;
                if (ixj > i) {
                    bool up = ((i & k) == 0);
                    unsigned long long x = a[i], y = a[ixj];
                    if (up ? (x > y) : (x < y)) { a[i] = y; a[ixj] = x; }
                }
            }
            __syncthreads();
        }
    }
    if (mode == 0) {
        for (int t = tid; t < kcount; t += 512)
            keys[h * NKEYP + t] = (int)(a[t] & 0xFFFFFFFFull);
    } else {
        for (int t = tid; t < kcount; t += 512)
            keys[h * NKEYP + VSZ + t] = (SEQ - 1) - (int)(a[t] & 0xFFFFFFFFull);
        for (int t = NKEY + tid; t < NKEYP; t += 512) keys[h * NKEYP + t] = -1;
    }
}

// ---------------- gather sparse K/V rows ----------------------------------
__global__ void gather_kernel(const float* __restrict__ k, const float* __restrict__ v,
                              const int* __restrict__ keys,
                              float* __restrict__ ksp, float* __restrict__ vsp) {
    int j = blockIdx.x;  // NH*NKEYP
    int h = j / NKEYP;
    int d = threadIdx.x;  // 64
    int key = keys[j];
    int kvh = h >> 2;
    float kv = 0.f, vv = 0.f;
    if (key >= 0) {
        kv = k[(size_t)key * (NKV * HD) + kvh * HD + d];
        vv = v[(size_t)key * (NKV * HD) + kvh * HD + d];
    }
    ksp[(size_t)j * HD + d] = kv;
    vsp[(size_t)j * HD + d] = vv;
}

// ---------------- sparse attention (online softmax, 64q x 32k tiles) -----
__global__ void spattn_kernel(const float* __restrict__ q, const float* __restrict__ ksp,
                              const float* __restrict__ vsp, const int* __restrict__ keys,
                              float* __restrict__ attout) {
    int qb = blockIdx.x;  // 0..63
    int h = blockIdx.y;   // 0..31
    __shared__ float qs[64][65];
    __shared__ float ks[32][65];
    __shared__ float vs[32][65];
    __shared__ float ss[64][33];
    __shared__ int kid[32];
    int tid = threadIdx.x;  // 256
    int qi = tid >> 2, g = tid & 3;

    for (int l = tid; l < 64 * 64; l += 256) {
        int r = l >> 6, d = l & 63;
        qs[r][d] = q[(size_t)(qb * 64 + r) * DIM + h * HD + d];
    }

    float m = -INFINITY, lsum = 0.f;
    float out[16];
#pragma unroll
    for (int i = 0; i < 16; i++) out[i] = 0.f;
    int sglob = qb * 64 + qi;

    for (int t = 0; t < NKEYP / 32; t++) {
        __syncthreads();  // previous accumulation done before overwrite
        for (int l = tid; l < 32 * 64; l += 256) {
            int r = l >> 6, d = l & 63;
            ks[r][d] = ksp[((size_t)h * NKEYP + t * 32 + r) * HD + d];
            vs[r][d] = vsp[((size_t)h * NKEYP + t * 32 + r) * HD + d];
        }
        if (tid < 32) kid[tid] = keys[h * NKEYP + t * 32 + tid];
        __syncthreads();

        // 8 scores per thread: keys g*8 .. g*8+7
        float s8[8];
#pragma unroll
        for (int jj = 0; jj < 8; jj++) s8[jj] = 0.f;
        for (int d = 0; d < 64; d++) {
            float qd = qs[qi][d];
#pragma unroll
            for (int jj = 0; jj < 8; jj++) s8[jj] += qd * ks[g * 8 + jj][d];
        }
#pragma unroll
        for (int jj = 0; jj < 8; jj++) {
            int key = kid[g * 8 + jj];
            float val;
            if (key < 0) val = -INFINITY;           // pad: exact zero prob
            else if (key <= sglob) val = s8[jj] * SCALE;
            else val = -1e30f;                      // causal mask (matches ref)
            ss[qi][g * 8 + jj] = val;
        }
        __syncthreads();

        // per-query tile max (redundant across the 4 threads, identical result)
        float tm = m;
#pragma unroll
        for (int j = 0; j < 32; j++) tm = fmaxf(tm, ss[qi][j]);
        float corr = expf(m - tm);
        m = tm;
        lsum *= corr;
#pragma unroll
        for (int i = 0; i < 16; i++) out[i] *= corr;
        __syncthreads();  // everyone done reading raw scores

        // exp once per (q,k), store back
#pragma unroll
        for (int jj = 0; jj < 8; jj++) {
            float p = expf(ss[qi][g * 8 + jj] - m);
            ss[qi][g * 8 + jj] = p;
        }
        __syncthreads();

        float ps = 0.f;
        for (int j = 0; j < 32; j++) {
            float p = ss[qi][j];
            ps += p;
#pragma unroll
            for (int dd = 0; dd < 16; dd++) out[dd] += p * vs[j][g * 16 + dd];
        }
        lsum += ps;
    }

    float inv = 1.f / lsum;
#pragma unroll
    for (int dd = 0; dd < 16; dd++)
        attout[(size_t)sglob * DIM + h * HD + g * 16 + dd] = out[dd] * inv;
}

// --------------------------------- launch --------------------------------
extern "C" void kernel_launch(void* const* d_in, const int* in_sizes, int n_in,
                              void* d_out, int out_size) {
    const float* x    = (const float*)d_in[0];
    const float* fcos = (const float*)d_in[1];
    const float* fsin = (const float*)d_in[2];
    const float* wq   = (const float*)d_in[3];
    const float* wk   = (const float*)d_in[4];
    const float* wv   = (const float*)d_in[5];
    const float* wo   = (const float*)d_in[6];
    float* out = (float*)d_out;

    float *q, *k, *v, *probs, *vert, *dgp, *ksp, *vsp, *att;
    int* keys;
    cudaGetSymbolAddress((void**)&q, g_q);
    cudaGetSymbolAddress((void**)&k, g_k);
    cudaGetSymbolAddress((void**)&v, g_v);
    cudaGetSymbolAddress((void**)&probs, g_probs);
    cudaGetSymbolAddress((void**)&vert, g_vert);
    cudaGetSymbolAddress((void**)&dgp, g_diag);
    cudaGetSymbolAddress((void**)&keys, g_keys);
    cudaGetSymbolAddress((void**)&ksp, g_ksp);
    cudaGetSymbolAddress((void**)&vsp, g_vsp);
    cudaGetSymbolAddress((void**)&att, g_att);

    // projections
    sgemm128<<<dim3(DIM / 128, SEQ / 128), 256>>>(x, wq, q, SEQ, DIM, DIM);
    sgemm128<<<dim3((NKV * HD) / 128, SEQ / 128), 256>>>(x, wk, k, SEQ, NKV * HD, DIM);
    sgemm128<<<dim3((NKV * HD) / 128, SEQ / 128), 256>>>(x, wv, v, SEQ, NKV * HD, DIM);

    // RoPE
    {
        int tq = SEQ * NH * 32;
        rope_kernel<<<(tq + 255) / 256, 256>>>(q, fcos, fsin, NH, tq);
        int tk = SEQ * NKV * 32;
        rope_kernel<<<(tk + 255) / 256, 256>>>(k, fcos, fsin, NKV, tk);
    }

    // estimation probs
    est_softmax_kernel<<<dim3(ESTQ, NH), 256>>>(q, k, probs);

    // vertical / diagonal scores
    vertical_kernel<<<(NH * SEQ) / 256, 256>>>(probs, vert);
    diag_kernel<<<(NH * SEQ) / 256, 256>>>(probs, dgp);

    // top-k selections
    topk_kernel<<<NH, 512>>>(vert, VSZ, 0, keys);
    topk_kernel<<<NH, 512>>>(dgp, SSZ, 1, keys);

    // gather sparse K/V
    gather_kernel<<<NH * NKEYP, 64>>>(k, v, keys, ksp, vsp);

    // sparse attention
    spattn_kernel<<<dim3(SEQ / 64, NH), 256>>>(q, ksp, vsp, keys, att);

    // output projection
    sgemm128<<<dim3(DIM / 128, SEQ / 128), 256>>>(att, wo, out, SEQ, DIM, DIM);
}

// round 3
// speedup vs baseline: 1.0510x; 1.0510x over previous
#include <cuda_runtime.h>
#include <math.h>
#include <stdint.h>

#define SEQ   4096
#define DIM   2048
#define NH    32
#define NKV   8
#define HD    64
#define ESTQ  64
#define VSZ   300
#define SSZ   800
#define NKEY  1100
#define NKEYP 1152
#define SCALE 0.125f   // 1/sqrt(64)

// ---------------- device scratch (no allocation allowed) ----------------
__device__ float g_q[SEQ * DIM];            // 32 MB  [s][h*64+d]
__device__ float g_k[SEQ * NKV * HD];       //  8 MB  [s][kvh*64+d]
__device__ float g_v[SEQ * NKV * HD];       //  8 MB
__device__ float g_probs[NH * ESTQ * SEQ];  // 32 MB  [h][qi][kk]
__device__ float g_vert[NH * SEQ];
__device__ float g_diag[NH * SEQ];
__device__ int   g_keys[NH * NKEYP];
__device__ float g_ksp[NH * NKEYP * HD];    // 9.4 MB
__device__ float g_vsp[NH * NKEYP * HD];    // 9.4 MB
__device__ float g_att[SEQ * DIM];          // 32 MB  [s][h*64+d]

// ---------------- 3xTF32 tensor-core GEMM: C = A @ B ---------------------
// 128x128 block tile, BK=16, 256 threads (8 warps 4x2), warp tile 32x64,
// mma.sync.m16n8k8 tf32 with hi/lo split (3 MMAs) => ~fp32 accuracy.
__device__ __forceinline__ uint32_t f2tf32(float f) {
    uint32_t r;
    asm("cvt.rna.tf32.f32 %0, %1;" : "=r"(r) : "f"(f));
    return r;
}

__device__ __forceinline__ void mma_tf32(float c[4], const uint32_t a[4],
                                         uint32_t b0, uint32_t b1) {
    asm volatile(
        "mma.sync.aligned.m16n8k8.row.col.f32.tf32.tf32.f32 "
        "{%0,%1,%2,%3}, {%4,%5,%6,%7}, {%8,%9}, {%0,%1,%2,%3};\n"
        : "+f"(c[0]), "+f"(c[1]), "+f"(c[2]), "+f"(c[3])
        : "r"(a[0]), "r"(a[1]), "r"(a[2]), "r"(a[3]), "r"(b0), "r"(b1));
}

#define AS_ST 20    // 16 + 4 pad (u32)
#define BS_ST 132   // 128 + 4 pad (u32)

__global__ __launch_bounds__(256) void gemm_tf32x3(const float* __restrict__ A,
                                                   const float* __restrict__ B,
                                                   float* __restrict__ C,
                                                   int M, int N, int K) {
    __shared__ uint32_t AsH[128 * AS_ST];
    __shared__ uint32_t AsL[128 * AS_ST];
    __shared__ uint32_t BsH[16 * BS_ST];
    __shared__ uint32_t BsL[16 * BS_ST];
    int tid = threadIdx.x;
    int lane = tid & 31;
    int warp = tid >> 5;
    int wm = warp & 3;   // 32-row slab
    int wn = warp >> 2;  // 64-col slab
    int row0 = blockIdx.y * 128;
    int col0 = blockIdx.x * 128;

    float acc[2][8][4];
#pragma unroll
    for (int mi = 0; mi < 2; mi++)
#pragma unroll
        for (int nj = 0; nj < 8; nj++)
#pragma unroll
            for (int e = 0; e < 4; e++) acc[mi][nj][e] = 0.f;

    int lr = lane >> 2;  // 0..7
    int lc = lane & 3;   // 0..3

    for (int k0 = 0; k0 < K; k0 += 16) {
        // A tile 128x16 (hi/lo)
#pragma unroll
        for (int i = 0; i < 2; i++) {
            int f = i * 256 + tid;
            int r = f >> 2;
            int c = (f & 3) << 2;
            float4 v = *(const float4*)(A + (size_t)(row0 + r) * K + k0 + c);
            uint32_t* dh = &AsH[r * AS_ST + c];
            uint32_t* dl = &AsL[r * AS_ST + c];
            uint32_t h0 = f2tf32(v.x), h1 = f2tf32(v.y), h2 = f2tf32(v.z), h3 = f2tf32(v.w);
            dh[0] = h0; dh[1] = h1; dh[2] = h2; dh[3] = h3;
            dl[0] = f2tf32(v.x - __uint_as_float(h0));
            dl[1] = f2tf32(v.y - __uint_as_float(h1));
            dl[2] = f2tf32(v.z - __uint_as_float(h2));
            dl[3] = f2tf32(v.w - __uint_as_float(h3));
        }
        // B tile 16x128 (hi/lo)
#pragma unroll
        for (int i = 0; i < 2; i++) {
            int f = i * 256 + tid;
            int r = f >> 5;
            int c = (f & 31) << 2;
            float4 v = *(const float4*)(B + (size_t)(k0 + r) * N + col0 + c);
            uint32_t* dh = &BsH[r * BS_ST + c];
            uint32_t* dl = &BsL[r * BS_ST + c];
            uint32_t h0 = f2tf32(v.x), h1 = f2tf32(v.y), h2 = f2tf32(v.z), h3 = f2tf32(v.w);
            dh[0] = h0; dh[1] = h1; dh[2] = h2; dh[3] = h3;
            dl[0] = f2tf32(v.x - __uint_as_float(h0));
            dl[1] = f2tf32(v.y - __uint_as_float(h1));
            dl[2] = f2tf32(v.z - __uint_as_float(h2));
            dl[3] = f2tf32(v.w - __uint_as_float(h3));
        }
        __syncthreads();

#pragma unroll
        for (int ks = 0; ks < 2; ks++) {
            int kb = ks * 8;
            uint32_t aH[2][4], aL[2][4];
#pragma unroll
            for (int mi = 0; mi < 2; mi++) {
                int r = wm * 32 + mi * 16 + lr;
                aH[mi][0] = AsH[r * AS_ST + kb + lc];
                aH[mi][1] = AsH[(r + 8) * AS_ST + kb + lc];
                aH[mi][2] = AsH[r * AS_ST + kb + lc + 4];
                aH[mi][3] = AsH[(r + 8) * AS_ST + kb + lc + 4];
                aL[mi][0] = AsL[r * AS_ST + kb + lc];
                aL[mi][1] = AsL[(r + 8) * AS_ST + kb + lc];
                aL[mi][2] = AsL[r * AS_ST + kb + lc + 4];
                aL[mi][3] = AsL[(r + 8) * AS_ST + kb + lc + 4];
            }
#pragma unroll
            for (int nj = 0; nj < 8; nj++) {
                int c = wn * 64 + nj * 8 + lr;
                uint32_t b0h = BsH[(kb + lc) * BS_ST + c];
                uint32_t b1h = BsH[(kb + lc + 4) * BS_ST + c];
                uint32_t b0l = BsL[(kb + lc) * BS_ST + c];
                uint32_t b1l = BsL[(kb + lc + 4) * BS_ST + c];
#pragma unroll
                for (int mi = 0; mi < 2; mi++) {
                    mma_tf32(acc[mi][nj], aH[mi], b0h, b1h);  // hi*hi
                    mma_tf32(acc[mi][nj], aH[mi], b0l, b1l);  // hi*lo
                    mma_tf32(acc[mi][nj], aL[mi], b0h, b1h);  // lo*hi
                }
            }
        }
        __syncthreads();
    }

#pragma unroll
    for (int mi = 0; mi < 2; mi++) {
        int row = row0 + wm * 32 + mi * 16 + lr;
#pragma unroll
        for (int nj = 0; nj < 8; nj++) {
            int col = col0 + wn * 64 + nj * 8 + 2 * lc;
            float* cp0 = C + (size_t)row * N + col;
            cp0[0] = acc[mi][nj][0];
            cp0[1] = acc[mi][nj][1];
            float* cp1 = C + (size_t)(row + 8) * N + col;
            cp1[0] = acc[mi][nj][2];
            cp1[1] = acc[mi][nj][3];
        }
    }
}

// ---------------- RoPE in place on [S][H][64] ----------------------------
__global__ void rope_kernel(float* t, const float* __restrict__ cosb,
                            const float* __restrict__ sinb, int H, int total) {
    int idx = blockIdx.x * blockDim.x + threadIdx.x;
    if (idx >= total) return;
    int d2 = idx & 31;
    int h = (idx >> 5) % H;
    int s = idx / (32 * H);
    float c = cosb[s * 32 + d2];
    float sn = sinb[s * 32 + d2];
    float* p = t + ((size_t)s * H + h) * 64 + 2 * d2;
    float xr = p[0], xi = p[1];
    p[0] = xr * c - xi * sn;
    p[1] = xr * sn + xi * c;
}

// ---------------- estimation scores + softmax per (h, qi) row ------------
__global__ void est_softmax_kernel(const float* __restrict__ q,
                                   const float* __restrict__ k,
                                   float* __restrict__ probs) {
    int qi = blockIdx.x;  // 0..63
    int h = blockIdx.y;   // 0..31
    __shared__ float sc[SEQ];
    __shared__ float qs[HD];
    __shared__ float red[8];
    int tid = threadIdx.x;  // 256

    if (tid < HD) qs[tid] = q[(size_t)qi * DIM + h * HD + tid];
    __syncthreads();

    int kvh = h >> 2;
    for (int kk = tid; kk < SEQ; kk += 256) {
        const float* kr = k + (size_t)kk * (NKV * HD) + kvh * HD;
        float dot = 0.f;
#pragma unroll
        for (int d = 0; d < HD; d += 4) {
            float4 kv4 = *(const float4*)(kr + d);
            dot += qs[d] * kv4.x + qs[d + 1] * kv4.y + qs[d + 2] * kv4.z + qs[d + 3] * kv4.w;
        }
        float val = dot * SCALE;
        if (kk >= SEQ - ESTQ && qi < kk - (SEQ - ESTQ)) val = -INFINITY;
        sc[kk] = val;
    }
    __syncthreads();

    float m = -INFINITY;
    for (int kk = tid; kk < SEQ; kk += 256) m = fmaxf(m, sc[kk]);
#pragma unroll
    for (int o = 16; o; o >>= 1) m = fmaxf(m, __shfl_xor_sync(0xFFFFFFFFu, m, o));
    if ((tid & 31) == 0) red[tid >> 5] = m;
    __syncthreads();
    if (tid == 0) {
        float mm = red[0];
#pragma unroll
        for (int i = 1; i < 8; i++) mm = fmaxf(mm, red[i]);
        red[0] = mm;
    }
    __syncthreads();
    m = red[0];
    __syncthreads();

    float s = 0.f;
    for (int kk = tid; kk < SEQ; kk += 256) {
        float e = expf(sc[kk] - m);
        sc[kk] = e;
        s += e;
    }
#pragma unroll
    for (int o = 16; o; o >>= 1) s += __shfl_xor_sync(0xFFFFFFFFu, s, o);
    if ((tid & 31) == 0) red[tid >> 5] = s;
    __syncthreads();
    if (tid == 0) {
        float ss = 0.f;
#pragma unroll
        for (int i = 0; i < 8; i++) ss += red[i];
        red[0] = ss;
    }
    __syncthreads();
    float inv = 1.f / red[0];

    float* pr = probs + ((size_t)h * ESTQ + qi) * SEQ;
    for (int kk = tid; kk < SEQ; kk += 256) pr[kk] = sc[kk] * inv;
}

// ---------------- vertical column sums -----------------------------------
__global__ void vertical_kernel(const float* __restrict__ probs, float* __restrict__ vert) {
    int idx = blockIdx.x * 256 + threadIdx.x;  // NH*SEQ
    int h = idx >> 12;
    int kk = idx & (SEQ - 1);
    float s = 0.f;
    const float* base = probs + (size_t)h * ESTQ * SEQ + kk;
    for (int i = 0; i < ESTQ; i++) s += base[(size_t)i * SEQ];
    vert[idx] = s;
}

// ---------------- diagonal sums: diag[j'] = sum_i P[i, i+j'-63] ----------
__global__ void diag_kernel(const float* __restrict__ probs, float* __restrict__ dg) {
    int idx = blockIdx.x * 256 + threadIdx.x;  // NH*SEQ
    int h = idx >> 12;
    int jp = idx & (SEQ - 1);
    float s = 0.f;
    const float* base = probs + (size_t)h * ESTQ * SEQ;
    for (int i = 0; i < ESTQ; i++) {
        int col = i + jp - 63;
        if (col >= 0 && col < SEQ) s += base[(size_t)i * SEQ + col];
    }
    dg[idx] = s;
}

// ---------------- per-head top-k via bitonic sort of (val,idx) -----------
__global__ void topk_kernel(const float* __restrict__ vals, int kcount, int mode,
                            int* __restrict__ keys) {
    int h = blockIdx.x;
    __shared__ unsigned long long a[SEQ];
    int tid = threadIdx.x;  // 512
    for (int i = tid; i < SEQ; i += 512) {
        unsigned u = __float_as_uint(vals[h * SEQ + i]);
        u = (u & 0x80000000u) ? ~u : (u | 0x80000000u);
        a[i] = ((unsigned long long)(~u) << 32) | (unsigned)i;
    }
    __syncthreads();
    for (int k = 2; k <= SEQ; k <<= 1) {
        for (int j = k >> 1; j > 0; j >>= 1) {
            for (int i = tid; i < SEQ; i += 512) {
                int ixj = i ^ j;
                if (ixj > i) {
                    bool up = ((i & k) == 0);
                    unsigned long long x = a[i], y = a[ixj];
                    if (up ? (x > y) : (x < y)) { a[i] = y; a[ixj] = x; }
                }
            }
            __syncthreads();
        }
    }
    if (mode == 0) {
        for (int t = tid; t < kcount; t += 512)
            keys[h * NKEYP + t] = (int)(a[t] & 0xFFFFFFFFull);
    } else {
        for (int t = tid; t < kcount; t += 512)
            keys[h * NKEYP + VSZ + t] = (SEQ - 1) - (int)(a[t] & 0xFFFFFFFFull);
        for (int t = NKEY + tid; t < NKEYP; t += 512) keys[h * NKEYP + t] = -1;
    }
}

// ---------------- gather sparse K/V rows ----------------------------------
__global__ void gather_kernel(const float* __restrict__ k, const float* __restrict__ v,
                              const int* __restrict__ keys,
                              float* __restrict__ ksp, float* __restrict__ vsp) {
    int j = blockIdx.x;  // NH*NKEYP
    int h = j / NKEYP;
    int d = threadIdx.x;  // 64
    int key = keys[j];
    int kvh = h >> 2;
    float kv = 0.f, vv = 0.f;
    if (key >= 0) {
        kv = k[(size_t)key * (NKV * HD) + kvh * HD + d];
        vv = v[(size_t)key * (NKV * HD) + kvh * HD + d];
    }
    ksp[(size_t)j * HD + d] = kv;
    vsp[(size_t)j * HD + d] = vv;
}

// ---------------- sparse attention (online softmax, 64q x 32k tiles) -----
__global__ void spattn_kernel(const float* __restrict__ q, const float* __restrict__ ksp,
                              const float* __restrict__ vsp, const int* __restrict__ keys,
                              float* __restrict__ attout) {
    int qb = blockIdx.x;  // 0..63
    int h = blockIdx.y;   // 0..31
    __shared__ float qs[64][65];
    __shared__ float ks[32][65];
    __shared__ float vs[32][65];
    __shared__ float ss[64][33];
    __shared__ int kid[32];
    int tid = threadIdx.x;  // 256
    int qi = tid >> 2, g = tid & 3;

    for (int l = tid; l < 64 * 64; l += 256) {
        int r = l >> 6, d = l & 63;
        qs[r][d] = q[(size_t)(qb * 64 + r) * DIM + h * HD + d];
    }

    float m = -INFINITY, lsum = 0.f;
    float out[16];
#pragma unroll
    for (int i = 0; i < 16; i++) out[i] = 0.f;
    int sglob = qb * 64 + qi;

    for (int t = 0; t < NKEYP / 32; t++) {
        __syncthreads();
        for (int l = tid; l < 32 * 64; l += 256) {
            int r = l >> 6, d = l & 63;
            ks[r][d] = ksp[((size_t)h * NKEYP + t * 32 + r) * HD + d];
            vs[r][d] = vsp[((size_t)h * NKEYP + t * 32 + r) * HD + d];
        }
        if (tid < 32) kid[tid] = keys[h * NKEYP + t * 32 + tid];
        __syncthreads();

        float s8[8];
#pragma unroll
        for (int jj = 0; jj < 8; jj++) s8[jj] = 0.f;
        for (int d = 0; d < 64; d++) {
            float qd = qs[qi][d];
#pragma unroll
            for (int jj = 0; jj < 8; jj++) s8[jj] += qd * ks[g * 8 + jj][d];
        }
#pragma unroll
        for (int jj = 0; jj < 8; jj++) {
            int key = kid[g * 8 + jj];
            float val;
            if (key < 0) val = -INFINITY;
            else if (key <= sglob) val = s8[jj] * SCALE;
            else val = -1e30f;
            ss[qi][g * 8 + jj] = val;
        }
        __syncthreads();

        float tm = m;
#pragma unroll
        for (int j = 0; j < 32; j++) tm = fmaxf(tm, ss[qi][j]);
        float corr = expf(m - tm);
        m = tm;
        lsum *= corr;
#pragma unroll
        for (int i = 0; i < 16; i++) out[i] *= corr;
        __syncthreads();

#pragma unroll
        for (int jj = 0; jj < 8; jj++) {
            float p = expf(ss[qi][g * 8 + jj] - m);
            ss[qi][g * 8 + jj] = p;
        }
        __syncthreads();

        float ps = 0.f;
        for (int j = 0; j < 32; j++) {
            float p = ss[qi][j];
            ps += p;
#pragma unroll
            for (int dd = 0; dd < 16; dd++) out[dd] += p * vs[j][g * 16 + dd];
        }
        lsum += ps;
    }

    float inv = 1.f / lsum;
#pragma unroll
    for (int dd = 0; dd < 16; dd++)
        attout[(size_t)sglob * DIM + h * HD + g * 16 + dd] = out[dd] * inv;
}

// --------------------------------- launch --------------------------------
extern "C" void kernel_launch(void* const* d_in, const int* in_sizes, int n_in,
                              void* d_out, int out_size) {
    const float* x    = (const float*)d_in[0];
    const float* fcos = (const float*)d_in[1];
    const float* fsin = (const float*)d_in[2];
    const float* wq   = (const float*)d_in[3];
    const float* wk   = (const float*)d_in[4];
    const float* wv   = (const float*)d_in[5];
    const float* wo   = (const float*)d_in[6];
    float* out = (float*)d_out;

    float *q, *k, *v, *probs, *vert, *dgp, *ksp, *vsp, *att;
    int* keys;
    cudaGetSymbolAddress((void**)&q, g_q);
    cudaGetSymbolAddress((void**)&k, g_k);
    cudaGetSymbolAddress((void**)&v, g_v);
    cudaGetSymbolAddress((void**)&probs, g_probs);
    cudaGetSymbolAddress((void**)&vert, g_vert);
    cudaGetSymbolAddress((void**)&dgp, g_diag);
    cudaGetSymbolAddress((void**)&keys, g_keys);
    cudaGetSymbolAddress((void**)&ksp, g_ksp);
    cudaGetSymbolAddress((void**)&vsp, g_vsp);
    cudaGetSymbolAddress((void**)&att, g_att);

    // projections (3xTF32 tensor cores, ~fp32 accuracy)
    gemm_tf32x3<<<dim3(DIM / 128, SEQ / 128), 256>>>(x, wq, q, SEQ, DIM, DIM);
    gemm_tf32x3<<<dim3((NKV * HD) / 128, SEQ / 128), 256>>>(x, wk, k, SEQ, NKV * HD, DIM);
    gemm_tf32x3<<<dim3((NKV * HD) / 128, SEQ / 128), 256>>>(x, wv, v, SEQ, NKV * HD, DIM);

    // RoPE
    {
        int tq = SEQ * NH * 32;
        rope_kernel<<<(tq + 255) / 256, 256>>>(q, fcos, fsin, NH, tq);
        int tk = SEQ * NKV * 32;
        rope_kernel<<<(tk + 255) / 256, 256>>>(k, fcos, fsin, NKV, tk);
    }

    // estimation probs
    est_softmax_kernel<<<dim3(ESTQ, NH), 256>>>(q, k, probs);

    // vertical / diagonal scores
    vertical_kernel<<<(NH * SEQ) / 256, 256>>>(probs, vert);
    diag_kernel<<<(NH * SEQ) / 256, 256>>>(probs, dgp);

    // top-k selections
    topk_kernel<<<NH, 512>>>(vert, VSZ, 0, keys);
    topk_kernel<<<NH, 512>>>(dgp, SSZ, 1, keys);

    // gather sparse K/V
    gather_kernel<<<NH * NKEYP, 64>>>(k, v, keys, ksp, vsp);

    // sparse attention
    spattn_kernel<<<dim3(SEQ / 64, NH), 256>>>(q, ksp, vsp, keys, att);

    // output projection (3xTF32 tensor cores)
    gemm_tf32x3<<<dim3(DIM / 128, SEQ / 128), 256>>>(att, wo, out, SEQ, DIM, DIM);
}

// round 4
// speedup vs baseline: 1.2435x; 1.1831x over previous
#include <cuda_runtime.h>
#include <math.h>
#include <stdint.h>

#define SEQ   4096
#define DIM   2048
#define NH    32
#define NKV   8
#define HD    64
#define ESTQ  64
#define VSZ   300
#define SSZ   800
#define NKEY  1100
#define NKEYP 1152
#define SCALE 0.125f   // 1/sqrt(64)

// ---------------- device scratch (no allocation allowed) ----------------
__device__ float g_q[SEQ * DIM];            // 32 MB  [s][h*64+d]  (tf32-accurate)
__device__ float g_q64[ESTQ * DIM];         // exact fp32 q for estimation rows
__device__ float g_k[SEQ * NKV * HD];       //  8 MB  (3xTF32-accurate)
__device__ float g_v[SEQ * NKV * HD];       //  8 MB
__device__ float g_probs[NH * ESTQ * SEQ];  // 32 MB
__device__ float g_vert[NH * SEQ];
__device__ float g_diag[NH * SEQ];
__device__ int   g_keys[NH * NKEYP];
__device__ float g_ksp[NH * NKEYP * HD];
__device__ float g_vsp[NH * NKEYP * HD];
__device__ float g_att[SEQ * DIM];

// ---------------- common tf32 helpers ------------------------------------
__device__ __forceinline__ uint32_t f2tf32(float f) {
    uint32_t r;
    asm("cvt.rna.tf32.f32 %0, %1;" : "=r"(r) : "f"(f));
    return r;
}

__device__ __forceinline__ void mma_tf32(float c[4], const uint32_t a[4],
                                         uint32_t b0, uint32_t b1) {
    asm volatile(
        "mma.sync.aligned.m16n8k8.row.col.f32.tf32.tf32.f32 "
        "{%0,%1,%2,%3}, {%4,%5,%6,%7}, {%8,%9}, {%0,%1,%2,%3};\n"
        : "+f"(c[0]), "+f"(c[1]), "+f"(c[2]), "+f"(c[3])
        : "r"(a[0]), "r"(a[1]), "r"(a[2]), "r"(a[3]), "r"(b0), "r"(b1));
}

// ================= single-pass tf32 GEMM (BK=32) ==========================
#define A1_ST 36
#define B1_ST 132

__global__ __launch_bounds__(256) void gemm_tf32_1x(const float* __restrict__ A,
                                                    const float* __restrict__ B,
                                                    float* __restrict__ C,
                                                    int M, int N, int K) {
    __shared__ uint32_t As[128 * A1_ST];
    __shared__ uint32_t Bs[32 * B1_ST];
    int tid = threadIdx.x;
    int lane = tid & 31;
    int warp = tid >> 5;
    int wm = warp & 3;
    int wn = warp >> 2;
    int row0 = blockIdx.y * 128;
    int col0 = blockIdx.x * 128;

    float acc[2][8][4];
#pragma unroll
    for (int mi = 0; mi < 2; mi++)
#pragma unroll
        for (int nj = 0; nj < 8; nj++)
#pragma unroll
            for (int e = 0; e < 4; e++) acc[mi][nj][e] = 0.f;

    int lr = lane >> 2;
    int lc = lane & 3;

    for (int k0 = 0; k0 < K; k0 += 32) {
#pragma unroll
        for (int i = 0; i < 4; i++) {
            int f = i * 256 + tid;
            int r = f >> 3;
            int c = (f & 7) << 2;
            float4 v = *(const float4*)(A + (size_t)(row0 + r) * K + k0 + c);
            uint32_t* dst = &As[r * A1_ST + c];
            dst[0] = f2tf32(v.x);
            dst[1] = f2tf32(v.y);
            dst[2] = f2tf32(v.z);
            dst[3] = f2tf32(v.w);
        }
#pragma unroll
        for (int i = 0; i < 4; i++) {
            int f = i * 256 + tid;
            int r = f >> 5;
            int c = (f & 31) << 2;
            float4 v = *(const float4*)(B + (size_t)(k0 + r) * N + col0 + c);
            uint32_t* dst = &Bs[r * B1_ST + c];
            dst[0] = f2tf32(v.x);
            dst[1] = f2tf32(v.y);
            dst[2] = f2tf32(v.z);
            dst[3] = f2tf32(v.w);
        }
        __syncthreads();

#pragma unroll
        for (int ks = 0; ks < 4; ks++) {
            int kb = ks * 8;
            uint32_t a[2][4];
#pragma unroll
            for (int mi = 0; mi < 2; mi++) {
                int r = wm * 32 + mi * 16 + lr;
                a[mi][0] = As[r * A1_ST + kb + lc];
                a[mi][1] = As[(r + 8) * A1_ST + kb + lc];
                a[mi][2] = As[r * A1_ST + kb + lc + 4];
                a[mi][3] = As[(r + 8) * A1_ST + kb + lc + 4];
            }
#pragma unroll
            for (int nj = 0; nj < 8; nj++) {
                int c = wn * 64 + nj * 8 + lr;
                uint32_t b0 = Bs[(kb + lc) * B1_ST + c];
                uint32_t b1 = Bs[(kb + lc + 4) * B1_ST + c];
                mma_tf32(acc[0][nj], a[0], b0, b1);
                mma_tf32(acc[1][nj], a[1], b0, b1);
            }
        }
        __syncthreads();
    }

#pragma unroll
    for (int mi = 0; mi < 2; mi++) {
        int row = row0 + wm * 32 + mi * 16 + lr;
#pragma unroll
        for (int nj = 0; nj < 8; nj++) {
            int col = col0 + wn * 64 + nj * 8 + 2 * lc;
            float* cp0 = C + (size_t)row * N + col;
            cp0[0] = acc[mi][nj][0];
            cp0[1] = acc[mi][nj][1];
            float* cp1 = C + (size_t)(row + 8) * N + col;
            cp1[0] = acc[mi][nj][2];
            cp1[1] = acc[mi][nj][3];
        }
    }
}

// ================= 3xTF32 GEMM (BK=16), ~fp32 accuracy (for k-proj) =======
#define AS_ST 20
#define BS_ST 132

__global__ __launch_bounds__(256) void gemm_tf32x3(const float* __restrict__ A,
                                                   const float* __restrict__ B,
                                                   float* __restrict__ C,
                                                   int M, int N, int K) {
    __shared__ uint32_t AsH[128 * AS_ST];
    __shared__ uint32_t AsL[128 * AS_ST];
    __shared__ uint32_t BsH[16 * BS_ST];
    __shared__ uint32_t BsL[16 * BS_ST];
    int tid = threadIdx.x;
    int lane = tid & 31;
    int warp = tid >> 5;
    int wm = warp & 3;
    int wn = warp >> 2;
    int row0 = blockIdx.y * 128;
    int col0 = blockIdx.x * 128;

    float acc[2][8][4];
#pragma unroll
    for (int mi = 0; mi < 2; mi++)
#pragma unroll
        for (int nj = 0; nj < 8; nj++)
#pragma unroll
            for (int e = 0; e < 4; e++) acc[mi][nj][e] = 0.f;

    int lr = lane >> 2;
    int lc = lane & 3;

    for (int k0 = 0; k0 < K; k0 += 16) {
#pragma unroll
        for (int i = 0; i < 2; i++) {
            int f = i * 256 + tid;
            int r = f >> 2;
            int c = (f & 3) << 2;
            float4 v = *(const float4*)(A + (size_t)(row0 + r) * K + k0 + c);
            uint32_t* dh = &AsH[r * AS_ST + c];
            uint32_t* dl = &AsL[r * AS_ST + c];
            uint32_t h0 = f2tf32(v.x), h1 = f2tf32(v.y), h2 = f2tf32(v.z), h3 = f2tf32(v.w);
            dh[0] = h0; dh[1] = h1; dh[2] = h2; dh[3] = h3;
            dl[0] = f2tf32(v.x - __uint_as_float(h0));
            dl[1] = f2tf32(v.y - __uint_as_float(h1));
            dl[2] = f2tf32(v.z - __uint_as_float(h2));
            dl[3] = f2tf32(v.w - __uint_as_float(h3));
        }
#pragma unroll
        for (int i = 0; i < 2; i++) {
            int f = i * 256 + tid;
            int r = f >> 5;
            int c = (f & 31) << 2;
            float4 v = *(const float4*)(B + (size_t)(k0 + r) * N + col0 + c);
            uint32_t* dh = &BsH[r * BS_ST + c];
            uint32_t* dl = &BsL[r * BS_ST + c];
            uint32_t h0 = f2tf32(v.x), h1 = f2tf32(v.y), h2 = f2tf32(v.z), h3 = f2tf32(v.w);
            dh[0] = h0; dh[1] = h1; dh[2] = h2; dh[3] = h3;
            dl[0] = f2tf32(v.x - __uint_as_float(h0));
            dl[1] = f2tf32(v.y - __uint_as_float(h1));
            dl[2] = f2tf32(v.z - __uint_as_float(h2));
            dl[3] = f2tf32(v.w - __uint_as_float(h3));
        }
        __syncthreads();

#pragma unroll
        for (int ks = 0; ks < 2; ks++) {
            int kb = ks * 8;
            uint32_t aH[2][4], aL[2][4];
#pragma unroll
            for (int mi = 0; mi < 2; mi++) {
                int r = wm * 32 + mi * 16 + lr;
                aH[mi][0] = AsH[r * AS_ST + kb + lc];
                aH[mi][1] = AsH[(r + 8) * AS_ST + kb + lc];
                aH[mi][2] = AsH[r * AS_ST + kb + lc + 4];
                aH[mi][3] = AsH[(r + 8) * AS_ST + kb + lc + 4];
                aL[mi][0] = AsL[r * AS_ST + kb + lc];
                aL[mi][1] = AsL[(r + 8) * AS_ST + kb + lc];
                aL[mi][2] = AsL[r * AS_ST + kb + lc + 4];
                aL[mi][3] = AsL[(r + 8) * AS_ST + kb + lc + 4];
            }
#pragma unroll
            for (int nj = 0; nj < 8; nj++) {
                int c = wn * 64 + nj * 8 + lr;
                uint32_t b0h = BsH[(kb + lc) * BS_ST + c];
                uint32_t b1h = BsH[(kb + lc + 4) * BS_ST + c];
                uint32_t b0l = BsL[(kb + lc) * BS_ST + c];
                uint32_t b1l = BsL[(kb + lc + 4) * BS_ST + c];
#pragma unroll
                for (int mi = 0; mi < 2; mi++) {
                    mma_tf32(acc[mi][nj], aH[mi], b0h, b1h);
                    mma_tf32(acc[mi][nj], aH[mi], b0l, b1l);
                    mma_tf32(acc[mi][nj], aL[mi], b0h, b1h);
                }
            }
        }
        __syncthreads();
    }

#pragma unroll
    for (int mi = 0; mi < 2; mi++) {
        int row = row0 + wm * 32 + mi * 16 + lr;
#pragma unroll
        for (int nj = 0; nj < 8; nj++) {
            int col = col0 + wn * 64 + nj * 8 + 2 * lc;
            float* cp0 = C + (size_t)row * N + col;
            cp0[0] = acc[mi][nj][0];
            cp0[1] = acc[mi][nj][1];
            float* cp1 = C + (size_t)(row + 8) * N + col;
            cp1[0] = acc[mi][nj][2];
            cp1[1] = acc[mi][nj][3];
        }
    }
}

// ---------------- exact fp32 projection for q rows 0..63 ------------------
// grid (N/128, 64/8), block 128: each block -> 8 rows x 128 cols, K=DIM
__global__ __launch_bounds__(128) void qproj_exact64(const float* __restrict__ x,
                                                     const float* __restrict__ wq,
                                                     float* __restrict__ q64) {
    __shared__ float xs[8][256];
    int tid = threadIdx.x;
    int col = blockIdx.x * 128 + tid;
    int r0 = blockIdx.y * 8;
    float acc[8];
#pragma unroll
    for (int rr = 0; rr < 8; rr++) acc[rr] = 0.f;

    for (int k0 = 0; k0 < DIM; k0 += 256) {
        for (int i = tid; i < 8 * 256; i += 128) {
            int rr = i >> 8, kk = i & 255;
            xs[rr][kk] = x[(size_t)(r0 + rr) * DIM + k0 + kk];
        }
        __syncthreads();
        for (int kk = 0; kk < 256; kk++) {
            float w = wq[(size_t)(k0 + kk) * DIM + col];
#pragma unroll
            for (int rr = 0; rr < 8; rr++) acc[rr] += xs[rr][kk] * w;
        }
        __syncthreads();
    }
#pragma unroll
    for (int rr = 0; rr < 8; rr++) q64[(size_t)(r0 + rr) * DIM + col] = acc[rr];
}

// ---------------- RoPE in place on [S][H][64] ----------------------------
__global__ void rope_kernel(float* t, const float* __restrict__ cosb,
                            const float* __restrict__ sinb, int H, int total) {
    int idx = blockIdx.x * blockDim.x + threadIdx.x;
    if (idx >= total) return;
    int d2 = idx & 31;
    int h = (idx >> 5) % H;
    int s = idx / (32 * H);
    float c = cosb[s * 32 + d2];
    float sn = sinb[s * 32 + d2];
    float* p = t + ((size_t)s * H + h) * 64 + 2 * d2;
    float xr = p[0], xi = p[1];
    p[0] = xr * c - xi * sn;
    p[1] = xr * sn + xi * c;
}

// ---------------- estimation scores + softmax per (h, qi) row ------------
__global__ void est_softmax_kernel(const float* __restrict__ q,
                                   const float* __restrict__ k,
                                   float* __restrict__ probs) {
    int qi = blockIdx.x;
    int h = blockIdx.y;
    __shared__ float sc[SEQ];
    __shared__ float qs[HD];
    __shared__ float red[8];
    int tid = threadIdx.x;  // 256

    if (tid < HD) qs[tid] = q[(size_t)qi * DIM + h * HD + tid];
    __syncthreads();

    int kvh = h >> 2;
    for (int kk = tid; kk < SEQ; kk += 256) {
        const float* kr = k + (size_t)kk * (NKV * HD) + kvh * HD;
        float dot = 0.f;
#pragma unroll
        for (int d = 0; d < HD; d += 4) {
            float4 kv4 = *(const float4*)(kr + d);
            dot += qs[d] * kv4.x + qs[d + 1] * kv4.y + qs[d + 2] * kv4.z + qs[d + 3] * kv4.w;
        }
        float val = dot * SCALE;
        if (kk >= SEQ - ESTQ && qi < kk - (SEQ - ESTQ)) val = -INFINITY;
        sc[kk] = val;
    }
    __syncthreads();

    float m = -INFINITY;
    for (int kk = tid; kk < SEQ; kk += 256) m = fmaxf(m, sc[kk]);
#pragma unroll
    for (int o = 16; o; o >>= 1) m = fmaxf(m, __shfl_xor_sync(0xFFFFFFFFu, m, o));
    if ((tid & 31) == 0) red[tid >> 5] = m;
    __syncthreads();
    if (tid == 0) {
        float mm = red[0];
#pragma unroll
        for (int i = 1; i < 8; i++) mm = fmaxf(mm, red[i]);
        red[0] = mm;
    }
    __syncthreads();
    m = red[0];
    __syncthreads();

    float s = 0.f;
    for (int kk = tid; kk < SEQ; kk += 256) {
        float e = expf(sc[kk] - m);
        sc[kk] = e;
        s += e;
    }
#pragma unroll
    for (int o = 16; o; o >>= 1) s += __shfl_xor_sync(0xFFFFFFFFu, s, o);
    if ((tid & 31) == 0) red[tid >> 5] = s;
    __syncthreads();
    if (tid == 0) {
        float ss = 0.f;
#pragma unroll
        for (int i = 0; i < 8; i++) ss += red[i];
        red[0] = ss;
    }
    __syncthreads();
    float inv = 1.f / red[0];

    float* pr = probs + ((size_t)h * ESTQ + qi) * SEQ;
    for (int kk = tid; kk < SEQ; kk += 256) pr[kk] = sc[kk] * inv;
}

// ---------------- vertical column sums -----------------------------------
__global__ void vertical_kernel(const float* __restrict__ probs, float* __restrict__ vert) {
    int idx = blockIdx.x * 256 + threadIdx.x;
    int h = idx >> 12;
    int kk = idx & (SEQ - 1);
    float s = 0.f;
    const float* base = probs + (size_t)h * ESTQ * SEQ + kk;
    for (int i = 0; i < ESTQ; i++) s += base[(size_t)i * SEQ];
    vert[idx] = s;
}

// ---------------- diagonal sums ------------------------------------------
__global__ void diag_kernel(const float* __restrict__ probs, float* __restrict__ dg) {
    int idx = blockIdx.x * 256 + threadIdx.x;
    int h = idx >> 12;
    int jp = idx & (SEQ - 1);
    float s = 0.f;
    const float* base = probs + (size_t)h * ESTQ * SEQ;
    for (int i = 0; i < ESTQ; i++) {
        int col = i + jp - 63;
        if (col >= 0 && col < SEQ) s += base[(size_t)i * SEQ + col];
    }
    dg[idx] = s;
}

// ---------------- per-head top-k via bitonic sort -------------------------
__global__ void topk_kernel(const float* __restrict__ vals, int kcount, int mode,
                            int* __restrict__ keys) {
    int h = blockIdx.x;
    __shared__ unsigned long long a[SEQ];
    int tid = threadIdx.x;  // 512
    for (int i = tid; i < SEQ; i += 512) {
        unsigned u = __float_as_uint(vals[h * SEQ + i]);
        u = (u & 0x80000000u) ? ~u : (u | 0x80000000u);
        a[i] = ((unsigned long long)(~u) << 32) | (unsigned)i;
    }
    __syncthreads();
    for (int k = 2; k <= SEQ; k <<= 1) {
        for (int j = k >> 1; j > 0; j >>= 1) {
            for (int i = tid; i < SEQ; i += 512) {
                int ixj = i ^ j;
                if (ixj > i) {
                    bool up = ((i & k) == 0);
                    unsigned long long x = a[i], y = a[ixj];
                    if (up ? (x > y) : (x < y)) { a[i] = y; a[ixj] = x; }
                }
            }
            __syncthreads();
        }
    }
    if (mode == 0) {
        for (int t = tid; t < kcount; t += 512)
            keys[h * NKEYP + t] = (int)(a[t] & 0xFFFFFFFFull);
    } else {
        for (int t = tid; t < kcount; t += 512)
            keys[h * NKEYP + VSZ + t] = (SEQ - 1) - (int)(a[t] & 0xFFFFFFFFull);
        for (int t = NKEY + tid; t < NKEYP; t += 512) keys[h * NKEYP + t] = -1;
    }
}

// ---------------- gather sparse K/V rows ----------------------------------
__global__ void gather_kernel(const float* __restrict__ k, const float* __restrict__ v,
                              const int* __restrict__ keys,
                              float* __restrict__ ksp, float* __restrict__ vsp) {
    int j = blockIdx.x;
    int h = j / NKEYP;
    int d = threadIdx.x;
    int key = keys[j];
    int kvh = h >> 2;
    float kv = 0.f, vv = 0.f;
    if (key >= 0) {
        kv = k[(size_t)key * (NKV * HD) + kvh * HD + d];
        vv = v[(size_t)key * (NKV * HD) + kvh * HD + d];
    }
    ksp[(size_t)j * HD + d] = kv;
    vsp[(size_t)j * HD + d] = vv;
}

// ---------------- sparse attention (online softmax, 64q x 32k tiles) -----
__global__ void spattn_kernel(const float* __restrict__ q, const float* __restrict__ ksp,
                              const float* __restrict__ vsp, const int* __restrict__ keys,
                              float* __restrict__ attout) {
    int qb = blockIdx.x;
    int h = blockIdx.y;
    __shared__ float qs[64][65];
    __shared__ float ks[32][65];
    __shared__ float vs[32][65];
    __shared__ float ss[64][33];
    __shared__ int kid[32];
    int tid = threadIdx.x;  // 256
    int qi = tid >> 2, g = tid & 3;

    for (int l = tid; l < 64 * 64; l += 256) {
        int r = l >> 6, d = l & 63;
        qs[r][d] = q[(size_t)(qb * 64 + r) * DIM + h * HD + d];
    }

    float m = -INFINITY, lsum = 0.f;
    float out[16];
#pragma unroll
    for (int i = 0; i < 16; i++) out[i] = 0.f;
    int sglob = qb * 64 + qi;

    for (int t = 0; t < NKEYP / 32; t++) {
        __syncthreads();
        for (int l = tid; l < 32 * 64; l += 256) {
            int r = l >> 6, d = l & 63;
            ks[r][d] = ksp[((size_t)h * NKEYP + t * 32 + r) * HD + d];
            vs[r][d] = vsp[((size_t)h * NKEYP + t * 32 + r) * HD + d];
        }
        if (tid < 32) kid[tid] = keys[h * NKEYP + t * 32 + tid];
        __syncthreads();

        float s8[8];
#pragma unroll
        for (int jj = 0; jj < 8; jj++) s8[jj] = 0.f;
        for (int d = 0; d < 64; d++) {
            float qd = qs[qi][d];
#pragma unroll
            for (int jj = 0; jj < 8; jj++) s8[jj] += qd * ks[g * 8 + jj][d];
        }
#pragma unroll
        for (int jj = 0; jj < 8; jj++) {
            int key = kid[g * 8 + jj];
            float val;
            if (key < 0) val = -INFINITY;
            else if (key <= sglob) val = s8[jj] * SCALE;
            else val = -1e30f;
            ss[qi][g * 8 + jj] = val;
        }
        __syncthreads();

        float tm = m;
#pragma unroll
        for (int j = 0; j < 32; j++) tm = fmaxf(tm, ss[qi][j]);
        float corr = expf(m - tm);
        m = tm;
        lsum *= corr;
#pragma unroll
        for (int i = 0; i < 16; i++) out[i] *= corr;
        __syncthreads();

#pragma unroll
        for (int jj = 0; jj < 8; jj++) {
            float p = expf(ss[qi][g * 8 + jj] - m);
            ss[qi][g * 8 + jj] = p;
        }
        __syncthreads();

        float ps = 0.f;
        for (int j = 0; j < 32; j++) {
            float p = ss[qi][j];
            ps += p;
#pragma unroll
            for (int dd = 0; dd < 16; dd++) out[dd] += p * vs[j][g * 16 + dd];
        }
        lsum += ps;
    }

    float inv = 1.f / lsum;
#pragma unroll
    for (int dd = 0; dd < 16; dd++)
        attout[(size_t)sglob * DIM + h * HD + g * 16 + dd] = out[dd] * inv;
}

// --------------------------------- launch --------------------------------
extern "C" void kernel_launch(void* const* d_in, const int* in_sizes, int n_in,
                              void* d_out, int out_size) {
    const float* x    = (const float*)d_in[0];
    const float* fcos = (const float*)d_in[1];
    const float* fsin = (const float*)d_in[2];
    const float* wq   = (const float*)d_in[3];
    const float* wk   = (const float*)d_in[4];
    const float* wv   = (const float*)d_in[5];
    const float* wo   = (const float*)d_in[6];
    float* out = (float*)d_out;

    float *q, *q64, *k, *v, *probs, *vert, *dgp, *ksp, *vsp, *att;
    int* keys;
    cudaGetSymbolAddress((void**)&q, g_q);
    cudaGetSymbolAddress((void**)&q64, g_q64);
    cudaGetSymbolAddress((void**)&k, g_k);
    cudaGetSymbolAddress((void**)&v, g_v);
    cudaGetSymbolAddress((void**)&probs, g_probs);
    cudaGetSymbolAddress((void**)&vert, g_vert);
    cudaGetSymbolAddress((void**)&dgp, g_diag);
    cudaGetSymbolAddress((void**)&keys, g_keys);
    cudaGetSymbolAddress((void**)&ksp, g_ksp);
    cudaGetSymbolAddress((void**)&vsp, g_vsp);
    cudaGetSymbolAddress((void**)&att, g_att);

    // projections: q/v single-pass tf32, k 3xTF32 (selection accuracy)
    gemm_tf32_1x<<<dim3(DIM / 128, SEQ / 128), 256>>>(x, wq, q, SEQ, DIM, DIM);
    gemm_tf32x3<<<dim3((NKV * HD) / 128, SEQ / 128), 256>>>(x, wk, k, SEQ, NKV * HD, DIM);
    gemm_tf32_1x<<<dim3((NKV * HD) / 128, SEQ / 128), 256>>>(x, wv, v, SEQ, NKV * HD, DIM);

    // exact fp32 q for estimation rows 0..63
    qproj_exact64<<<dim3(DIM / 128, ESTQ / 8), 128>>>(x, wq, q64);

    // RoPE
    {
        int tq = SEQ * NH * 32;
        rope_kernel<<<(tq + 255) / 256, 256>>>(q, fcos, fsin, NH, tq);
        int tk = SEQ * NKV * 32;
        rope_kernel<<<(tk + 255) / 256, 256>>>(k, fcos, fsin, NKV, tk);
        int tq64 = ESTQ * NH * 32;
        rope_kernel<<<(tq64 + 255) / 256, 256>>>(q64, fcos, fsin, NH, tq64);
    }

    // estimation probs from exact q64 + accurate k
    est_softmax_kernel<<<dim3(ESTQ, NH), 256>>>(q64, k, probs);

    // vertical / diagonal scores
    vertical_kernel<<<(NH * SEQ) / 256, 256>>>(probs, vert);
    diag_kernel<<<(NH * SEQ) / 256, 256>>>(probs, dgp);

    // top-k selections
    topk_kernel<<<NH, 512>>>(vert, VSZ, 0, keys);
    topk_kernel<<<NH, 512>>>(dgp, SSZ, 1, keys);

    // gather sparse K/V
    gather_kernel<<<NH * NKEYP, 64>>>(k, v, keys, ksp, vsp);

    // sparse attention
    spattn_kernel<<<dim3(SEQ / 64, NH), 256>>>(q, ksp, vsp, keys, att);

    // output projection (single-pass tf32)
    gemm_tf32_1x<<<dim3(DIM / 128, SEQ / 128), 256>>>(att, wo, out, SEQ, DIM, DIM);
}

// round 5
// speedup vs baseline: 1.8437x; 1.4826x over previous
#include <cuda_runtime.h>
#include <math.h>
#include <stdint.h>

#define SEQ   4096
#define DIM   2048
#define NH    32
#define NKV   8
#define HD    64
#define ESTQ  64
#define VSZ   300
#define SSZ   800
#define NKEY  1100
#define NKEYP 1152
#define SCALE 0.125f   // 1/sqrt(64)
#define PADKEY 0x3FFFFFFF

// ---------------- device scratch (no allocation allowed) ----------------
__device__ float g_q[SEQ * DIM];            // tf32-accurate q
__device__ float g_q64[ESTQ * DIM];         // exact fp32 q rows 0..63
__device__ float g_q64p[8 * ESTQ * DIM];    // split-K partials
__device__ float g_k[SEQ * NKV * HD];       // 3xTF32-accurate
__device__ float g_v[SEQ * NKV * HD];       // 3xTF32-accurate
__device__ float g_probs[NH * ESTQ * SEQ];
__device__ float g_vert[NH * SEQ];
__device__ float g_diag[NH * SEQ];
__device__ int   g_keys[NH * NKEYP];
__device__ float g_ksp[NH * NKEYP * HD];
__device__ float g_vsp[NH * NKEYP * HD];
__device__ float g_att[SEQ * DIM];

// ---------------- common tf32 helpers ------------------------------------
__device__ __forceinline__ uint32_t f2tf32(float f) {
    uint32_t r;
    asm("cvt.rna.tf32.f32 %0, %1;" : "=r"(r) : "f"(f));
    return r;
}

__device__ __forceinline__ void mma_tf32(float c[4], const uint32_t a[4],
                                         uint32_t b0, uint32_t b1) {
    asm volatile(
        "mma.sync.aligned.m16n8k8.row.col.f32.tf32.tf32.f32 "
        "{%0,%1,%2,%3}, {%4,%5,%6,%7}, {%8,%9}, {%0,%1,%2,%3};\n"
        : "+f"(c[0]), "+f"(c[1]), "+f"(c[2]), "+f"(c[3])
        : "r"(a[0]), "r"(a[1]), "r"(a[2]), "r"(a[3]), "r"(b0), "r"(b1));
}

// ================= single-pass tf32 GEMM (BK=32) ==========================
#define A1_ST 36
#define B1_ST 132

__global__ __launch_bounds__(256) void gemm_tf32_1x(const float* __restrict__ A,
                                                    const float* __restrict__ B,
                                                    float* __restrict__ C,
                                                    int M, int N, int K) {
    __shared__ uint32_t As[128 * A1_ST];
    __shared__ uint32_t Bs[32 * B1_ST];
    int tid = threadIdx.x;
    int lane = tid & 31;
    int warp = tid >> 5;
    int wm = warp & 3;
    int wn = warp >> 2;
    int row0 = blockIdx.y * 128;
    int col0 = blockIdx.x * 128;

    float acc[2][8][4];
#pragma unroll
    for (int mi = 0; mi < 2; mi++)
#pragma unroll
        for (int nj = 0; nj < 8; nj++)
#pragma unroll
            for (int e = 0; e < 4; e++) acc[mi][nj][e] = 0.f;

    int lr = lane >> 2;
    int lc = lane & 3;

    for (int k0 = 0; k0 < K; k0 += 32) {
#pragma unroll
        for (int i = 0; i < 4; i++) {
            int f = i * 256 + tid;
            int r = f >> 3;
            int c = (f & 7) << 2;
            float4 v = *(const float4*)(A + (size_t)(row0 + r) * K + k0 + c);
            uint32_t* dst = &As[r * A1_ST + c];
            dst[0] = f2tf32(v.x);
            dst[1] = f2tf32(v.y);
            dst[2] = f2tf32(v.z);
            dst[3] = f2tf32(v.w);
        }
#pragma unroll
        for (int i = 0; i < 4; i++) {
            int f = i * 256 + tid;
            int r = f >> 5;
            int c = (f & 31) << 2;
            float4 v = *(const float4*)(B + (size_t)(k0 + r) * N + col0 + c);
            uint32_t* dst = &Bs[r * B1_ST + c];
            dst[0] = f2tf32(v.x);
            dst[1] = f2tf32(v.y);
            dst[2] = f2tf32(v.z);
            dst[3] = f2tf32(v.w);
        }
        __syncthreads();

#pragma unroll
        for (int ks = 0; ks < 4; ks++) {
            int kb = ks * 8;
            uint32_t a[2][4];
#pragma unroll
            for (int mi = 0; mi < 2; mi++) {
                int r = wm * 32 + mi * 16 + lr;
                a[mi][0] = As[r * A1_ST + kb + lc];
                a[mi][1] = As[(r + 8) * A1_ST + kb + lc];
                a[mi][2] = As[r * A1_ST + kb + lc + 4];
                a[mi][3] = As[(r + 8) * A1_ST + kb + lc + 4];
            }
#pragma unroll
            for (int nj = 0; nj < 8; nj++) {
                int c = wn * 64 + nj * 8 + lr;
                uint32_t b0 = Bs[(kb + lc) * B1_ST + c];
                uint32_t b1 = Bs[(kb + lc + 4) * B1_ST + c];
                mma_tf32(acc[0][nj], a[0], b0, b1);
                mma_tf32(acc[1][nj], a[1], b0, b1);
            }
        }
        __syncthreads();
    }

#pragma unroll
    for (int mi = 0; mi < 2; mi++) {
        int row = row0 + wm * 32 + mi * 16 + lr;
#pragma unroll
        for (int nj = 0; nj < 8; nj++) {
            int col = col0 + wn * 64 + nj * 8 + 2 * lc;
            float* cp0 = C + (size_t)row * N + col;
            cp0[0] = acc[mi][nj][0];
            cp0[1] = acc[mi][nj][1];
            float* cp1 = C + (size_t)(row + 8) * N + col;
            cp1[0] = acc[mi][nj][2];
            cp1[1] = acc[mi][nj][3];
        }
    }
}

// ================= 3xTF32 GEMM (BK=16), ~fp32 accuracy ====================
#define AS_ST 20
#define BS_ST 132

__global__ __launch_bounds__(256) void gemm_tf32x3(const float* __restrict__ A,
                                                   const float* __restrict__ B,
                                                   float* __restrict__ C,
                                                   int M, int N, int K) {
    __shared__ uint32_t AsH[128 * AS_ST];
    __shared__ uint32_t AsL[128 * AS_ST];
    __shared__ uint32_t BsH[16 * BS_ST];
    __shared__ uint32_t BsL[16 * BS_ST];
    int tid = threadIdx.x;
    int lane = tid & 31;
    int warp = tid >> 5;
    int wm = warp & 3;
    int wn = warp >> 2;
    int row0 = blockIdx.y * 128;
    int col0 = blockIdx.x * 128;

    float acc[2][8][4];
#pragma unroll
    for (int mi = 0; mi < 2; mi++)
#pragma unroll
        for (int nj = 0; nj < 8; nj++)
#pragma unroll
            for (int e = 0; e < 4; e++) acc[mi][nj][e] = 0.f;

    int lr = lane >> 2;
    int lc = lane & 3;

    for (int k0 = 0; k0 < K; k0 += 16) {
#pragma unroll
        for (int i = 0; i < 2; i++) {
            int f = i * 256 + tid;
            int r = f >> 2;
            int c = (f & 3) << 2;
            float4 v = *(const float4*)(A + (size_t)(row0 + r) * K + k0 + c);
            uint32_t* dh = &AsH[r * AS_ST + c];
            uint32_t* dl = &AsL[r * AS_ST + c];
            uint32_t h0 = f2tf32(v.x), h1 = f2tf32(v.y), h2 = f2tf32(v.z), h3 = f2tf32(v.w);
            dh[0] = h0; dh[1] = h1; dh[2] = h2; dh[3] = h3;
            dl[0] = f2tf32(v.x - __uint_as_float(h0));
            dl[1] = f2tf32(v.y - __uint_as_float(h1));
            dl[2] = f2tf32(v.z - __uint_as_float(h2));
            dl[3] = f2tf32(v.w - __uint_as_float(h3));
        }
#pragma unroll
        for (int i = 0; i < 2; i++) {
            int f = i * 256 + tid;
            int r = f >> 5;
            int c = (f & 31) << 2;
            float4 v = *(const float4*)(B + (size_t)(k0 + r) * N + col0 + c);
            uint32_t* dh = &BsH[r * BS_ST + c];
            uint32_t* dl = &BsL[r * BS_ST + c];
            uint32_t h0 = f2tf32(v.x), h1 = f2tf32(v.y), h2 = f2tf32(v.z), h3 = f2tf32(v.w);
            dh[0] = h0; dh[1] = h1; dh[2] = h2; dh[3] = h3;
            dl[0] = f2tf32(v.x - __uint_as_float(h0));
            dl[1] = f2tf32(v.y - __uint_as_float(h1));
            dl[2] = f2tf32(v.z - __uint_as_float(h2));
            dl[3] = f2tf32(v.w - __uint_as_float(h3));
        }
        __syncthreads();

#pragma unroll
        for (int ks = 0; ks < 2; ks++) {
            int kb = ks * 8;
            uint32_t aH[2][4], aL[2][4];
#pragma unroll
            for (int mi = 0; mi < 2; mi++) {
                int r = wm * 32 + mi * 16 + lr;
                aH[mi][0] = AsH[r * AS_ST + kb + lc];
                aH[mi][1] = AsH[(r + 8) * AS_ST + kb + lc];
                aH[mi][2] = AsH[r * AS_ST + kb + lc + 4];
                aH[mi][3] = AsH[(r + 8) * AS_ST + kb + lc + 4];
                aL[mi][0] = AsL[r * AS_ST + kb + lc];
                aL[mi][1] = AsL[(r + 8) * AS_ST + kb + lc];
                aL[mi][2] = AsL[r * AS_ST + kb + lc + 4];
                aL[mi][3] = AsL[(r + 8) * AS_ST + kb + lc + 4];
            }
#pragma unroll
            for (int nj = 0; nj < 8; nj++) {
                int c = wn * 64 + nj * 8 + lr;
                uint32_t b0h = BsH[(kb + lc) * BS_ST + c];
                uint32_t b1h = BsH[(kb + lc + 4) * BS_ST + c];
                uint32_t b0l = BsL[(kb + lc) * BS_ST + c];
                uint32_t b1l = BsL[(kb + lc + 4) * BS_ST + c];
#pragma unroll
                for (int mi = 0; mi < 2; mi++) {
                    mma_tf32(acc[mi][nj], aH[mi], b0h, b1h);
                    mma_tf32(acc[mi][nj], aH[mi], b0l, b1l);
                    mma_tf32(acc[mi][nj], aL[mi], b0h, b1h);
                }
            }
        }
        __syncthreads();
    }

#pragma unroll
    for (int mi = 0; mi < 2; mi++) {
        int row = row0 + wm * 32 + mi * 16 + lr;
#pragma unroll
        for (int nj = 0; nj < 8; nj++) {
            int col = col0 + wn * 64 + nj * 8 + 2 * lc;
            float* cp0 = C + (size_t)row * N + col;
            cp0[0] = acc[mi][nj][0];
            cp0[1] = acc[mi][nj][1];
            float* cp1 = C + (size_t)(row + 8) * N + col;
            cp1[0] = acc[mi][nj][2];
            cp1[1] = acc[mi][nj][3];
        }
    }
}

// ---------------- exact fp32 q rows 0..63: split-K --------------------------
// stage 1: grid (16, 8, 8) block 128: partial over K slice of 256
__global__ __launch_bounds__(128) void qproj_part(const float* __restrict__ x,
                                                  const float* __restrict__ wq,
                                                  float* __restrict__ part) {
    __shared__ float xs[8][256];
    int tid = threadIdx.x;
    int col = blockIdx.x * 128 + tid;
    int r0 = blockIdx.y * 8;
    int k0 = blockIdx.z * 256;
    float acc[8];
#pragma unroll
    for (int rr = 0; rr < 8; rr++) acc[rr] = 0.f;

    for (int i = tid; i < 8 * 256; i += 128) {
        int rr = i >> 8, kk = i & 255;
        xs[rr][kk] = x[(size_t)(r0 + rr) * DIM + k0 + kk];
    }
    __syncthreads();
    for (int kk = 0; kk < 256; kk++) {
        float w = wq[(size_t)(k0 + kk) * DIM + col];
#pragma unroll
        for (int rr = 0; rr < 8; rr++) acc[rr] += xs[rr][kk] * w;
    }
#pragma unroll
    for (int rr = 0; rr < 8; rr++)
        part[(size_t)blockIdx.z * ESTQ * DIM + (size_t)(r0 + rr) * DIM + col] = acc[rr];
}

// stage 2: fixed-order reduction (deterministic)
__global__ void qproj_red(const float* __restrict__ part, float* __restrict__ q64) {
    int idx = blockIdx.x * 256 + threadIdx.x;
    if (idx >= ESTQ * DIM) return;
    float s = 0.f;
#pragma unroll
    for (int ks = 0; ks < 8; ks++) s += part[(size_t)ks * ESTQ * DIM + idx];
    q64[idx] = s;
}

// ---------------- RoPE in place on [S][H][64] ----------------------------
__global__ void rope_kernel(float* t, const float* __restrict__ cosb,
                            const float* __restrict__ sinb, int H, int total) {
    int idx = blockIdx.x * blockDim.x + threadIdx.x;
    if (idx >= total) return;
    int d2 = idx & 31;
    int h = (idx >> 5) % H;
    int s = idx / (32 * H);
    float c = cosb[s * 32 + d2];
    float sn = sinb[s * 32 + d2];
    float* p = t + ((size_t)s * H + h) * 64 + 2 * d2;
    float xr = p[0], xi = p[1];
    p[0] = xr * c - xi * sn;
    p[1] = xr * sn + xi * c;
}

// ---------------- est phase A: raw masked scores ---------------------------
// grid (SEQ/64, NH), block 256: 64 queries x 64 keys per block
__global__ __launch_bounds__(256) void est_score(const float* __restrict__ q64,
                                                 const float* __restrict__ k,
                                                 float* __restrict__ probs) {
    __shared__ float qs[64][68];
    __shared__ float ksm[64][68];
    int tid = threadIdx.x;
    int h = blockIdx.y;
    int c0 = blockIdx.x * 64;
    int kvh = h >> 2;
    int qi = tid >> 2;
    int kg = tid & 3;

    for (int l = tid; l < 64 * 64; l += 256) {
        int r = l >> 6, d = l & 63;
        qs[r][d] = q64[(size_t)r * DIM + h * HD + d];
        ksm[r][d] = k[(size_t)(c0 + r) * (NKV * HD) + kvh * HD + d];
    }
    __syncthreads();

    float s16[16];
#pragma unroll
    for (int j = 0; j < 16; j++) s16[j] = 0.f;
#pragma unroll
    for (int d4 = 0; d4 < 16; d4++) {
        float4 q4 = *(float4*)&qs[qi][d4 * 4];
#pragma unroll
        for (int j = 0; j < 16; j++) {
            float4 k4 = *(float4*)&ksm[kg * 16 + j][d4 * 4];
            s16[j] += q4.x * k4.x + q4.y * k4.y + q4.z * k4.z + q4.w * k4.w;
        }
    }
    float* pr = probs + ((size_t)h * ESTQ + qi) * SEQ + c0 + kg * 16;
#pragma unroll
    for (int j = 0; j < 16; j++) {
        int kk = c0 + kg * 16 + j;
        float val = s16[j] * SCALE;
        if (kk >= SEQ - ESTQ && qi < kk - (SEQ - ESTQ)) val = -INFINITY;
        pr[j] = val;
    }
}

// ---------------- est phase B: row softmax in place ------------------------
__global__ __launch_bounds__(256) void est_norm(float* __restrict__ probs) {
    int qi = blockIdx.x;
    int h = blockIdx.y;
    __shared__ float sc[SEQ];
    __shared__ float red[8];
    int tid = threadIdx.x;
    float* pr = probs + ((size_t)h * ESTQ + qi) * SEQ;

    for (int l = tid; l < SEQ / 4; l += 256)
        *(float4*)&sc[l * 4] = *(const float4*)&pr[l * 4];
    __syncthreads();

    float m = -INFINITY;
    for (int kk = tid; kk < SEQ; kk += 256) m = fmaxf(m, sc[kk]);
#pragma unroll
    for (int o = 16; o; o >>= 1) m = fmaxf(m, __shfl_xor_sync(0xFFFFFFFFu, m, o));
    if ((tid & 31) == 0) red[tid >> 5] = m;
    __syncthreads();
    if (tid == 0) {
        float mm = red[0];
#pragma unroll
        for (int i = 1; i < 8; i++) mm = fmaxf(mm, red[i]);
        red[0] = mm;
    }
    __syncthreads();
    m = red[0];
    __syncthreads();

    float s = 0.f;
    for (int kk = tid; kk < SEQ; kk += 256) {
        float e = expf(sc[kk] - m);
        sc[kk] = e;
        s += e;
    }
#pragma unroll
    for (int o = 16; o; o >>= 1) s += __shfl_xor_sync(0xFFFFFFFFu, s, o);
    if ((tid & 31) == 0) red[tid >> 5] = s;
    __syncthreads();
    if (tid == 0) {
        float ss = 0.f;
#pragma unroll
        for (int i = 0; i < 8; i++) ss += red[i];
        red[0] = ss;
    }
    __syncthreads();
    float inv = 1.f / red[0];
    for (int kk = tid; kk < SEQ; kk += 256) pr[kk] = sc[kk] * inv;
}

// ---------------- vertical column sums -----------------------------------
__global__ void vertical_kernel(const float* __restrict__ probs, float* __restrict__ vert) {
    int idx = blockIdx.x * 256 + threadIdx.x;
    int h = idx >> 12;
    int kk = idx & (SEQ - 1);
    float s = 0.f;
    const float* base = probs + (size_t)h * ESTQ * SEQ + kk;
    for (int i = 0; i < ESTQ; i++) s += base[(size_t)i * SEQ];
    vert[idx] = s;
}

// ---------------- diagonal sums ------------------------------------------
__global__ void diag_kernel(const float* __restrict__ probs, float* __restrict__ dg) {
    int idx = blockIdx.x * 256 + threadIdx.x;
    int h = idx >> 12;
    int jp = idx & (SEQ - 1);
    float s = 0.f;
    const float* base = probs + (size_t)h * ESTQ * SEQ;
    for (int i = 0; i < ESTQ; i++) {
        int col = i + jp - 63;
        if (col >= 0 && col < SEQ) s += base[(size_t)i * SEQ + col];
    }
    dg[idx] = s;
}

// ---------------- per-head top-k via bitonic sort -------------------------
__global__ void topk_kernel(const float* __restrict__ vals, int kcount, int mode,
                            int* __restrict__ keys) {
    int h = blockIdx.x;
    __shared__ unsigned long long a[SEQ];
    int tid = threadIdx.x;  // 512
    for (int i = tid; i < SEQ; i += 512) {
        unsigned u = __float_as_uint(vals[h * SEQ + i]);
        u = (u & 0x80000000u) ? ~u : (u | 0x80000000u);
        a[i] = ((unsigned long long)(~u) << 32) | (unsigned)i;
    }
    __syncthreads();
    for (int k = 2; k <= SEQ; k <<= 1) {
        for (int j = k >> 1; j > 0; j >>= 1) {
            for (int i = tid; i < SEQ; i += 512) {
                int ixj = i ^ j;
                if (ixj > i) {
                    bool up = ((i & k) == 0);
                    unsigned long long x = a[i], y = a[ixj];
                    if (up ? (x > y) : (x < y)) { a[i] = y; a[ixj] = x; }
                }
            }
            __syncthreads();
        }
    }
    if (mode == 0) {
        for (int t = tid; t < kcount; t += 512)
            keys[h * NKEYP + t] = (int)(a[t] & 0xFFFFFFFFull);
    } else {
        for (int t = tid; t < kcount; t += 512)
            keys[h * NKEYP + VSZ + t] = (SEQ - 1) - (int)(a[t] & 0xFFFFFFFFull);
        for (int t = NKEY + tid; t < NKEYP; t += 512) keys[h * NKEYP + t] = PADKEY;
    }
}

// ---------------- sort keys ascending per head -----------------------------
__global__ __launch_bounds__(256) void sortkeys_kernel(int* __restrict__ keys) {
    int h = blockIdx.x;
    __shared__ int a[2048];
    int tid = threadIdx.x;
    for (int i = tid; i < 2048; i += 256)
        a[i] = (i < NKEYP) ? keys[h * NKEYP + i] : PADKEY;
    __syncthreads();
    for (int k = 2; k <= 2048; k <<= 1) {
        for (int j = k >> 1; j > 0; j >>= 1) {
            for (int i = tid; i < 2048; i += 256) {
                int ixj = i ^ j;
                if (ixj > i) {
                    bool up = ((i & k) == 0);
                    int x = a[i], y = a[ixj];
                    if (up ? (x > y) : (x < y)) { a[i] = y; a[ixj] = x; }
                }
            }
            __syncthreads();
        }
    }
    for (int i = tid; i < NKEYP; i += 256) keys[h * NKEYP + i] = a[i];
}

// ---------------- gather sparse K/V rows ----------------------------------
__global__ void gather_kernel(const float* __restrict__ k, const float* __restrict__ v,
                              const int* __restrict__ keys,
                              float* __restrict__ ksp, float* __restrict__ vsp) {
    int j = blockIdx.x;
    int h = j / NKEYP;
    int d = threadIdx.x;
    int key = keys[j];
    int kvh = h >> 2;
    float kv = 0.f, vv = 0.f;
    if (key < SEQ) {
        kv = k[(size_t)key * (NKV * HD) + kvh * HD + d];
        vv = v[(size_t)key * (NKV * HD) + kvh * HD + d];
    }
    ksp[(size_t)j * HD + d] = kv;
    vsp[(size_t)j * HD + d] = vv;
}

// ---------------- sparse attention v2: sorted keys + tile skip -------------
// block (qb, h): 64 queries; 256 threads: qp = tid>>3 (0..31), g = tid&7.
// thread handles queries {qp, qp+32}; QK keys g*4..g*4+3; PV dims g*8..g*8+7.
__global__ __launch_bounds__(256) void spattn_kernel(const float* __restrict__ q,
                                                     const float* __restrict__ ksp,
                                                     const float* __restrict__ vsp,
                                                     const int* __restrict__ keys,
                                                     float* __restrict__ attout) {
    int qb = blockIdx.x;
    int h = blockIdx.y;
    __shared__ float qs[64][68];
    __shared__ float ks[32][68];
    __shared__ float vs[32][68];
    __shared__ float ss[64][36];
    __shared__ int kid[32];
    int tid = threadIdx.x;
    int qp = tid >> 3;
    int g = tid & 7;
    int qi0 = qp, qi1 = qp + 32;
    int sglob0 = qb * 64 + qi0;
    int sglob1 = qb * 64 + qi1;
    int qbmax = qb * 64 + 63;

    for (int l = tid; l < 64 * 16; l += 256) {
        int r = l >> 4, c4 = l & 15;
        *(float4*)&qs[r][c4 * 4] =
            *(const float4*)&q[(size_t)(qb * 64 + r) * DIM + h * HD + c4 * 4];
    }

    float m0 = -INFINITY, m1 = -INFINITY, lsum0 = 0.f, lsum1 = 0.f;
    float out0[8], out1[8];
#pragma unroll
    for (int i = 0; i < 8; i++) { out0[i] = 0.f; out1[i] = 0.f; }

    for (int t = 0; t < NKEYP / 32; t++) {
        __syncthreads();
        if (tid < 32) kid[tid] = keys[h * NKEYP + t * 32 + tid];
        __syncthreads();
        if (kid[0] > qbmax) continue;  // whole tile causally masked for this block

        for (int l = tid; l < 32 * 16; l += 256) {
            int r = l >> 4, c4 = l & 15;
            *(float4*)&ks[r][c4 * 4] =
                *(const float4*)&ksp[((size_t)h * NKEYP + t * 32 + r) * HD + c4 * 4];
            *(float4*)&vs[r][c4 * 4] =
                *(const float4*)&vsp[((size_t)h * NKEYP + t * 32 + r) * HD + c4 * 4];
        }
        __syncthreads();

        // QK: 2 queries x 4 keys
        float s0[4], s1[4];
#pragma unroll
        for (int j = 0; j < 4; j++) { s0[j] = 0.f; s1[j] = 0.f; }
#pragma unroll
        for (int d4 = 0; d4 < 16; d4++) {
            float4 q0 = *(float4*)&qs[qi0][d4 * 4];
            float4 q1 = *(float4*)&qs[qi1][d4 * 4];
#pragma unroll
            for (int j = 0; j < 4; j++) {
                float4 k4 = *(float4*)&ks[g * 4 + j][d4 * 4];
                s0[j] += q0.x * k4.x + q0.y * k4.y + q0.z * k4.z + q0.w * k4.w;
                s1[j] += q1.x * k4.x + q1.y * k4.y + q1.z * k4.z + q1.w * k4.w;
            }
        }
#pragma unroll
        for (int j = 0; j < 4; j++) {
            int key = kid[g * 4 + j];
            float v0, v1;
            if (key >= SEQ) { v0 = -INFINITY; v1 = -INFINITY; }  // pad
            else {
                v0 = (key <= sglob0) ? s0[j] * SCALE : -1e30f;
                v1 = (key <= sglob1) ? s1[j] * SCALE : -1e30f;
            }
            ss[qi0][g * 4 + j] = v0;
            ss[qi1][g * 4 + j] = v1;
        }
        __syncthreads();

        // per-query tile max (redundant across 8 g-threads, identical result)
        float tm0 = m0, tm1 = m1;
#pragma unroll
        for (int j = 0; j < 32; j++) {
            tm0 = fmaxf(tm0, ss[qi0][j]);
            tm1 = fmaxf(tm1, ss[qi1][j]);
        }
        float c0 = expf(m0 - tm0);
        float c1 = expf(m1 - tm1);
        m0 = tm0; m1 = tm1;
        lsum0 *= c0; lsum1 *= c1;
#pragma unroll
        for (int i = 0; i < 8; i++) { out0[i] *= c0; out1[i] *= c1; }
        __syncthreads();  // all raw reads done before exp overwrite

#pragma unroll
        for (int j = 0; j < 4; j++) {
            ss[qi0][g * 4 + j] = expf(ss[qi0][g * 4 + j] - m0);
            ss[qi1][g * 4 + j] = expf(ss[qi1][g * 4 + j] - m1);
        }
        __syncthreads();

        float ps0 = 0.f, ps1 = 0.f;
#pragma unroll
        for (int j = 0; j < 32; j++) {
            float p0 = ss[qi0][j];
            float p1 = ss[qi1][j];
            ps0 += p0; ps1 += p1;
            float4 va = *(float4*)&vs[j][g * 8];
            float4 vb = *(float4*)&vs[j][g * 8 + 4];
            out0[0] += p0 * va.x; out0[1] += p0 * va.y; out0[2] += p0 * va.z; out0[3] += p0 * va.w;
            out0[4] += p0 * vb.x; out0[5] += p0 * vb.y; out0[6] += p0 * vb.z; out0[7] += p0 * vb.w;
            out1[0] += p1 * va.x; out1[1] += p1 * va.y; out1[2] += p1 * va.z; out1[3] += p1 * va.w;
            out1[4] += p1 * vb.x; out1[5] += p1 * vb.y; out1[6] += p1 * vb.z; out1[7] += p1 * vb.w;
        }
        lsum0 += ps0;
        lsum1 += ps1;
    }

    // fallback for all-masked queries: uniform 1/NKEY over all real keys (= ref)
    if (m0 < -5e29f) {
        lsum0 = (float)NKEY;
#pragma unroll
        for (int i = 0; i < 8; i++) out0[i] = 0.f;
        for (int j = 0; j < NKEYP; j++) {
            if (keys[h * NKEYP + j] < SEQ) {
                const float* vr = &vsp[((size_t)h * NKEYP + j) * HD + g * 8];
#pragma unroll
                for (int i = 0; i < 8; i++) out0[i] += vr[i];
            }
        }
    }
    if (m1 < -5e29f) {
        lsum1 = (float)NKEY;
#pragma unroll
        for (int i = 0; i < 8; i++) out1[i] = 0.f;
        for (int j = 0; j < NKEYP; j++) {
            if (keys[h * NKEYP + j] < SEQ) {
                const float* vr = &vsp[((size_t)h * NKEYP + j) * HD + g * 8];
#pragma unroll
                for (int i = 0; i < 8; i++) out1[i] += vr[i];
            }
        }
    }

    float inv0 = 1.f / lsum0;
    float inv1 = 1.f / lsum1;
#pragma unroll
    for (int i = 0; i < 8; i++) {
        attout[(size_t)sglob0 * DIM + h * HD + g * 8 + i] = out0[i] * inv0;
        attout[(size_t)sglob1 * DIM + h * HD + g * 8 + i] = out1[i] * inv1;
    }
}

// --------------------------------- launch --------------------------------
extern "C" void kernel_launch(void* const* d_in, const int* in_sizes, int n_in,
                              void* d_out, int out_size) {
    const float* x    = (const float*)d_in[0];
    const float* fcos = (const float*)d_in[1];
    const float* fsin = (const float*)d_in[2];
    const float* wq   = (const float*)d_in[3];
    const float* wk   = (const float*)d_in[4];
    const float* wv   = (const float*)d_in[5];
    const float* wo   = (const float*)d_in[6];
    float* out = (float*)d_out;

    float *q, *q64, *q64p, *k, *v, *probs, *vert, *dgp, *ksp, *vsp, *att;
    int* keys;
    cudaGetSymbolAddress((void**)&q, g_q);
    cudaGetSymbolAddress((void**)&q64, g_q64);
    cudaGetSymbolAddress((void**)&q64p, g_q64p);
    cudaGetSymbolAddress((void**)&k, g_k);
    cudaGetSymbolAddress((void**)&v, g_v);
    cudaGetSymbolAddress((void**)&probs, g_probs);
    cudaGetSymbolAddress((void**)&vert, g_vert);
    cudaGetSymbolAddress((void**)&dgp, g_diag);
    cudaGetSymbolAddress((void**)&keys, g_keys);
    cudaGetSymbolAddress((void**)&ksp, g_ksp);
    cudaGetSymbolAddress((void**)&vsp, g_vsp);
    cudaGetSymbolAddress((void**)&att, g_att);

    // projections: q 1x tf32, k/v 3xTF32
    gemm_tf32_1x<<<dim3(DIM / 128, SEQ / 128), 256>>>(x, wq, q, SEQ, DIM, DIM);
    gemm_tf32x3<<<dim3((NKV * HD) / 128, SEQ / 128), 256>>>(x, wk, k, SEQ, NKV * HD, DIM);
    gemm_tf32x3<<<dim3((NKV * HD) / 128, SEQ / 128), 256>>>(x, wv, v, SEQ, NKV * HD, DIM);

    // exact fp32 q rows 0..63 via split-K
    qproj_part<<<dim3(16, 8, 8), 128>>>(x, wq, q64p);
    qproj_red<<<(ESTQ * DIM + 255) / 256, 256>>>(q64p, q64);

    // RoPE
    {
        int tq = SEQ * NH * 32;
        rope_kernel<<<(tq + 255) / 256, 256>>>(q, fcos, fsin, NH, tq);
        int tk = SEQ * NKV * 32;
        rope_kernel<<<(tk + 255) / 256, 256>>>(k, fcos, fsin, NKV, tk);
        int tq64 = ESTQ * NH * 32;
        rope_kernel<<<(tq64 + 255) / 256, 256>>>(q64, fcos, fsin, NH, tq64);
    }

    // estimation: scores then row softmax
    est_score<<<dim3(SEQ / 64, NH), 256>>>(q64, k, probs);
    est_norm<<<dim3(ESTQ, NH), 256>>>(probs);

    // vertical / diagonal scores
    vertical_kernel<<<(NH * SEQ) / 256, 256>>>(probs, vert);
    diag_kernel<<<(NH * SEQ) / 256, 256>>>(probs, dgp);

    // top-k selections
    topk_kernel<<<NH, 512>>>(vert, VSZ, 0, keys);
    topk_kernel<<<NH, 512>>>(dgp, SSZ, 1, keys);

    // sort keys ascending (softmax is order-invariant; enables tile skipping)
    sortkeys_kernel<<<NH, 256>>>(keys);

    // gather sparse K/V
    gather_kernel<<<NH * NKEYP, 64>>>(k, v, keys, ksp, vsp);

    // sparse attention with tile skip
    spattn_kernel<<<dim3(SEQ / 64, NH), 256>>>(q, ksp, vsp, keys, att);

    // output projection (1x tf32)
    gemm_tf32_1x<<<dim3(DIM / 128, SEQ / 128), 256>>>(att, wo, out, SEQ, DIM, DIM);
}

// round 6
// speedup vs baseline: 2.5348x; 1.3748x over previous
#include <cuda_runtime.h>
#include <math.h>
#include <stdint.h>

#define SEQ   4096
#define DIM   2048
#define NH    32
#define NKV   8
#define HD    64
#define ESTQ  64
#define VSZ   300
#define SSZ   800
#define NKEY  1100
#define NKEYP 1152
#define SCALE 0.125f   // 1/sqrt(64)
#define PADKEY 0x3FFFFFFF

// ---------------- device scratch (no allocation allowed) ----------------
__device__ float g_q[SEQ * DIM];            // tf32-accurate q
__device__ float g_q64[ESTQ * DIM];         // exact fp32 q rows 0..63
__device__ float g_q64p[8 * ESTQ * DIM];    // split-K partials
__device__ float g_k[SEQ * NKV * HD];       // 3xTF32-accurate
__device__ float g_v[SEQ * NKV * HD];       // 3xTF32-accurate
__device__ float g_probs[NH * ESTQ * SEQ];
__device__ float g_vert[NH * SEQ];
__device__ float g_diag[NH * SEQ];
__device__ int   g_keys[NH * NKEYP];
__device__ float g_ksp[NH * NKEYP * HD];
__device__ float g_vsp[NH * NKEYP * HD];
__device__ float g_att[SEQ * DIM];

// ---------------- common tf32 helpers ------------------------------------
__device__ __forceinline__ uint32_t f2tf32(float f) {
    uint32_t r;
    asm("cvt.rna.tf32.f32 %0, %1;" : "=r"(r) : "f"(f));
    return r;
}

__device__ __forceinline__ void mma_tf32(float c[4], const uint32_t a[4],
                                         uint32_t b0, uint32_t b1) {
    asm volatile(
        "mma.sync.aligned.m16n8k8.row.col.f32.tf32.tf32.f32 "
        "{%0,%1,%2,%3}, {%4,%5,%6,%7}, {%8,%9}, {%0,%1,%2,%3};\n"
        : "+f"(c[0]), "+f"(c[1]), "+f"(c[2]), "+f"(c[3])
        : "r"(a[0]), "r"(a[1]), "r"(a[2]), "r"(a[3]), "r"(b0), "r"(b1));
}

// ================= single-pass tf32 GEMM (BK=32) ==========================
#define A1_ST 36
#define B1_ST 132

__global__ __launch_bounds__(256) void gemm_tf32_1x(const float* __restrict__ A,
                                                    const float* __restrict__ B,
                                                    float* __restrict__ C,
                                                    int M, int N, int K) {
    __shared__ uint32_t As[128 * A1_ST];
    __shared__ uint32_t Bs[32 * B1_ST];
    int tid = threadIdx.x;
    int lane = tid & 31;
    int warp = tid >> 5;
    int wm = warp & 3;
    int wn = warp >> 2;
    int row0 = blockIdx.y * 128;
    int col0 = blockIdx.x * 128;

    float acc[2][8][4];
#pragma unroll
    for (int mi = 0; mi < 2; mi++)
#pragma unroll
        for (int nj = 0; nj < 8; nj++)
#pragma unroll
            for (int e = 0; e < 4; e++) acc[mi][nj][e] = 0.f;

    int lr = lane >> 2;
    int lc = lane & 3;

    for (int k0 = 0; k0 < K; k0 += 32) {
#pragma unroll
        for (int i = 0; i < 4; i++) {
            int f = i * 256 + tid;
            int r = f >> 3;
            int c = (f & 7) << 2;
            float4 v = *(const float4*)(A + (size_t)(row0 + r) * K + k0 + c);
            uint32_t* dst = &As[r * A1_ST + c];
            dst[0] = f2tf32(v.x);
            dst[1] = f2tf32(v.y);
            dst[2] = f2tf32(v.z);
            dst[3] = f2tf32(v.w);
        }
#pragma unroll
        for (int i = 0; i < 4; i++) {
            int f = i * 256 + tid;
            int r = f >> 5;
            int c = (f & 31) << 2;
            float4 v = *(const float4*)(B + (size_t)(k0 + r) * N + col0 + c);
            uint32_t* dst = &Bs[r * B1_ST + c];
            dst[0] = f2tf32(v.x);
            dst[1] = f2tf32(v.y);
            dst[2] = f2tf32(v.z);
            dst[3] = f2tf32(v.w);
        }
        __syncthreads();

#pragma unroll
        for (int ks = 0; ks < 4; ks++) {
            int kb = ks * 8;
            uint32_t a[2][4];
#pragma unroll
            for (int mi = 0; mi < 2; mi++) {
                int r = wm * 32 + mi * 16 + lr;
                a[mi][0] = As[r * A1_ST + kb + lc];
                a[mi][1] = As[(r + 8) * A1_ST + kb + lc];
                a[mi][2] = As[r * A1_ST + kb + lc + 4];
                a[mi][3] = As[(r + 8) * A1_ST + kb + lc + 4];
            }
#pragma unroll
            for (int nj = 0; nj < 8; nj++) {
                int c = wn * 64 + nj * 8 + lr;
                uint32_t b0 = Bs[(kb + lc) * B1_ST + c];
                uint32_t b1 = Bs[(kb + lc + 4) * B1_ST + c];
                mma_tf32(acc[0][nj], a[0], b0, b1);
                mma_tf32(acc[1][nj], a[1], b0, b1);
            }
        }
        __syncthreads();
    }

#pragma unroll
    for (int mi = 0; mi < 2; mi++) {
        int row = row0 + wm * 32 + mi * 16 + lr;
#pragma unroll
        for (int nj = 0; nj < 8; nj++) {
            int col = col0 + wn * 64 + nj * 8 + 2 * lc;
            float* cp0 = C + (size_t)row * N + col;
            cp0[0] = acc[mi][nj][0];
            cp0[1] = acc[mi][nj][1];
            float* cp1 = C + (size_t)(row + 8) * N + col;
            cp1[0] = acc[mi][nj][2];
            cp1[1] = acc[mi][nj][3];
        }
    }
}

// ================= 3xTF32 GEMM (BK=16), ~fp32 accuracy ====================
#define AS_ST 20
#define BS_ST 132

__global__ __launch_bounds__(256) void gemm_tf32x3(const float* __restrict__ A,
                                                   const float* __restrict__ B,
                                                   float* __restrict__ C,
                                                   int M, int N, int K) {
    __shared__ uint32_t AsH[128 * AS_ST];
    __shared__ uint32_t AsL[128 * AS_ST];
    __shared__ uint32_t BsH[16 * BS_ST];
    __shared__ uint32_t BsL[16 * BS_ST];
    int tid = threadIdx.x;
    int lane = tid & 31;
    int warp = tid >> 5;
    int wm = warp & 3;
    int wn = warp >> 2;
    int row0 = blockIdx.y * 128;
    int col0 = blockIdx.x * 128;

    float acc[2][8][4];
#pragma unroll
    for (int mi = 0; mi < 2; mi++)
#pragma unroll
        for (int nj = 0; nj < 8; nj++)
#pragma unroll
            for (int e = 0; e < 4; e++) acc[mi][nj][e] = 0.f;

    int lr = lane >> 2;
    int lc = lane & 3;

    for (int k0 = 0; k0 < K; k0 += 16) {
#pragma unroll
        for (int i = 0; i < 2; i++) {
            int f = i * 256 + tid;
            int r = f >> 2;
            int c = (f & 3) << 2;
            float4 v = *(const float4*)(A + (size_t)(row0 + r) * K + k0 + c);
            uint32_t* dh = &AsH[r * AS_ST + c];
            uint32_t* dl = &AsL[r * AS_ST + c];
            uint32_t h0 = f2tf32(v.x), h1 = f2tf32(v.y), h2 = f2tf32(v.z), h3 = f2tf32(v.w);
            dh[0] = h0; dh[1] = h1; dh[2] = h2; dh[3] = h3;
            dl[0] = f2tf32(v.x - __uint_as_float(h0));
            dl[1] = f2tf32(v.y - __uint_as_float(h1));
            dl[2] = f2tf32(v.z - __uint_as_float(h2));
            dl[3] = f2tf32(v.w - __uint_as_float(h3));
        }
#pragma unroll
        for (int i = 0; i < 2; i++) {
            int f = i * 256 + tid;
            int r = f >> 5;
            int c = (f & 31) << 2;
            float4 v = *(const float4*)(B + (size_t)(k0 + r) * N + col0 + c);
            uint32_t* dh = &BsH[r * BS_ST + c];
            uint32_t* dl = &BsL[r * BS_ST + c];
            uint32_t h0 = f2tf32(v.x), h1 = f2tf32(v.y), h2 = f2tf32(v.z), h3 = f2tf32(v.w);
            dh[0] = h0; dh[1] = h1; dh[2] = h2; dh[3] = h3;
            dl[0] = f2tf32(v.x - __uint_as_float(h0));
            dl[1] = f2tf32(v.y - __uint_as_float(h1));
            dl[2] = f2tf32(v.z - __uint_as_float(h2));
            dl[3] = f2tf32(v.w - __uint_as_float(h3));
        }
        __syncthreads();

#pragma unroll
        for (int ks = 0; ks < 2; ks++) {
            int kb = ks * 8;
            uint32_t aH[2][4], aL[2][4];
#pragma unroll
            for (int mi = 0; mi < 2; mi++) {
                int r = wm * 32 + mi * 16 + lr;
                aH[mi][0] = AsH[r * AS_ST + kb + lc];
                aH[mi][1] = AsH[(r + 8) * AS_ST + kb + lc];
                aH[mi][2] = AsH[r * AS_ST + kb + lc + 4];
                aH[mi][3] = AsH[(r + 8) * AS_ST + kb + lc + 4];
                aL[mi][0] = AsL[r * AS_ST + kb + lc];
                aL[mi][1] = AsL[(r + 8) * AS_ST + kb + lc];
                aL[mi][2] = AsL[r * AS_ST + kb + lc + 4];
                aL[mi][3] = AsL[(r + 8) * AS_ST + kb + lc + 4];
            }
#pragma unroll
            for (int nj = 0; nj < 8; nj++) {
                int c = wn * 64 + nj * 8 + lr;
                uint32_t b0h = BsH[(kb + lc) * BS_ST + c];
                uint32_t b1h = BsH[(kb + lc + 4) * BS_ST + c];
                uint32_t b0l = BsL[(kb + lc) * BS_ST + c];
                uint32_t b1l = BsL[(kb + lc + 4) * BS_ST + c];
#pragma unroll
                for (int mi = 0; mi < 2; mi++) {
                    mma_tf32(acc[mi][nj], aH[mi], b0h, b1h);
                    mma_tf32(acc[mi][nj], aH[mi], b0l, b1l);
                    mma_tf32(acc[mi][nj], aL[mi], b0h, b1h);
                }
            }
        }
        __syncthreads();
    }

#pragma unroll
    for (int mi = 0; mi < 2; mi++) {
        int row = row0 + wm * 32 + mi * 16 + lr;
#pragma unroll
        for (int nj = 0; nj < 8; nj++) {
            int col = col0 + wn * 64 + nj * 8 + 2 * lc;
            float* cp0 = C + (size_t)row * N + col;
            cp0[0] = acc[mi][nj][0];
            cp0[1] = acc[mi][nj][1];
            float* cp1 = C + (size_t)(row + 8) * N + col;
            cp1[0] = acc[mi][nj][2];
            cp1[1] = acc[mi][nj][3];
        }
    }
}

// ---------------- exact fp32 q rows 0..63: split-K --------------------------
__global__ __launch_bounds__(128) void qproj_part(const float* __restrict__ x,
                                                  const float* __restrict__ wq,
                                                  float* __restrict__ part) {
    __shared__ float xs[8][256];
    int tid = threadIdx.x;
    int col = blockIdx.x * 128 + tid;
    int r0 = blockIdx.y * 8;
    int k0 = blockIdx.z * 256;
    float acc[8];
#pragma unroll
    for (int rr = 0; rr < 8; rr++) acc[rr] = 0.f;

    for (int i = tid; i < 8 * 256; i += 128) {
        int rr = i >> 8, kk = i & 255;
        xs[rr][kk] = x[(size_t)(r0 + rr) * DIM + k0 + kk];
    }
    __syncthreads();
    for (int kk = 0; kk < 256; kk++) {
        float w = wq[(size_t)(k0 + kk) * DIM + col];
#pragma unroll
        for (int rr = 0; rr < 8; rr++) acc[rr] += xs[rr][kk] * w;
    }
#pragma unroll
    for (int rr = 0; rr < 8; rr++)
        part[(size_t)blockIdx.z * ESTQ * DIM + (size_t)(r0 + rr) * DIM + col] = acc[rr];
}

__global__ void qproj_red(const float* __restrict__ part, float* __restrict__ q64) {
    int idx = blockIdx.x * 256 + threadIdx.x;
    if (idx >= ESTQ * DIM) return;
    float s = 0.f;
#pragma unroll
    for (int ks = 0; ks < 8; ks++) s += part[(size_t)ks * ESTQ * DIM + idx];
    q64[idx] = s;
}

// ---------------- RoPE in place on [S][H][64] ----------------------------
__global__ void rope_kernel(float* t, const float* __restrict__ cosb,
                            const float* __restrict__ sinb, int H, int total) {
    int idx = blockIdx.x * blockDim.x + threadIdx.x;
    if (idx >= total) return;
    int d2 = idx & 31;
    int h = (idx >> 5) % H;
    int s = idx / (32 * H);
    float c = cosb[s * 32 + d2];
    float sn = sinb[s * 32 + d2];
    float* p = t + ((size_t)s * H + h) * 64 + 2 * d2;
    float xr = p[0], xi = p[1];
    p[0] = xr * c - xi * sn;
    p[1] = xr * sn + xi * c;
}

// ---------------- est phase A: raw masked scores ---------------------------
__global__ __launch_bounds__(256) void est_score(const float* __restrict__ q64,
                                                 const float* __restrict__ k,
                                                 float* __restrict__ probs) {
    __shared__ float qs[64][68];
    __shared__ float ksm[64][68];
    int tid = threadIdx.x;
    int h = blockIdx.y;
    int c0 = blockIdx.x * 64;
    int kvh = h >> 2;
    int qi = tid >> 2;
    int kg = tid & 3;

    for (int l = tid; l < 64 * 64; l += 256) {
        int r = l >> 6, d = l & 63;
        qs[r][d] = q64[(size_t)r * DIM + h * HD + d];
        ksm[r][d] = k[(size_t)(c0 + r) * (NKV * HD) + kvh * HD + d];
    }
    __syncthreads();

    float s16[16];
#pragma unroll
    for (int j = 0; j < 16; j++) s16[j] = 0.f;
#pragma unroll
    for (int d4 = 0; d4 < 16; d4++) {
        float4 q4 = *(float4*)&qs[qi][d4 * 4];
#pragma unroll
        for (int j = 0; j < 16; j++) {
            float4 k4 = *(float4*)&ksm[kg * 16 + j][d4 * 4];
            s16[j] += q4.x * k4.x + q4.y * k4.y + q4.z * k4.z + q4.w * k4.w;
        }
    }
    float* pr = probs + ((size_t)h * ESTQ + qi) * SEQ + c0 + kg * 16;
#pragma unroll
    for (int j = 0; j < 16; j++) {
        int kk = c0 + kg * 16 + j;
        float val = s16[j] * SCALE;
        if (kk >= SEQ - ESTQ && qi < kk - (SEQ - ESTQ)) val = -INFINITY;
        pr[j] = val;
    }
}

// ---------------- est phase B: row softmax in place ------------------------
__global__ __launch_bounds__(256) void est_norm(float* __restrict__ probs) {
    int qi = blockIdx.x;
    int h = blockIdx.y;
    __shared__ float sc[SEQ];
    __shared__ float red[8];
    int tid = threadIdx.x;
    float* pr = probs + ((size_t)h * ESTQ + qi) * SEQ;

    for (int l = tid; l < SEQ / 4; l += 256)
        *(float4*)&sc[l * 4] = *(const float4*)&pr[l * 4];
    __syncthreads();

    float m = -INFINITY;
    for (int kk = tid; kk < SEQ; kk += 256) m = fmaxf(m, sc[kk]);
#pragma unroll
    for (int o = 16; o; o >>= 1) m = fmaxf(m, __shfl_xor_sync(0xFFFFFFFFu, m, o));
    if ((tid & 31) == 0) red[tid >> 5] = m;
    __syncthreads();
    if (tid == 0) {
        float mm = red[0];
#pragma unroll
        for (int i = 1; i < 8; i++) mm = fmaxf(mm, red[i]);
        red[0] = mm;
    }
    __syncthreads();
    m = red[0];
    __syncthreads();

    float s = 0.f;
    for (int kk = tid; kk < SEQ; kk += 256) {
        float e = expf(sc[kk] - m);
        sc[kk] = e;
        s += e;
    }
#pragma unroll
    for (int o = 16; o; o >>= 1) s += __shfl_xor_sync(0xFFFFFFFFu, s, o);
    if ((tid & 31) == 0) red[tid >> 5] = s;
    __syncthreads();
    if (tid == 0) {
        float ss = 0.f;
#pragma unroll
        for (int i = 0; i < 8; i++) ss += red[i];
        red[0] = ss;
    }
    __syncthreads();
    float inv = 1.f / red[0];
    for (int kk = tid; kk < SEQ; kk += 256) pr[kk] = sc[kk] * inv;
}

// ---------------- vertical column sums -----------------------------------
__global__ void vertical_kernel(const float* __restrict__ probs, float* __restrict__ vert) {
    int idx = blockIdx.x * 256 + threadIdx.x;
    int h = idx >> 12;
    int kk = idx & (SEQ - 1);
    float s = 0.f;
    const float* base = probs + (size_t)h * ESTQ * SEQ + kk;
    for (int i = 0; i < ESTQ; i++) s += base[(size_t)i * SEQ];
    vert[idx] = s;
}

// ---------------- diagonal sums ------------------------------------------
__global__ void diag_kernel(const float* __restrict__ probs, float* __restrict__ dg) {
    int idx = blockIdx.x * 256 + threadIdx.x;
    int h = idx >> 12;
    int jp = idx & (SEQ - 1);
    float s = 0.f;
    const float* base = probs + (size_t)h * ESTQ * SEQ;
    for (int i = 0; i < ESTQ; i++) {
        int col = i + jp - 63;
        if (col >= 0 && col < SEQ) s += base[(size_t)i * SEQ + col];
    }
    dg[idx] = s;
}

// ---------------- per-head top-k via bitonic sort -------------------------
__global__ void topk_kernel(const float* __restrict__ vals, int kcount, int mode,
                            int* __restrict__ keys) {
    int h = blockIdx.x;
    __shared__ unsigned long long a[SEQ];
    int tid = threadIdx.x;  // 512
    for (int i = tid; i < SEQ; i += 512) {
        unsigned u = __float_as_uint(vals[h * SEQ + i]);
        u = (u & 0x80000000u) ? ~u : (u | 0x80000000u);
        a[i] = ((unsigned long long)(~u) << 32) | (unsigned)i;
    }
    __syncthreads();
    for (int k = 2; k <= SEQ; k <<= 1) {
        for (int j = k >> 1; j > 0; j >>= 1) {
            for (int i = tid; i < SEQ; i += 512) {
                int ixj = i ^ j;
                if (ixj > i) {
                    bool up = ((i & k) == 0);
                    unsigned long long x = a[i], y = a[ixj];
                    if (up ? (x > y) : (x < y)) { a[i] = y; a[ixj] = x; }
                }
            }
            __syncthreads();
        }
    }
    if (mode == 0) {
        for (int t = tid; t < kcount; t += 512)
            keys[h * NKEYP + t] = (int)(a[t] & 0xFFFFFFFFull);
    } else {
        for (int t = tid; t < kcount; t += 512)
            keys[h * NKEYP + VSZ + t] = (SEQ - 1) - (int)(a[t] & 0xFFFFFFFFull);
        for (int t = NKEY + tid; t < NKEYP; t += 512) keys[h * NKEYP + t] = PADKEY;
    }
}

// ---------------- sort keys ascending per head -----------------------------
__global__ __launch_bounds__(256) void sortkeys_kernel(int* __restrict__ keys) {
    int h = blockIdx.x;
    __shared__ int a[2048];
    int tid = threadIdx.x;
    for (int i = tid; i < 2048; i += 256)
        a[i] = (i < NKEYP) ? keys[h * NKEYP + i] : PADKEY;
    __syncthreads();
    for (int k = 2; k <= 2048; k <<= 1) {
        for (int j = k >> 1; j > 0; j >>= 1) {
            for (int i = tid; i < 2048; i += 256) {
                int ixj = i ^ j;
                if (ixj > i) {
                    bool up = ((i & k) == 0);
                    int x = a[i], y = a[ixj];
                    if (up ? (x > y) : (x < y)) { a[i] = y; a[ixj] = x; }
                }
            }
            __syncthreads();
        }
    }
    for (int i = tid; i < NKEYP; i += 256) keys[h * NKEYP + i] = a[i];
}

// ---------------- gather sparse K/V rows ----------------------------------
__global__ void gather_kernel(const float* __restrict__ k, const float* __restrict__ v,
                              const int* __restrict__ keys,
                              float* __restrict__ ksp, float* __restrict__ vsp) {
    int j = blockIdx.x;
    int h = j / NKEYP;
    int d = threadIdx.x;
    int key = keys[j];
    int kvh = h >> 2;
    float kv = 0.f, vv = 0.f;
    if (key < SEQ) {
        kv = k[(size_t)key * (NKV * HD) + kvh * HD + d];
        vv = v[(size_t)key * (NKV * HD) + kvh * HD + d];
    }
    ksp[(size_t)j * HD + d] = kv;
    vsp[(size_t)j * HD + d] = vv;
}

// ---------------- sparse attention v3: TC QK (3xTF32) + SIMT PV ----------
// dynamic smem layout (u32 words):
//   qhl: 64 x 132  (hi in cols 0..63, lo in cols 64..127)
//   khl: 32 x 132
//   vs : 32 x 68 floats
//   ss : 64 x 36 floats
//   kid: 32 ints
#define QHL_ST 132
#define SP_WORDS (64 * 132 + 32 * 132 + 32 * 68 + 64 * 36 + 32)

__global__ __launch_bounds__(256) void spattn_kernel(const float* __restrict__ q,
                                                     const float* __restrict__ ksp,
                                                     const float* __restrict__ vsp,
                                                     const int* __restrict__ keys,
                                                     float* __restrict__ attout) {
    extern __shared__ uint32_t smem[];
    uint32_t* qhl = smem;                         // 64*132
    uint32_t* khl = qhl + 64 * 132;               // 32*132
    float* vs = (float*)(khl + 32 * 132);         // 32*68
    float* ss = vs + 32 * 68;                     // 64*36
    int* kid = (int*)(ss + 64 * 36);              // 32

    int qb = blockIdx.x;
    int h = blockIdx.y;
    int tid = threadIdx.x;
    int lane = tid & 31;
    int warp = tid >> 5;
    int lr = lane >> 2;
    int lc = lane & 3;
    int wm = warp & 3;       // m-slab (16 rows)
    int wn = warp >> 2;      // n-half (16 cols)
    int qp = tid >> 3;
    int g = tid & 7;
    int qi0 = qp, qi1 = qp + 32;
    int sglob0 = qb * 64 + qi0;
    int sglob1 = qb * 64 + qi1;
    int qbmax = qb * 64 + 63;

    // load q tile 64x64 -> hi/lo tf32 smem (done once)
    for (int l = tid; l < 64 * 16; l += 256) {
        int r = l >> 4, c4 = (l & 15) * 4;
        float4 v = *(const float4*)&q[(size_t)(qb * 64 + r) * DIM + h * HD + c4];
        uint32_t* dh = &qhl[r * QHL_ST + c4];
        uint32_t h0 = f2tf32(v.x), h1 = f2tf32(v.y), h2 = f2tf32(v.z), h3 = f2tf32(v.w);
        dh[0] = h0; dh[1] = h1; dh[2] = h2; dh[3] = h3;
        dh[64] = f2tf32(v.x - __uint_as_float(h0));
        dh[65] = f2tf32(v.y - __uint_as_float(h1));
        dh[66] = f2tf32(v.z - __uint_as_float(h2));
        dh[67] = f2tf32(v.w - __uint_as_float(h3));
    }

    float m0 = -INFINITY, m1 = -INFINITY, lsum0 = 0.f, lsum1 = 0.f;
    float out0[8], out1[8];
#pragma unroll
    for (int i = 0; i < 8; i++) { out0[i] = 0.f; out1[i] = 0.f; }

    for (int t = 0; t < NKEYP / 32; t++) {
        __syncthreads();
        if (tid < 32) kid[tid] = keys[h * NKEYP + t * 32 + tid];
        __syncthreads();
        if (kid[0] > qbmax) continue;  // whole tile causally masked

        // load k tile -> hi/lo, v tile -> fp32
        for (int l = tid; l < 32 * 16; l += 256) {
            int r = l >> 4, c4 = (l & 15) * 4;
            float4 kv = *(const float4*)&ksp[((size_t)h * NKEYP + t * 32 + r) * HD + c4];
            uint32_t* dh = &khl[r * QHL_ST + c4];
            uint32_t h0 = f2tf32(kv.x), h1 = f2tf32(kv.y), h2 = f2tf32(kv.z), h3 = f2tf32(kv.w);
            dh[0] = h0; dh[1] = h1; dh[2] = h2; dh[3] = h3;
            dh[64] = f2tf32(kv.x - __uint_as_float(h0));
            dh[65] = f2tf32(kv.y - __uint_as_float(h1));
            dh[66] = f2tf32(kv.z - __uint_as_float(h2));
            dh[67] = f2tf32(kv.w - __uint_as_float(h3));
            *(float4*)&vs[r * 68 + c4] =
                *(const float4*)&vsp[((size_t)h * NKEYP + t * 32 + r) * HD + c4];
        }
        __syncthreads();

        // QK via tensor cores: S[64][32], warp (wm, wn) -> rows wm*16.., cols wn*16..
        {
            float acc[2][4];
#pragma unroll
            for (int nt = 0; nt < 2; nt++)
#pragma unroll
                for (int e = 0; e < 4; e++) acc[nt][e] = 0.f;
#pragma unroll
            for (int ksI = 0; ksI < 8; ksI++) {
                int kb = ksI * 8;
                int ra = wm * 16 + lr;
                uint32_t aH[4], aL[4];
                aH[0] = qhl[ra * QHL_ST + kb + lc];
                aH[1] = qhl[(ra + 8) * QHL_ST + kb + lc];
                aH[2] = qhl[ra * QHL_ST + kb + lc + 4];
                aH[3] = qhl[(ra + 8) * QHL_ST + kb + lc + 4];
                aL[0] = qhl[ra * QHL_ST + 64 + kb + lc];
                aL[1] = qhl[(ra + 8) * QHL_ST + 64 + kb + lc];
                aL[2] = qhl[ra * QHL_ST + 64 + kb + lc + 4];
                aL[3] = qhl[(ra + 8) * QHL_ST + 64 + kb + lc + 4];
#pragma unroll
                for (int nt = 0; nt < 2; nt++) {
                    int n0 = wn * 16 + nt * 8;
                    uint32_t b0h = khl[(n0 + lr) * QHL_ST + kb + lc];
                    uint32_t b1h = khl[(n0 + lr) * QHL_ST + kb + lc + 4];
                    uint32_t b0l = khl[(n0 + lr) * QHL_ST + 64 + kb + lc];
                    uint32_t b1l = khl[(n0 + lr) * QHL_ST + 64 + kb + lc + 4];
                    mma_tf32(acc[nt], aH, b0h, b1h);
                    mma_tf32(acc[nt], aH, b0l, b1l);
                    mma_tf32(acc[nt], aL, b0h, b1h);
                }
            }
            // write raw S to ss
#pragma unroll
            for (int nt = 0; nt < 2; nt++) {
                int row = wm * 16 + lr;
                int col = wn * 16 + nt * 8 + 2 * lc;
                ss[row * 36 + col] = acc[nt][0];
                ss[row * 36 + col + 1] = acc[nt][1];
                ss[(row + 8) * 36 + col] = acc[nt][2];
                ss[(row + 8) * 36 + col + 1] = acc[nt][3];
            }
        }
        __syncthreads();

        // mask + scale (same mapping as R5)
#pragma unroll
        for (int j = 0; j < 4; j++) {
            int jj = g * 4 + j;
            int key = kid[jj];
            float r0 = ss[qi0 * 36 + jj];
            float r1 = ss[qi1 * 36 + jj];
            float v0, v1;
            if (key >= SEQ) { v0 = -INFINITY; v1 = -INFINITY; }
            else {
                v0 = (key <= sglob0) ? r0 * SCALE : -1e30f;
                v1 = (key <= sglob1) ? r1 * SCALE : -1e30f;
            }
            ss[qi0 * 36 + jj] = v0;
            ss[qi1 * 36 + jj] = v1;
        }
        __syncthreads();

        // per-query tile max (redundant across 8 g-threads)
        float tm0 = m0, tm1 = m1;
#pragma unroll
        for (int j = 0; j < 32; j++) {
            tm0 = fmaxf(tm0, ss[qi0 * 36 + j]);
            tm1 = fmaxf(tm1, ss[qi1 * 36 + j]);
        }
        float c0 = expf(m0 - tm0);
        float c1 = expf(m1 - tm1);
        m0 = tm0; m1 = tm1;
        lsum0 *= c0; lsum1 *= c1;
#pragma unroll
        for (int i = 0; i < 8; i++) { out0[i] *= c0; out1[i] *= c1; }
        __syncthreads();  // all raw reads done before exp overwrite

#pragma unroll
        for (int j = 0; j < 4; j++) {
            int jj = g * 4 + j;
            ss[qi0 * 36 + jj] = expf(ss[qi0 * 36 + jj] - m0);
            ss[qi1 * 36 + jj] = expf(ss[qi1 * 36 + jj] - m1);
        }
        __syncthreads();

        float ps0 = 0.f, ps1 = 0.f;
#pragma unroll
        for (int j = 0; j < 32; j++) {
            float p0 = ss[qi0 * 36 + j];
            float p1 = ss[qi1 * 36 + j];
            ps0 += p0; ps1 += p1;
            float4 va = *(float4*)&vs[j * 68 + g * 8];
            float4 vb = *(float4*)&vs[j * 68 + g * 8 + 4];
            out0[0] += p0 * va.x; out0[1] += p0 * va.y; out0[2] += p0 * va.z; out0[3] += p0 * va.w;
            out0[4] += p0 * vb.x; out0[5] += p0 * vb.y; out0[6] += p0 * vb.z; out0[7] += p0 * vb.w;
            out1[0] += p1 * va.x; out1[1] += p1 * va.y; out1[2] += p1 * va.z; out1[3] += p1 * va.w;
            out1[4] += p1 * vb.x; out1[5] += p1 * vb.y; out1[6] += p1 * vb.z; out1[7] += p1 * vb.w;
        }
        lsum0 += ps0;
        lsum1 += ps1;
    }

    // fallback for all-masked queries: uniform over all real keys (= ref)
    if (m0 < -5e29f) {
        lsum0 = (float)NKEY;
#pragma unroll
        for (int i = 0; i < 8; i++) out0[i] = 0.f;
        for (int j = 0; j < NKEYP; j++) {
            if (keys[h * NKEYP + j] < SEQ) {
                const float* vr = &vsp[((size_t)h * NKEYP + j) * HD + g * 8];
#pragma unroll
                for (int i = 0; i < 8; i++) out0[i] += vr[i];
            }
        }
    }
    if (m1 < -5e29f) {
        lsum1 = (float)NKEY;
#pragma unroll
        for (int i = 0; i < 8; i++) out1[i] = 0.f;
        for (int j = 0; j < NKEYP; j++) {
            if (keys[h * NKEYP + j] < SEQ) {
                const float* vr = &vsp[((size_t)h * NKEYP + j) * HD + g * 8];
#pragma unroll
                for (int i = 0; i < 8; i++) out1[i] += vr[i];
            }
        }
    }

    float inv0 = 1.f / lsum0;
    float inv1 = 1.f / lsum1;
#pragma unroll
    for (int i = 0; i < 8; i++) {
        attout[(size_t)sglob0 * DIM + h * HD + g * 8 + i] = out0[i] * inv0;
        attout[(size_t)sglob1 * DIM + h * HD + g * 8 + i] = out1[i] * inv1;
    }
}

// --------------------------------- launch --------------------------------
extern "C" void kernel_launch(void* const* d_in, const int* in_sizes, int n_in,
                              void* d_out, int out_size) {
    const float* x    = (const float*)d_in[0];
    const float* fcos = (const float*)d_in[1];
    const float* fsin = (const float*)d_in[2];
    const float* wq   = (const float*)d_in[3];
    const float* wk   = (const float*)d_in[4];
    const float* wv   = (const float*)d_in[5];
    const float* wo   = (const float*)d_in[6];
    float* out = (float*)d_out;

    float *q, *q64, *q64p, *k, *v, *probs, *vert, *dgp, *ksp, *vsp, *att;
    int* keys;
    cudaGetSymbolAddress((void**)&q, g_q);
    cudaGetSymbolAddress((void**)&q64, g_q64);
    cudaGetSymbolAddress((void**)&q64p, g_q64p);
    cudaGetSymbolAddress((void**)&k, g_k);
    cudaGetSymbolAddress((void**)&v, g_v);
    cudaGetSymbolAddress((void**)&probs, g_probs);
    cudaGetSymbolAddress((void**)&vert, g_vert);
    cudaGetSymbolAddress((void**)&dgp, g_diag);
    cudaGetSymbolAddress((void**)&keys, g_keys);
    cudaGetSymbolAddress((void**)&ksp, g_ksp);
    cudaGetSymbolAddress((void**)&vsp, g_vsp);
    cudaGetSymbolAddress((void**)&att, g_att);

    // projections: q 1x tf32, k/v 3xTF32
    gemm_tf32_1x<<<dim3(DIM / 128, SEQ / 128), 256>>>(x, wq, q, SEQ, DIM, DIM);
    gemm_tf32x3<<<dim3((NKV * HD) / 128, SEQ / 128), 256>>>(x, wk, k, SEQ, NKV * HD, DIM);
    gemm_tf32x3<<<dim3((NKV * HD) / 128, SEQ / 128), 256>>>(x, wv, v, SEQ, NKV * HD, DIM);

    // exact fp32 q rows 0..63 via split-K
    qproj_part<<<dim3(16, 8, 8), 128>>>(x, wq, q64p);
    qproj_red<<<(ESTQ * DIM + 255) / 256, 256>>>(q64p, q64);

    // RoPE
    {
        int tq = SEQ * NH * 32;
        rope_kernel<<<(tq + 255) / 256, 256>>>(q, fcos, fsin, NH, tq);
        int tk = SEQ * NKV * 32;
        rope_kernel<<<(tk + 255) / 256, 256>>>(k, fcos, fsin, NKV, tk);
        int tq64 = ESTQ * NH * 32;
        rope_kernel<<<(tq64 + 255) / 256, 256>>>(q64, fcos, fsin, NH, tq64);
    }

    // estimation: scores then row softmax
    est_score<<<dim3(SEQ / 64, NH), 256>>>(q64, k, probs);
    est_norm<<<dim3(ESTQ, NH), 256>>>(probs);

    // vertical / diagonal scores
    vertical_kernel<<<(NH * SEQ) / 256, 256>>>(probs, vert);
    diag_kernel<<<(NH * SEQ) / 256, 256>>>(probs, dgp);

    // top-k selections
    topk_kernel<<<NH, 512>>>(vert, VSZ, 0, keys);
    topk_kernel<<<NH, 512>>>(dgp, SSZ, 1, keys);

    // sort keys ascending (order-invariant; enables tile skipping)
    sortkeys_kernel<<<NH, 256>>>(keys);

    // gather sparse K/V
    gather_kernel<<<NH * NKEYP, 64>>>(k, v, keys, ksp, vsp);

    // sparse attention: TC QK (3xTF32) + SIMT PV, tile skip
    {
        size_t spbytes = (size_t)SP_WORDS * 4;
        cudaFuncSetAttribute(spattn_kernel,
                             cudaFuncAttributeMaxDynamicSharedMemorySize, (int)spbytes);
        spattn_kernel<<<dim3(SEQ / 64, NH), 256, spbytes>>>(q, ksp, vsp, keys, att);
    }

    // output projection (1x tf32)
    gemm_tf32_1x<<<dim3(DIM / 128, SEQ / 128), 256>>>(att, wo, out, SEQ, DIM, DIM);
}

// round 7
// speedup vs baseline: 2.5383x; 1.0014x over previous
#include <cuda_runtime.h>
#include <math.h>
#include <stdint.h>

#define SEQ   4096
#define DIM   2048
#define NH    32
#define NKV   8
#define HD    64
#define ESTQ  64
#define VSZ   300
#define SSZ   800
#define NKEY  1100
#define NKEYP 1152
#define SCALE 0.125f   // 1/sqrt(64)
#define PADKEY 0x3FFFFFFF
#define KVW   1024     // fused k|v row width

// ---------------- device scratch (no allocation allowed) ----------------
__device__ float g_q[SEQ * DIM];            // tf32-accurate q
__device__ float g_q64[ESTQ * DIM];         // exact fp32 q rows 0..63
__device__ float g_q64p[8 * ESTQ * DIM];    // split-K partials
__device__ float g_wkv[DIM * KVW];          // [wk | wv] fused weights
__device__ float g_kv[SEQ * KVW];           // fused k|v output (k: 0..511, v: 512..1023)
__device__ float g_probs[NH * ESTQ * SEQ];
__device__ float g_vert[NH * SEQ];
__device__ float g_diag[NH * SEQ];
__device__ int   g_keys[NH * NKEYP];
__device__ float g_ksp[NH * NKEYP * HD];
__device__ float g_vsp[NH * NKEYP * HD];
__device__ float g_att[SEQ * DIM];

// ---------------- common tf32 helpers ------------------------------------
__device__ __forceinline__ uint32_t f2tf32(float f) {
    uint32_t r;
    asm("cvt.rna.tf32.f32 %0, %1;" : "=r"(r) : "f"(f));
    return r;
}

__device__ __forceinline__ void mma_tf32(float c[4], const uint32_t a[4],
                                         uint32_t b0, uint32_t b1) {
    asm volatile(
        "mma.sync.aligned.m16n8k8.row.col.f32.tf32.tf32.f32 "
        "{%0,%1,%2,%3}, {%4,%5,%6,%7}, {%8,%9}, {%0,%1,%2,%3};\n"
        : "+f"(c[0]), "+f"(c[1]), "+f"(c[2]), "+f"(c[3])
        : "r"(a[0]), "r"(a[1]), "r"(a[2]), "r"(a[3]), "r"(b0), "r"(b1));
}

// ================= single-pass tf32 GEMM (BK=32, prefetch) ================
#define A1_ST 36
#define B1_ST 132

__global__ __launch_bounds__(256) void gemm_tf32_1x(const float* __restrict__ A,
                                                    const float* __restrict__ B,
                                                    float* __restrict__ C,
                                                    int M, int N, int K) {
    __shared__ uint32_t As[128 * A1_ST];
    __shared__ uint32_t Bs[32 * B1_ST];
    int tid = threadIdx.x;
    int lane = tid & 31;
    int warp = tid >> 5;
    int wm = warp & 3;
    int wn = warp >> 2;
    int row0 = blockIdx.y * 128;
    int col0 = blockIdx.x * 128;

    float acc[2][8][4];
#pragma unroll
    for (int mi = 0; mi < 2; mi++)
#pragma unroll
        for (int nj = 0; nj < 8; nj++)
#pragma unroll
            for (int e = 0; e < 4; e++) acc[mi][nj][e] = 0.f;

    int lr = lane >> 2;
    int lc = lane & 3;

    // prefetch registers
    float4 aReg[4], bReg[4];
#pragma unroll
    for (int i = 0; i < 4; i++) {
        int f = i * 256 + tid;
        aReg[i] = *(const float4*)(A + (size_t)(row0 + (f >> 3)) * K + ((f & 7) << 2));
        bReg[i] = *(const float4*)(B + (size_t)(f >> 5) * N + col0 + ((f & 31) << 2));
    }

    for (int k0 = 0; k0 < K; k0 += 32) {
        // store prefetched tile to smem (with tf32 convert)
#pragma unroll
        for (int i = 0; i < 4; i++) {
            int f = i * 256 + tid;
            uint32_t* da = &As[(f >> 3) * A1_ST + ((f & 7) << 2)];
            da[0] = f2tf32(aReg[i].x);
            da[1] = f2tf32(aReg[i].y);
            da[2] = f2tf32(aReg[i].z);
            da[3] = f2tf32(aReg[i].w);
            uint32_t* db = &Bs[(f >> 5) * B1_ST + ((f & 31) << 2)];
            db[0] = f2tf32(bReg[i].x);
            db[1] = f2tf32(bReg[i].y);
            db[2] = f2tf32(bReg[i].z);
            db[3] = f2tf32(bReg[i].w);
        }
        __syncthreads();

        // issue next tile's global loads early
        if (k0 + 32 < K) {
#pragma unroll
            for (int i = 0; i < 4; i++) {
                int f = i * 256 + tid;
                aReg[i] = *(const float4*)(A + (size_t)(row0 + (f >> 3)) * K + k0 + 32 + ((f & 7) << 2));
                bReg[i] = *(const float4*)(B + (size_t)(k0 + 32 + (f >> 5)) * N + col0 + ((f & 31) << 2));
            }
        }

#pragma unroll
        for (int ks = 0; ks < 4; ks++) {
            int kb = ks * 8;
            uint32_t a[2][4];
#pragma unroll
            for (int mi = 0; mi < 2; mi++) {
                int r = wm * 32 + mi * 16 + lr;
                a[mi][0] = As[r * A1_ST + kb + lc];
                a[mi][1] = As[(r + 8) * A1_ST + kb + lc];
                a[mi][2] = As[r * A1_ST + kb + lc + 4];
                a[mi][3] = As[(r + 8) * A1_ST + kb + lc + 4];
            }
#pragma unroll
            for (int nj = 0; nj < 8; nj++) {
                int c = wn * 64 + nj * 8 + lr;
                uint32_t b0 = Bs[(kb + lc) * B1_ST + c];
                uint32_t b1 = Bs[(kb + lc + 4) * B1_ST + c];
                mma_tf32(acc[0][nj], a[0], b0, b1);
                mma_tf32(acc[1][nj], a[1], b0, b1);
            }
        }
        __syncthreads();
    }

#pragma unroll
    for (int mi = 0; mi < 2; mi++) {
        int row = row0 + wm * 32 + mi * 16 + lr;
#pragma unroll
        for (int nj = 0; nj < 8; nj++) {
            int col = col0 + wn * 64 + nj * 8 + 2 * lc;
            float* cp0 = C + (size_t)row * N + col;
            cp0[0] = acc[mi][nj][0];
            cp0[1] = acc[mi][nj][1];
            float* cp1 = C + (size_t)(row + 8) * N + col;
            cp1[0] = acc[mi][nj][2];
            cp1[1] = acc[mi][nj][3];
        }
    }
}

// ================= 3xTF32 GEMM (BK=16, prefetch), ~fp32 accuracy ==========
#define AS_ST 20
#define BS_ST 132

__global__ __launch_bounds__(256) void gemm_tf32x3(const float* __restrict__ A,
                                                   const float* __restrict__ B,
                                                   float* __restrict__ C,
                                                   int M, int N, int K) {
    __shared__ uint32_t AsH[128 * AS_ST];
    __shared__ uint32_t AsL[128 * AS_ST];
    __shared__ uint32_t BsH[16 * BS_ST];
    __shared__ uint32_t BsL[16 * BS_ST];
    int tid = threadIdx.x;
    int lane = tid & 31;
    int warp = tid >> 5;
    int wm = warp & 3;
    int wn = warp >> 2;
    int row0 = blockIdx.y * 128;
    int col0 = blockIdx.x * 128;

    float acc[2][8][4];
#pragma unroll
    for (int mi = 0; mi < 2; mi++)
#pragma unroll
        for (int nj = 0; nj < 8; nj++)
#pragma unroll
            for (int e = 0; e < 4; e++) acc[mi][nj][e] = 0.f;

    int lr = lane >> 2;
    int lc = lane & 3;

    float4 aReg[2], bReg[2];
#pragma unroll
    for (int i = 0; i < 2; i++) {
        int f = i * 256 + tid;
        aReg[i] = *(const float4*)(A + (size_t)(row0 + (f >> 2)) * K + ((f & 3) << 2));
        bReg[i] = *(const float4*)(B + (size_t)(f >> 5) * N + col0 + ((f & 31) << 2));
    }

    for (int k0 = 0; k0 < K; k0 += 16) {
#pragma unroll
        for (int i = 0; i < 2; i++) {
            int f = i * 256 + tid;
            int ra = f >> 2, ca = (f & 3) << 2;
            uint32_t* dh = &AsH[ra * AS_ST + ca];
            uint32_t* dl = &AsL[ra * AS_ST + ca];
            uint32_t h0 = f2tf32(aReg[i].x), h1 = f2tf32(aReg[i].y);
            uint32_t h2 = f2tf32(aReg[i].z), h3 = f2tf32(aReg[i].w);
            dh[0] = h0; dh[1] = h1; dh[2] = h2; dh[3] = h3;
            dl[0] = f2tf32(aReg[i].x - __uint_as_float(h0));
            dl[1] = f2tf32(aReg[i].y - __uint_as_float(h1));
            dl[2] = f2tf32(aReg[i].z - __uint_as_float(h2));
            dl[3] = f2tf32(aReg[i].w - __uint_as_float(h3));
            int rb = f >> 5, cb = (f & 31) << 2;
            uint32_t* eh = &BsH[rb * BS_ST + cb];
            uint32_t* el = &BsL[rb * BS_ST + cb];
            uint32_t g0 = f2tf32(bReg[i].x), g1 = f2tf32(bReg[i].y);
            uint32_t g2 = f2tf32(bReg[i].z), g3 = f2tf32(bReg[i].w);
            eh[0] = g0; eh[1] = g1; eh[2] = g2; eh[3] = g3;
            el[0] = f2tf32(bReg[i].x - __uint_as_float(g0));
            el[1] = f2tf32(bReg[i].y - __uint_as_float(g1));
            el[2] = f2tf32(bReg[i].z - __uint_as_float(g2));
            el[3] = f2tf32(bReg[i].w - __uint_as_float(g3));
        }
        __syncthreads();

        if (k0 + 16 < K) {
#pragma unroll
            for (int i = 0; i < 2; i++) {
                int f = i * 256 + tid;
                aReg[i] = *(const float4*)(A + (size_t)(row0 + (f >> 2)) * K + k0 + 16 + ((f & 3) << 2));
                bReg[i] = *(const float4*)(B + (size_t)(k0 + 16 + (f >> 5)) * N + col0 + ((f & 31) << 2));
            }
        }

#pragma unroll
        for (int ks = 0; ks < 2; ks++) {
            int kb = ks * 8;
            uint32_t aH[2][4], aL[2][4];
#pragma unroll
            for (int mi = 0; mi < 2; mi++) {
                int r = wm * 32 + mi * 16 + lr;
                aH[mi][0] = AsH[r * AS_ST + kb + lc];
                aH[mi][1] = AsH[(r + 8) * AS_ST + kb + lc];
                aH[mi][2] = AsH[r * AS_ST + kb + lc + 4];
                aH[mi][3] = AsH[(r + 8) * AS_ST + kb + lc + 4];
                aL[mi][0] = AsL[r * AS_ST + kb + lc];
                aL[mi][1] = AsL[(r + 8) * AS_ST + kb + lc];
                aL[mi][2] = AsL[r * AS_ST + kb + lc + 4];
                aL[mi][3] = AsL[(r + 8) * AS_ST + kb + lc + 4];
            }
#pragma unroll
            for (int nj = 0; nj < 8; nj++) {
                int c = wn * 64 + nj * 8 + lr;
                uint32_t b0h = BsH[(kb + lc) * BS_ST + c];
                uint32_t b1h = BsH[(kb + lc + 4) * BS_ST + c];
                uint32_t b0l = BsL[(kb + lc) * BS_ST + c];
                uint32_t b1l = BsL[(kb + lc + 4) * BS_ST + c];
#pragma unroll
                for (int mi = 0; mi < 2; mi++) {
                    mma_tf32(acc[mi][nj], aH[mi], b0h, b1h);
                    mma_tf32(acc[mi][nj], aH[mi], b0l, b1l);
                    mma_tf32(acc[mi][nj], aL[mi], b0h, b1h);
                }
            }
        }
        __syncthreads();
    }

#pragma unroll
    for (int mi = 0; mi < 2; mi++) {
        int row = row0 + wm * 32 + mi * 16 + lr;
#pragma unroll
        for (int nj = 0; nj < 8; nj++) {
            int col = col0 + wn * 64 + nj * 8 + 2 * lc;
            float* cp0 = C + (size_t)row * N + col;
            cp0[0] = acc[mi][nj][0];
            cp0[1] = acc[mi][nj][1];
            float* cp1 = C + (size_t)(row + 8) * N + col;
            cp1[0] = acc[mi][nj][2];
            cp1[1] = acc[mi][nj][3];
        }
    }
}

// ---------------- concat wk|wv into fused weight buffer -------------------
__global__ void concat_wkv(const float* __restrict__ wk, const float* __restrict__ wv,
                           float* __restrict__ wkv) {
    int idx = blockIdx.x * 256 + threadIdx.x;  // DIM*256 float4s
    int r = idx >> 8;
    int c4 = idx & 255;
    float4 val = (c4 < 128) ? ((const float4*)wk)[r * 128 + c4]
                            : ((const float4*)wv)[r * 128 + (c4 - 128)];
    ((float4*)wkv)[r * 256 + c4] = val;
}

// ---------------- exact fp32 q rows 0..63: split-K --------------------------
__global__ __launch_bounds__(128) void qproj_part(const float* __restrict__ x,
                                                  const float* __restrict__ wq,
                                                  float* __restrict__ part) {
    __shared__ float xs[8][256];
    int tid = threadIdx.x;
    int col = blockIdx.x * 128 + tid;
    int r0 = blockIdx.y * 8;
    int k0 = blockIdx.z * 256;
    float acc[8];
#pragma unroll
    for (int rr = 0; rr < 8; rr++) acc[rr] = 0.f;

    for (int i = tid; i < 8 * 256; i += 128) {
        int rr = i >> 8, kk = i & 255;
        xs[rr][kk] = x[(size_t)(r0 + rr) * DIM + k0 + kk];
    }
    __syncthreads();
    for (int kk = 0; kk < 256; kk++) {
        float w = wq[(size_t)(k0 + kk) * DIM + col];
#pragma unroll
        for (int rr = 0; rr < 8; rr++) acc[rr] += xs[rr][kk] * w;
    }
#pragma unroll
    for (int rr = 0; rr < 8; rr++)
        part[(size_t)blockIdx.z * ESTQ * DIM + (size_t)(r0 + rr) * DIM + col] = acc[rr];
}

__global__ void qproj_red(const float* __restrict__ part, float* __restrict__ q64) {
    int idx = blockIdx.x * 256 + threadIdx.x;
    if (idx >= ESTQ * DIM) return;
    float s = 0.f;
#pragma unroll
    for (int ks = 0; ks < 8; ks++) s += part[(size_t)ks * ESTQ * DIM + idx];
    q64[idx] = s;
}

// ---------------- RoPE in place, row stride parameterized -----------------
__global__ void rope_kernel(float* t, const float* __restrict__ cosb,
                            const float* __restrict__ sinb, int H, int stride, int total) {
    int idx = blockIdx.x * blockDim.x + threadIdx.x;
    if (idx >= total) return;
    int d2 = idx & 31;
    int h = (idx >> 5) % H;
    int s = idx / (32 * H);
    float c = cosb[s * 32 + d2];
    float sn = sinb[s * 32 + d2];
    float* p = t + (size_t)s * stride + h * 64 + 2 * d2;
    float xr = p[0], xi = p[1];
    p[0] = xr * c - xi * sn;
    p[1] = xr * sn + xi * c;
}

// ---------------- est phase A: raw masked scores ---------------------------
__global__ __launch_bounds__(256) void est_score(const float* __restrict__ q64,
                                                 const float* __restrict__ kv,
                                                 float* __restrict__ probs) {
    __shared__ float qs[64][68];
    __shared__ float ksm[64][68];
    int tid = threadIdx.x;
    int h = blockIdx.y;
    int c0 = blockIdx.x * 64;
    int kvh = h >> 2;
    int qi = tid >> 2;
    int kg = tid & 3;

    for (int l = tid; l < 64 * 64; l += 256) {
        int r = l >> 6, d = l & 63;
        qs[r][d] = q64[(size_t)r * DIM + h * HD + d];
        ksm[r][d] = kv[(size_t)(c0 + r) * KVW + kvh * HD + d];
    }
    __syncthreads();

    float s16[16];
#pragma unroll
    for (int j = 0; j < 16; j++) s16[j] = 0.f;
#pragma unroll
    for (int d4 = 0; d4 < 16; d4++) {
        float4 q4 = *(float4*)&qs[qi][d4 * 4];
#pragma unroll
        for (int j = 0; j < 16; j++) {
            float4 k4 = *(float4*)&ksm[kg * 16 + j][d4 * 4];
            s16[j] += q4.x * k4.x + q4.y * k4.y + q4.z * k4.z + q4.w * k4.w;
        }
    }
    float* pr = probs + ((size_t)h * ESTQ + qi) * SEQ + c0 + kg * 16;
#pragma unroll
    for (int j = 0; j < 16; j++) {
        int kk = c0 + kg * 16 + j;
        float val = s16[j] * SCALE;
        if (kk >= SEQ - ESTQ && qi < kk - (SEQ - ESTQ)) val = -INFINITY;
        pr[j] = val;
    }
}

// ---------------- est phase B: row softmax in place ------------------------
__global__ __launch_bounds__(256) void est_norm(float* __restrict__ probs) {
    int qi = blockIdx.x;
    int h = blockIdx.y;
    __shared__ float sc[SEQ];
    __shared__ float red[8];
    int tid = threadIdx.x;
    float* pr = probs + ((size_t)h * ESTQ + qi) * SEQ;

    for (int l = tid; l < SEQ / 4; l += 256)
        *(float4*)&sc[l * 4] = *(const float4*)&pr[l * 4];
    __syncthreads();

    float m = -INFINITY;
    for (int kk = tid; kk < SEQ; kk += 256) m = fmaxf(m, sc[kk]);
#pragma unroll
    for (int o = 16; o; o >>= 1) m = fmaxf(m, __shfl_xor_sync(0xFFFFFFFFu, m, o));
    if ((tid & 31) == 0) red[tid >> 5] = m;
    __syncthreads();
    if (tid == 0) {
        float mm = red[0];
#pragma unroll
        for (int i = 1; i < 8; i++) mm = fmaxf(mm, red[i]);
        red[0] = mm;
    }
    __syncthreads();
    m = red[0];
    __syncthreads();

    float s = 0.f;
    for (int kk = tid; kk < SEQ; kk += 256) {
        float e = expf(sc[kk] - m);
        sc[kk] = e;
        s += e;
    }
#pragma unroll
    for (int o = 16; o; o >>= 1) s += __shfl_xor_sync(0xFFFFFFFFu, s, o);
    if ((tid & 31) == 0) red[tid >> 5] = s;
    __syncthreads();
    if (tid == 0) {
        float ss = 0.f;
#pragma unroll
        for (int i = 0; i < 8; i++) ss += red[i];
        red[0] = ss;
    }
    __syncthreads();
    float inv = 1.f / red[0];
    for (int kk = tid; kk < SEQ; kk += 256) pr[kk] = sc[kk] * inv;
}

// ---------------- vertical column sums -----------------------------------
__global__ void vertical_kernel(const float* __restrict__ probs, float* __restrict__ vert) {
    int idx = blockIdx.x * 256 + threadIdx.x;
    int h = idx >> 12;
    int kk = idx & (SEQ - 1);
    float s = 0.f;
    const float* base = probs + (size_t)h * ESTQ * SEQ + kk;
    for (int i = 0; i < ESTQ; i++) s += base[(size_t)i * SEQ];
    vert[idx] = s;
}

// ---------------- diagonal sums ------------------------------------------
__global__ void diag_kernel(const float* __restrict__ probs, float* __restrict__ dg) {
    int idx = blockIdx.x * 256 + threadIdx.x;
    int h = idx >> 12;
    int jp = idx & (SEQ - 1);
    float s = 0.f;
    const float* base = probs + (size_t)h * ESTQ * SEQ;
    for (int i = 0; i < ESTQ; i++) {
        int col = i + jp - 63;
        if (col >= 0 && col < SEQ) s += base[(size_t)i * SEQ + col];
    }
    dg[idx] = s;
}

// ---------------- per-head top-k via bitonic sort -------------------------
__global__ void topk_kernel(const float* __restrict__ vals, int kcount, int mode,
                            int* __restrict__ keys) {
    int h = blockIdx.x;
    __shared__ unsigned long long a[SEQ];
    int tid = threadIdx.x;  // 512
    for (int i = tid; i < SEQ; i += 512) {
        unsigned u = __float_as_uint(vals[h * SEQ + i]);
        u = (u & 0x80000000u) ? ~u : (u | 0x80000000u);
        a[i] = ((unsigned long long)(~u) << 32) | (unsigned)i;
    }
    __syncthreads();
    for (int k = 2; k <= SEQ; k <<= 1) {
        for (int j = k >> 1; j > 0; j >>= 1) {
            for (int i = tid; i < SEQ; i += 512) {
                int ixj = i ^ j;
                if (ixj > i) {
                    bool up = ((i & k) == 0);
                    unsigned long long x = a[i], y = a[ixj];
                    if (up ? (x > y) : (x < y)) { a[i] = y; a[ixj] = x; }
                }
            }
            __syncthreads();
        }
    }
    if (mode == 0) {
        for (int t = tid; t < kcount; t += 512)
            keys[h * NKEYP + t] = (int)(a[t] & 0xFFFFFFFFull);
    } else {
        for (int t = tid; t < kcount; t += 512)
            keys[h * NKEYP + VSZ + t] = (SEQ - 1) - (int)(a[t] & 0xFFFFFFFFull);
        for (int t = NKEY + tid; t < NKEYP; t += 512) keys[h * NKEYP + t] = PADKEY;
    }
}

// ---------------- sort keys ascending per head -----------------------------
__global__ __launch_bounds__(256) void sortkeys_kernel(int* __restrict__ keys) {
    int h = blockIdx.x;
    __shared__ int a[2048];
    int tid = threadIdx.x;
    for (int i = tid; i < 2048; i += 256)
        a[i] = (i < NKEYP) ? keys[h * NKEYP + i] : PADKEY;
    __syncthreads();
    for (int k = 2; k <= 2048; k <<= 1) {
        for (int j = k >> 1; j > 0; j >>= 1) {
            for (int i = tid; i < 2048; i += 256) {
                int ixj = i ^ j;
                if (ixj > i) {
                    bool up = ((i & k) == 0);
                    int x = a[i], y = a[ixj];
                    if (up ? (x > y) : (x < y)) { a[i] = y; a[ixj] = x; }
                }
            }
            __syncthreads();
        }
    }
    for (int i = tid; i < NKEYP; i += 256) keys[h * NKEYP + i] = a[i];
}

// ---------------- gather sparse K/V rows (from fused kv) -------------------
__global__ void gather_kernel(const float* __restrict__ kv,
                              const int* __restrict__ keys,
                              float* __restrict__ ksp, float* __restrict__ vsp) {
    int j = blockIdx.x;
    int h = j / NKEYP;
    int d = threadIdx.x;
    int key = keys[j];
    int kvh = h >> 2;
    float kvv = 0.f, vvv = 0.f;
    if (key < SEQ) {
        kvv = kv[(size_t)key * KVW + kvh * HD + d];
        vvv = kv[(size_t)key * KVW + 512 + kvh * HD + d];
    }
    ksp[(size_t)j * HD + d] = kvv;
    vsp[(size_t)j * HD + d] = vvv;
}

// ---------------- sparse attention v3: TC QK (3xTF32) + SIMT PV ----------
#define QHL_ST 132
#define SP_WORDS (64 * 132 + 32 * 132 + 32 * 68 + 64 * 36 + 32)

__global__ __launch_bounds__(256) void spattn_kernel(const float* __restrict__ q,
                                                     const float* __restrict__ ksp,
                                                     const float* __restrict__ vsp,
                                                     const int* __restrict__ keys,
                                                     float* __restrict__ attout) {
    extern __shared__ uint32_t smem[];
    uint32_t* qhl = smem;
    uint32_t* khl = qhl + 64 * 132;
    float* vs = (float*)(khl + 32 * 132);
    float* ss = vs + 32 * 68;
    int* kid = (int*)(ss + 64 * 36);

    int qb = blockIdx.x;
    int h = blockIdx.y;
    int tid = threadIdx.x;
    int lane = tid & 31;
    int warp = tid >> 5;
    int lr = lane >> 2;
    int lc = lane & 3;
    int wm = warp & 3;
    int wn = warp >> 2;
    int qp = tid >> 3;
    int g = tid & 7;
    int qi0 = qp, qi1 = qp + 32;
    int sglob0 = qb * 64 + qi0;
    int sglob1 = qb * 64 + qi1;
    int qbmax = qb * 64 + 63;

    for (int l = tid; l < 64 * 16; l += 256) {
        int r = l >> 4, c4 = (l & 15) * 4;
        float4 v = *(const float4*)&q[(size_t)(qb * 64 + r) * DIM + h * HD + c4];
        uint32_t* dh = &qhl[r * QHL_ST + c4];
        uint32_t h0 = f2tf32(v.x), h1 = f2tf32(v.y), h2 = f2tf32(v.z), h3 = f2tf32(v.w);
        dh[0] = h0; dh[1] = h1; dh[2] = h2; dh[3] = h3;
        dh[64] = f2tf32(v.x - __uint_as_float(h0));
        dh[65] = f2tf32(v.y - __uint_as_float(h1));
        dh[66] = f2tf32(v.z - __uint_as_float(h2));
        dh[67] = f2tf32(v.w - __uint_as_float(h3));
    }

    float m0 = -INFINITY, m1 = -INFINITY, lsum0 = 0.f, lsum1 = 0.f;
    float out0[8], out1[8];
#pragma unroll
    for (int i = 0; i < 8; i++) { out0[i] = 0.f; out1[i] = 0.f; }

    for (int t = 0; t < NKEYP / 32; t++) {
        __syncthreads();
        if (tid < 32) kid[tid] = keys[h * NKEYP + t * 32 + tid];
        __syncthreads();
        if (kid[0] > qbmax) continue;

        for (int l = tid; l < 32 * 16; l += 256) {
            int r = l >> 4, c4 = (l & 15) * 4;
            float4 kv = *(const float4*)&ksp[((size_t)h * NKEYP + t * 32 + r) * HD + c4];
            uint32_t* dh = &khl[r * QHL_ST + c4];
            uint32_t h0 = f2tf32(kv.x), h1 = f2tf32(kv.y), h2 = f2tf32(kv.z), h3 = f2tf32(kv.w);
            dh[0] = h0; dh[1] = h1; dh[2] = h2; dh[3] = h3;
            dh[64] = f2tf32(kv.x - __uint_as_float(h0));
            dh[65] = f2tf32(kv.y - __uint_as_float(h1));
            dh[66] = f2tf32(kv.z - __uint_as_float(h2));
            dh[67] = f2tf32(kv.w - __uint_as_float(h3));
            *(float4*)&vs[r * 68 + c4] =
                *(const float4*)&vsp[((size_t)h * NKEYP + t * 32 + r) * HD + c4];
        }
        __syncthreads();

        {
            float acc[2][4];
#pragma unroll
            for (int nt = 0; nt < 2; nt++)
#pragma unroll
                for (int e = 0; e < 4; e++) acc[nt][e] = 0.f;
#pragma unroll
            for (int ksI = 0; ksI < 8; ksI++) {
                int kb = ksI * 8;
                int ra = wm * 16 + lr;
                uint32_t aH[4], aL[4];
                aH[0] = qhl[ra * QHL_ST + kb + lc];
                aH[1] = qhl[(ra + 8) * QHL_ST + kb + lc];
                aH[2] = qhl[ra * QHL_ST + kb + lc + 4];
                aH[3] = qhl[(ra + 8) * QHL_ST + kb + lc + 4];
                aL[0] = qhl[ra * QHL_ST + 64 + kb + lc];
                aL[1] = qhl[(ra + 8) * QHL_ST + 64 + kb + lc];
                aL[2] = qhl[ra * QHL_ST + 64 + kb + lc + 4];
                aL[3] = qhl[(ra + 8) * QHL_ST + 64 + kb + lc + 4];
#pragma unroll
                for (int nt = 0; nt < 2; nt++) {
                    int n0 = wn * 16 + nt * 8;
                    uint32_t b0h = khl[(n0 + lr) * QHL_ST + kb + lc];
                    uint32_t b1h = khl[(n0 + lr) * QHL_ST + kb + lc + 4];
                    uint32_t b0l = khl[(n0 + lr) * QHL_ST + 64 + kb + lc];
                    uint32_t b1l = khl[(n0 + lr) * QHL_ST + 64 + kb + lc + 4];
                    mma_tf32(acc[nt], aH, b0h, b1h);
                    mma_tf32(acc[nt], aH, b0l, b1l);
                    mma_tf32(acc[nt], aL, b0h, b1h);
                }
            }
#pragma unroll
            for (int nt = 0; nt < 2; nt++) {
                int row = wm * 16 + lr;
                int col = wn * 16 + nt * 8 + 2 * lc;
                ss[row * 36 + col] = acc[nt][0];
                ss[row * 36 + col + 1] = acc[nt][1];
                ss[(row + 8) * 36 + col] = acc[nt][2];
                ss[(row + 8) * 36 + col + 1] = acc[nt][3];
            }
        }
        __syncthreads();

#pragma unroll
        for (int j = 0; j < 4; j++) {
            int jj = g * 4 + j;
            int key = kid[jj];
            float r0 = ss[qi0 * 36 + jj];
            float r1 = ss[qi1 * 36 + jj];
            float v0, v1;
            if (key >= SEQ) { v0 = -INFINITY; v1 = -INFINITY; }
            else {
                v0 = (key <= sglob0) ? r0 * SCALE : -1e30f;
                v1 = (key <= sglob1) ? r1 * SCALE : -1e30f;
            }
            ss[qi0 * 36 + jj] = v0;
            ss[qi1 * 36 + jj] = v1;
        }
        __syncthreads();

        float tm0 = m0, tm1 = m1;
#pragma unroll
        for (int j = 0; j < 32; j++) {
            tm0 = fmaxf(tm0, ss[qi0 * 36 + j]);
            tm1 = fmaxf(tm1, ss[qi1 * 36 + j]);
        }
        float c0 = expf(m0 - tm0);
        float c1 = expf(m1 - tm1);
        m0 = tm0; m1 = tm1;
        lsum0 *= c0; lsum1 *= c1;
#pragma unroll
        for (int i = 0; i < 8; i++) { out0[i] *= c0; out1[i] *= c1; }
        __syncthreads();

#pragma unroll
        for (int j = 0; j < 4; j++) {
            int jj = g * 4 + j;
            ss[qi0 * 36 + jj] = expf(ss[qi0 * 36 + jj] - m0);
            ss[qi1 * 36 + jj] = expf(ss[qi1 * 36 + jj] - m1);
        }
        __syncthreads();

        float ps0 = 0.f, ps1 = 0.f;
#pragma unroll
        for (int j = 0; j < 32; j++) {
            float p0 = ss[qi0 * 36 + j];
            float p1 = ss[qi1 * 36 + j];
            ps0 += p0; ps1 += p1;
            float4 va = *(float4*)&vs[j * 68 + g * 8];
            float4 vb = *(float4*)&vs[j * 68 + g * 8 + 4];
            out0[0] += p0 * va.x; out0[1] += p0 * va.y; out0[2] += p0 * va.z; out0[3] += p0 * va.w;
            out0[4] += p0 * vb.x; out0[5] += p0 * vb.y; out0[6] += p0 * vb.z; out0[7] += p0 * vb.w;
            out1[0] += p1 * va.x; out1[1] += p1 * va.y; out1[2] += p1 * va.z; out1[3] += p1 * va.w;
            out1[4] += p1 * vb.x; out1[5] += p1 * vb.y; out1[6] += p1 * vb.z; out1[7] += p1 * vb.w;
        }
        lsum0 += ps0;
        lsum1 += ps1;
    }

    if (m0 < -5e29f) {
        lsum0 = (float)NKEY;
#pragma unroll
        for (int i = 0; i < 8; i++) out0[i] = 0.f;
        for (int j = 0; j < NKEYP; j++) {
            if (keys[h * NKEYP + j] < SEQ) {
                const float* vr = &vsp[((size_t)h * NKEYP + j) * HD + g * 8];
#pragma unroll
                for (int i = 0; i < 8; i++) out0[i] += vr[i];
            }
        }
    }
    if (m1 < -5e29f) {
        lsum1 = (float)NKEY;
#pragma unroll
        for (int i = 0; i < 8; i++) out1[i] = 0.f;
        for (int j = 0; j < NKEYP; j++) {
            if (keys[h * NKEYP + j] < SEQ) {
                const float* vr = &vsp[((size_t)h * NKEYP + j) * HD + g * 8];
#pragma unroll
                for (int i = 0; i < 8; i++) out1[i] += vr[i];
            }
        }
    }

    float inv0 = 1.f / lsum0;
    float inv1 = 1.f / lsum1;
#pragma unroll
    for (int i = 0; i < 8; i++) {
        attout[(size_t)sglob0 * DIM + h * HD + g * 8 + i] = out0[i] * inv0;
        attout[(size_t)sglob1 * DIM + h * HD + g * 8 + i] = out1[i] * inv1;
    }
}

// --------------------------------- launch --------------------------------
extern "C" void kernel_launch(void* const* d_in, const int* in_sizes, int n_in,
                              void* d_out, int out_size) {
    const float* x    = (const float*)d_in[0];
    const float* fcos = (const float*)d_in[1];
    const float* fsin = (const float*)d_in[2];
    const float* wq   = (const float*)d_in[3];
    const float* wk   = (const float*)d_in[4];
    const float* wv   = (const float*)d_in[5];
    const float* wo   = (const float*)d_in[6];
    float* out = (float*)d_out;

    float *q, *q64, *q64p, *wkv, *kv, *probs, *vert, *dgp, *ksp, *vsp, *att;
    int* keys;
    cudaGetSymbolAddress((void**)&q, g_q);
    cudaGetSymbolAddress((void**)&q64, g_q64);
    cudaGetSymbolAddress((void**)&q64p, g_q64p);
    cudaGetSymbolAddress((void**)&wkv, g_wkv);
    cudaGetSymbolAddress((void**)&kv, g_kv);
    cudaGetSymbolAddress((void**)&probs, g_probs);
    cudaGetSymbolAddress((void**)&vert, g_vert);
    cudaGetSymbolAddress((void**)&dgp, g_diag);
    cudaGetSymbolAddress((void**)&keys, g_keys);
    cudaGetSymbolAddress((void**)&ksp, g_ksp);
    cudaGetSymbolAddress((void**)&vsp, g_vsp);
    cudaGetSymbolAddress((void**)&att, g_att);

    // fuse wk|wv, then projections: q 1x tf32, kv fused 3xTF32
    concat_wkv<<<DIM, 256>>>(wk, wv, wkv);
    gemm_tf32_1x<<<dim3(DIM / 128, SEQ / 128), 256>>>(x, wq, q, SEQ, DIM, DIM);
    gemm_tf32x3<<<dim3(KVW / 128, SEQ / 128), 256>>>(x, wkv, kv, SEQ, KVW, DIM);

    // exact fp32 q rows 0..63 via split-K
    qproj_part<<<dim3(16, 8, 8), 128>>>(x, wq, q64p);
    qproj_red<<<(ESTQ * DIM + 255) / 256, 256>>>(q64p, q64);

    // RoPE (q: stride DIM; k inside fused kv: stride KVW; v not roped)
    {
        int tq = SEQ * NH * 32;
        rope_kernel<<<(tq + 255) / 256, 256>>>(q, fcos, fsin, NH, DIM, tq);
        int tk = SEQ * NKV * 32;
        rope_kernel<<<(tk + 255) / 256, 256>>>(kv, fcos, fsin, NKV, KVW, tk);
        int tq64 = ESTQ * NH * 32;
        rope_kernel<<<(tq64 + 255) / 256, 256>>>(q64, fcos, fsin, NH, DIM, tq64);
    }

    // estimation: scores then row softmax
    est_score<<<dim3(SEQ / 64, NH), 256>>>(q64, kv, probs);
    est_norm<<<dim3(ESTQ, NH), 256>>>(probs);

    // vertical / diagonal scores
    vertical_kernel<<<(NH * SEQ) / 256, 256>>>(probs, vert);
    diag_kernel<<<(NH * SEQ) / 256, 256>>>(probs, dgp);

    // top-k selections
    topk_kernel<<<NH, 512>>>(vert, VSZ, 0, keys);
    topk_kernel<<<NH, 512>>>(dgp, SSZ, 1, keys);

    // sort keys ascending (order-invariant; enables tile skipping)
    sortkeys_kernel<<<NH, 256>>>(keys);

    // gather sparse K/V from fused kv
    gather_kernel<<<NH * NKEYP, 64>>>(kv, keys, ksp, vsp);

    // sparse attention: TC QK (3xTF32) + SIMT PV, tile skip
    {
        size_t spbytes = (size_t)SP_WORDS * 4;
        cudaFuncSetAttribute(spattn_kernel,
                             cudaFuncAttributeMaxDynamicSharedMemorySize, (int)spbytes);
        spattn_kernel<<<dim3(SEQ / 64, NH), 256, spbytes>>>(q, ksp, vsp, keys, att);
    }

    // output projection (1x tf32)
    gemm_tf32_1x<<<dim3(DIM / 128, SEQ / 128), 256>>>(att, wo, out, SEQ, DIM, DIM);
}

// round 9
// speedup vs baseline: 2.8825x; 1.1356x over previous
#include <cuda_runtime.h>
#include <cuda_fp16.h>
#include <math.h>
#include <stdint.h>

#define SEQ   4096
#define DIM   2048
#define NH    32
#define NKV   8
#define HD    64
#define ESTQ  64
#define VSZ   300
#define SSZ   800
#define NKEY  1100
#define NKEYP 1152
#define SCALE 0.125f
#define PADKEY 0x3FFFFFFF
#define KVW   1024

// ---------------- device scratch ----------------
__device__ float g_q[SEQ * DIM];
__device__ float g_q64[ESTQ * DIM];
__device__ float g_q64p[8 * ESTQ * DIM];
__device__ float g_wkv[DIM * KVW];
__device__ float g_kv[SEQ * KVW];
__device__ float g_probs[NH * ESTQ * SEQ];
__device__ float g_vert[NH * SEQ];
__device__ float g_diag[NH * SEQ];
__device__ int   g_keys[NH * NKEYP];
__device__ float g_ksp[NH * NKEYP * HD];
__device__ float g_vsp[NH * NKEYP * HD];
__device__ float g_att[SEQ * DIM];
__device__ __half g_wqt[DIM * DIM];   // wq transposed [n][k] fp16
__device__ __half g_wot[DIM * DIM];   // wo transposed [n][k] fp16

// ---------------- helpers ------------------------------------------------
__device__ __forceinline__ uint32_t f2tf32(float f) {
    uint32_t r;
    asm("cvt.rna.tf32.f32 %0, %1;" : "=r"(r) : "f"(f));
    return r;
}

__device__ __forceinline__ void mma_tf32(float c[4], const uint32_t a[4],
                                         uint32_t b0, uint32_t b1) {
    asm volatile(
        "mma.sync.aligned.m16n8k8.row.col.f32.tf32.tf32.f32 "
        "{%0,%1,%2,%3}, {%4,%5,%6,%7}, {%8,%9}, {%0,%1,%2,%3};\n"
        : "+f"(c[0]), "+f"(c[1]), "+f"(c[2]), "+f"(c[3])
        : "r"(a[0]), "r"(a[1]), "r"(a[2]), "r"(a[3]), "r"(b0), "r"(b1));
}

__device__ __forceinline__ void mma_f16(float c[4], const uint32_t a[4],
                                        uint32_t b0, uint32_t b1) {
    asm volatile(
        "mma.sync.aligned.m16n8k16.row.col.f32.f16.f16.f32 "
        "{%0,%1,%2,%3}, {%4,%5,%6,%7}, {%8,%9}, {%0,%1,%2,%3};\n"
        : "+f"(c[0]), "+f"(c[1]), "+f"(c[2]), "+f"(c[3])
        : "r"(a[0]), "r"(a[1]), "r"(a[2]), "r"(a[3]), "r"(b0), "r"(b1));
}

// ================= fp16 k16 GEMM: C[M,N] = A[M,K] @ Bt[N,K]^T ==============
// A fp32 row-major; Bt fp16 [n][k]; 128x128 tile, BK=32, 256 thr, 8 warps 4x2.
#define AF_ST 20
#define BF_ST 20

__global__ __launch_bounds__(256) void gemm_f16(const float* __restrict__ A,
                                                const __half* __restrict__ Bt,
                                                float* __restrict__ C,
                                                int M, int N, int K) {
    __shared__ uint32_t As[128 * AF_ST];  // halves packed: word w = k 2w,2w+1
    __shared__ uint32_t Bs[128 * BF_ST];  // per n-row of tile
    int tid = threadIdx.x;
    int lane = tid & 31;
    int warp = tid >> 5;
    int wm = warp & 3;
    int wn = warp >> 2;
    int row0 = blockIdx.y * 128;
    int col0 = blockIdx.x * 128;
    int lr = lane >> 2;
    int lc = lane & 3;

    float acc[2][8][4];
#pragma unroll
    for (int mi = 0; mi < 2; mi++)
#pragma unroll
        for (int nj = 0; nj < 8; nj++)
#pragma unroll
            for (int e = 0; e < 4; e++) acc[mi][nj][e] = 0.f;

    for (int k0 = 0; k0 < K; k0 += 32) {
        // A: 128x32 fp32 -> fp16 smem
#pragma unroll
        for (int i = 0; i < 4; i++) {
            int s = i * 256 + tid;
            int r = s >> 3;
            int c4 = s & 7;
            float4 v = *(const float4*)(A + (size_t)(row0 + r) * K + k0 + c4 * 4);
            __half2 h0 = __floats2half2_rn(v.x, v.y);
            __half2 h1 = __floats2half2_rn(v.z, v.w);
            As[r * AF_ST + c4 * 2] = *(uint32_t*)&h0;
            As[r * AF_ST + c4 * 2 + 1] = *(uint32_t*)&h1;
        }
        // B: 128 n-rows x 32 halves, direct copy
#pragma unroll
        for (int i = 0; i < 2; i++) {
            int s = i * 256 + tid;
            int nr = s >> 2;
            int j = s & 3;
            uint4 bv = *((const uint4*)(Bt + (size_t)(col0 + nr) * K + k0) + j);
            *(uint4*)&Bs[nr * BF_ST + j * 4] = bv;
        }
        __syncthreads();

#pragma unroll
        for (int ks = 0; ks < 2; ks++) {
            int kb = ks * 8;
            uint32_t a[2][4];
#pragma unroll
            for (int mi = 0; mi < 2; mi++) {
                int ra = wm * 32 + mi * 16 + lr;
                a[mi][0] = As[ra * AF_ST + kb + lc];
                a[mi][1] = As[(ra + 8) * AF_ST + kb + lc];
                a[mi][2] = As[ra * AF_ST + kb + lc + 4];
                a[mi][3] = As[(ra + 8) * AF_ST + kb + lc + 4];
            }
#pragma unroll
            for (int nj = 0; nj < 8; nj++) {
                int col = wn * 64 + nj * 8 + lr;
                uint32_t b0 = Bs[col * BF_ST + kb + lc];
                uint32_t b1 = Bs[col * BF_ST + kb + lc + 4];
                mma_f16(acc[0][nj], a[0], b0, b1);
                mma_f16(acc[1][nj], a[1], b0, b1);
            }
        }
        __syncthreads();
    }

#pragma unroll
    for (int mi = 0; mi < 2; mi++) {
        int row = row0 + wm * 32 + mi * 16 + lr;
#pragma unroll
        for (int nj = 0; nj < 8; nj++) {
            int col = col0 + wn * 64 + nj * 8 + 2 * lc;
            float* cp0 = C + (size_t)row * N + col;
            cp0[0] = acc[mi][nj][0];
            cp0[1] = acc[mi][nj][1];
            float* cp1 = C + (size_t)(row + 8) * N + col;
            cp1[0] = acc[mi][nj][2];
            cp1[1] = acc[mi][nj][3];
        }
    }
}

// ---------------- transpose fp32 [k][n] -> fp16 [n][k] ----------------------
__global__ void transp_half(const float* __restrict__ w, __half* __restrict__ t) {
    __shared__ float tile[32][33];
    int bx = blockIdx.x * 32;  // n
    int by = blockIdx.y * 32;  // k
    int tx = threadIdx.x, ty = threadIdx.y;  // (32,8)
    for (int i = 0; i < 32; i += 8)
        tile[ty + i][tx] = w[(size_t)(by + ty + i) * DIM + bx + tx];
    __syncthreads();
    for (int i = 0; i < 32; i += 8)
        t[(size_t)(bx + ty + i) * DIM + by + tx] = __float2half_rn(tile[tx][ty + i]);
}

// ================= 3xTF32 GEMM (BK=16) — kv projection ====================
#define AS_ST 20
#define BS_ST 132

__global__ __launch_bounds__(256) void gemm_tf32x3(const float* __restrict__ A,
                                                   const float* __restrict__ B,
                                                   float* __restrict__ C,
                                                   int M, int N, int K) {
    __shared__ uint32_t AsH[128 * AS_ST];
    __shared__ uint32_t AsL[128 * AS_ST];
    __shared__ uint32_t BsH[16 * BS_ST];
    __shared__ uint32_t BsL[16 * BS_ST];
    int tid = threadIdx.x;
    int lane = tid & 31;
    int warp = tid >> 5;
    int wm = warp & 3;
    int wn = warp >> 2;
    int row0 = blockIdx.y * 128;
    int col0 = blockIdx.x * 128;

    float acc[2][8][4];
#pragma unroll
    for (int mi = 0; mi < 2; mi++)
#pragma unroll
        for (int nj = 0; nj < 8; nj++)
#pragma unroll
            for (int e = 0; e < 4; e++) acc[mi][nj][e] = 0.f;

    int lr = lane >> 2;
    int lc = lane & 3;

    for (int k0 = 0; k0 < K; k0 += 16) {
#pragma unroll
        for (int i = 0; i < 2; i++) {
            int f = i * 256 + tid;
            int ra = f >> 2, ca = (f & 3) << 2;
            float4 v = *(const float4*)(A + (size_t)(row0 + ra) * K + k0 + ca);
            uint32_t* dh = &AsH[ra * AS_ST + ca];
            uint32_t* dl = &AsL[ra * AS_ST + ca];
            uint32_t h0 = f2tf32(v.x), h1 = f2tf32(v.y), h2 = f2tf32(v.z), h3 = f2tf32(v.w);
            dh[0] = h0; dh[1] = h1; dh[2] = h2; dh[3] = h3;
            dl[0] = f2tf32(v.x - __uint_as_float(h0));
            dl[1] = f2tf32(v.y - __uint_as_float(h1));
            dl[2] = f2tf32(v.z - __uint_as_float(h2));
            dl[3] = f2tf32(v.w - __uint_as_float(h3));
            int rb = f >> 5, cb = (f & 31) << 2;
            float4 bv = *(const float4*)(B + (size_t)(k0 + rb) * N + col0 + cb);
            uint32_t* eh = &BsH[rb * BS_ST + cb];
            uint32_t* el = &BsL[rb * BS_ST + cb];
            uint32_t g0 = f2tf32(bv.x), g1 = f2tf32(bv.y), g2 = f2tf32(bv.z), g3 = f2tf32(bv.w);
            eh[0] = g0; eh[1] = g1; eh[2] = g2; eh[3] = g3;
            el[0] = f2tf32(bv.x - __uint_as_float(g0));
            el[1] = f2tf32(bv.y - __uint_as_float(g1));
            el[2] = f2tf32(bv.z - __uint_as_float(g2));
            el[3] = f2tf32(bv.w - __uint_as_float(g3));
        }
        __syncthreads();

#pragma unroll
        for (int ks = 0; ks < 2; ks++) {
            int kb = ks * 8;
            uint32_t aH[2][4], aL[2][4];
#pragma unroll
            for (int mi = 0; mi < 2; mi++) {
                int r = wm * 32 + mi * 16 + lr;
                aH[mi][0] = AsH[r * AS_ST + kb + lc];
                aH[mi][1] = AsH[(r + 8) * AS_ST + kb + lc];
                aH[mi][2] = AsH[r * AS_ST + kb + lc + 4];
                aH[mi][3] = AsH[(r + 8) * AS_ST + kb + lc + 4];
                aL[mi][0] = AsL[r * AS_ST + kb + lc];
                aL[mi][1] = AsL[(r + 8) * AS_ST + kb + lc];
                aL[mi][2] = AsL[r * AS_ST + kb + lc + 4];
                aL[mi][3] = AsL[(r + 8) * AS_ST + kb + lc + 4];
            }
#pragma unroll
            for (int nj = 0; nj < 8; nj++) {
                int c = wn * 64 + nj * 8 + lr;
                uint32_t b0h = BsH[(kb + lc) * BS_ST + c];
                uint32_t b1h = BsH[(kb + lc + 4) * BS_ST + c];
                uint32_t b0l = BsL[(kb + lc) * BS_ST + c];
                uint32_t b1l = BsL[(kb + lc + 4) * BS_ST + c];
#pragma unroll
                for (int mi = 0; mi < 2; mi++) {
                    mma_tf32(acc[mi][nj], aH[mi], b0h, b1h);
                    mma_tf32(acc[mi][nj], aH[mi], b0l, b1l);
                    mma_tf32(acc[mi][nj], aL[mi], b0h, b1h);
                }
            }
        }
        __syncthreads();
    }

#pragma unroll
    for (int mi = 0; mi < 2; mi++) {
        int row = row0 + wm * 32 + mi * 16 + lr;
#pragma unroll
        for (int nj = 0; nj < 8; nj++) {
            int col = col0 + wn * 64 + nj * 8 + 2 * lc;
            float* cp0 = C + (size_t)row * N + col;
            cp0[0] = acc[mi][nj][0];
            cp0[1] = acc[mi][nj][1];
            float* cp1 = C + (size_t)(row + 8) * N + col;
            cp1[0] = acc[mi][nj][2];
            cp1[1] = acc[mi][nj][3];
        }
    }
}

// ---------------- concat wk|wv ---------------------------------------------
__global__ void concat_wkv(const float* __restrict__ wk, const float* __restrict__ wv,
                           float* __restrict__ wkv) {
    int idx = blockIdx.x * 256 + threadIdx.x;
    int r = idx >> 8;
    int c4 = idx & 255;
    float4 val = (c4 < 128) ? ((const float4*)wk)[r * 128 + c4]
                            : ((const float4*)wv)[r * 128 + (c4 - 128)];
    ((float4*)wkv)[r * 256 + c4] = val;
}

// ---------------- exact fp32 q rows 0..63: split-K ---------------------------
__global__ __launch_bounds__(128) void qproj_part(const float* __restrict__ x,
                                                  const float* __restrict__ wq,
                                                  float* __restrict__ part) {
    __shared__ float xs[8][256];
    int tid = threadIdx.x;
    int col = blockIdx.x * 128 + tid;
    int r0 = blockIdx.y * 8;
    int k0 = blockIdx.z * 256;
    float acc[8];
#pragma unroll
    for (int rr = 0; rr < 8; rr++) acc[rr] = 0.f;

    for (int i = tid; i < 8 * 256; i += 128) {
        int rr = i >> 8, kk = i & 255;
        xs[rr][kk] = x[(size_t)(r0 + rr) * DIM + k0 + kk];
    }
    __syncthreads();
    for (int kk = 0; kk < 256; kk++) {
        float w = wq[(size_t)(k0 + kk) * DIM + col];
#pragma unroll
        for (int rr = 0; rr < 8; rr++) acc[rr] += xs[rr][kk] * w;
    }
#pragma unroll
    for (int rr = 0; rr < 8; rr++)
        part[(size_t)blockIdx.z * ESTQ * DIM + (size_t)(r0 + rr) * DIM + col] = acc[rr];
}

__global__ void qproj_red(const float* __restrict__ part, float* __restrict__ q64) {
    int idx = blockIdx.x * 256 + threadIdx.x;
    if (idx >= ESTQ * DIM) return;
    float s = 0.f;
#pragma unroll
    for (int ks = 0; ks < 8; ks++) s += part[(size_t)ks * ESTQ * DIM + idx];
    q64[idx] = s;
}

// ---------------- RoPE -------------------------------------------------------
__global__ void rope_kernel(float* t, const float* __restrict__ cosb,
                            const float* __restrict__ sinb, int H, int stride, int total) {
    int idx = blockIdx.x * blockDim.x + threadIdx.x;
    if (idx >= total) return;
    int d2 = idx & 31;
    int h = (idx >> 5) % H;
    int s = idx / (32 * H);
    float c = cosb[s * 32 + d2];
    float sn = sinb[s * 32 + d2];
    float* p = t + (size_t)s * stride + h * 64 + 2 * d2;
    float xr = p[0], xi = p[1];
    p[0] = xr * c - xi * sn;
    p[1] = xr * sn + xi * c;
}

// ---------------- est phase A -----------------------------------------------
__global__ __launch_bounds__(256) void est_score(const float* __restrict__ q64,
                                                 const float* __restrict__ kv,
                                                 float* __restrict__ probs) {
    __shared__ float qs[64][68];
    __shared__ float ksm[64][68];
    int tid = threadIdx.x;
    int h = blockIdx.y;
    int c0 = blockIdx.x * 64;
    int kvh = h >> 2;
    int qi = tid >> 2;
    int kg = tid & 3;

    for (int l = tid; l < 64 * 64; l += 256) {
        int r = l >> 6, d = l & 63;
        qs[r][d] = q64[(size_t)r * DIM + h * HD + d];
        ksm[r][d] = kv[(size_t)(c0 + r) * KVW + kvh * HD + d];
    }
    __syncthreads();

    float s16[16];
#pragma unroll
    for (int j = 0; j < 16; j++) s16[j] = 0.f;
#pragma unroll
    for (int d4 = 0; d4 < 16; d4++) {
        float4 q4 = *(float4*)&qs[qi][d4 * 4];
#pragma unroll
        for (int j = 0; j < 16; j++) {
            float4 k4 = *(float4*)&ksm[kg * 16 + j][d4 * 4];
            s16[j] += q4.x * k4.x + q4.y * k4.y + q4.z * k4.z + q4.w * k4.w;
        }
    }
    float* pr = probs + ((size_t)h * ESTQ + qi) * SEQ + c0 + kg * 16;
#pragma unroll
    for (int j = 0; j < 16; j++) {
        int kk = c0 + kg * 16 + j;
        float val = s16[j] * SCALE;
        if (kk >= SEQ - ESTQ && qi < kk - (SEQ - ESTQ)) val = -INFINITY;
        pr[j] = val;
    }
}

// ---------------- est phase B -------------------------------------------------
__global__ __launch_bounds__(256) void est_norm(float* __restrict__ probs) {
    int qi = blockIdx.x;
    int h = blockIdx.y;
    __shared__ float sc[SEQ];
    __shared__ float red[8];
    int tid = threadIdx.x;
    float* pr = probs + ((size_t)h * ESTQ + qi) * SEQ;

    for (int l = tid; l < SEQ / 4; l += 256)
        *(float4*)&sc[l * 4] = *(const float4*)&pr[l * 4];
    __syncthreads();

    float m = -INFINITY;
    for (int kk = tid; kk < SEQ; kk += 256) m = fmaxf(m, sc[kk]);
#pragma unroll
    for (int o = 16; o; o >>= 1) m = fmaxf(m, __shfl_xor_sync(0xFFFFFFFFu, m, o));
    if ((tid & 31) == 0) red[tid >> 5] = m;
    __syncthreads();
    if (tid == 0) {
        float mm = red[0];
#pragma unroll
        for (int i = 1; i < 8; i++) mm = fmaxf(mm, red[i]);
        red[0] = mm;
    }
    __syncthreads();
    m = red[0];
    __syncthreads();

    float s = 0.f;
    for (int kk = tid; kk < SEQ; kk += 256) {
        float e = expf(sc[kk] - m);
        sc[kk] = e;
        s += e;
    }
#pragma unroll
    for (int o = 16; o; o >>= 1) s += __shfl_xor_sync(0xFFFFFFFFu, s, o);
    if ((tid & 31) == 0) red[tid >> 5] = s;
    __syncthreads();
    if (tid == 0) {
        float ss = 0.f;
#pragma unroll
        for (int i = 0; i < 8; i++) ss += red[i];
        red[0] = ss;
    }
    __syncthreads();
    float inv = 1.f / red[0];
    for (int kk = tid; kk < SEQ; kk += 256) pr[kk] = sc[kk] * inv;
}

// ---------------- vertical / diagonal ------------------------------------------
__global__ void vertical_kernel(const float* __restrict__ probs, float* __restrict__ vert) {
    int idx = blockIdx.x * 256 + threadIdx.x;
    int h = idx >> 12;
    int kk = idx & (SEQ - 1);
    float s = 0.f;
    const float* base = probs + (size_t)h * ESTQ * SEQ + kk;
    for (int i = 0; i < ESTQ; i++) s += base[(size_t)i * SEQ];
    vert[idx] = s;
}

__global__ void diag_kernel(const float* __restrict__ probs, float* __restrict__ dg) {
    int idx = blockIdx.x * 256 + threadIdx.x;
    int h = idx >> 12;
    int jp = idx & (SEQ - 1);
    float s = 0.f;
    const float* base = probs + (size_t)h * ESTQ * SEQ;
    for (int i = 0; i < ESTQ; i++) {
        int col = i + jp - 63;
        if (col >= 0 && col < SEQ) s += base[(size_t)i * SEQ + col];
    }
    dg[idx] = s;
}

// ---------------- merged top-k: grid 64 = 32 heads x 2 modes -------------------
__global__ void topk2_kernel(const float* __restrict__ vert, const float* __restrict__ dg,
                             int* __restrict__ keys) {
    int b = blockIdx.x;
    int mode = b >> 5;
    int h = b & 31;
    const float* vals = mode ? dg : vert;
    int kcount = mode ? SSZ : VSZ;
    __shared__ unsigned long long a[SEQ];
    int tid = threadIdx.x;  // 512
    for (int i = tid; i < SEQ; i += 512) {
        unsigned u = __float_as_uint(vals[h * SEQ + i]);
        u = (u & 0x80000000u) ? ~u : (u | 0x80000000u);
        a[i] = ((unsigned long long)(~u) << 32) | (unsigned)i;
    }
    __syncthreads();
    for (int k = 2; k <= SEQ; k <<= 1) {
        for (int j = k >> 1; j > 0; j >>= 1) {
            for (int i = tid; i < SEQ; i += 512) {
                int ixj = i ^ j;
                if (ixj > i) {
                    bool up = ((i & k) == 0);
                    unsigned long long x = a[i], y = a[ixj];
                    if (up ? (x > y) : (x < y)) { a[i] = y; a[ixj] = x; }
                }
            }
            __syncthreads();
        }
    }
    if (mode == 0) {
        for (int t = tid; t < kcount; t += 512)
            keys[h * NKEYP + t] = (int)(a[t] & 0xFFFFFFFFull);
    } else {
        for (int t = tid; t < kcount; t += 512)
            keys[h * NKEYP + VSZ + t] = (SEQ - 1) - (int)(a[t] & 0xFFFFFFFFull);
        for (int t = NKEY + tid; t < NKEYP; t += 512) keys[h * NKEYP + t] = PADKEY;
    }
}

// ---------------- sort keys ascending per head ----------------------------------
__global__ __launch_bounds__(256) void sortkeys_kernel(int* __restrict__ keys) {
    int h = blockIdx.x;
    __shared__ int a[2048];
    int tid = threadIdx.x;
    for (int i = tid; i < 2048; i += 256)
        a[i] = (i < NKEYP) ? keys[h * NKEYP + i] : PADKEY;
    __syncthreads();
    for (int k = 2; k <= 2048; k <<= 1) {
        for (int j = k >> 1; j > 0; j >>= 1) {
            for (int i = tid; i < 2048; i += 256) {
                int ixj = i ^ j;
                if (ixj > i) {
                    bool up = ((i & k) == 0);
                    int x = a[i], y = a[ixj];
                    if (up ? (x > y) : (x < y)) { a[i] = y; a[ixj] = x; }
                }
            }
            __syncthreads();
        }
    }
    for (int i = tid; i < NKEYP; i += 256) keys[h * NKEYP + i] = a[i];
}

// ---------------- gather ----------------------------------------------------------
__global__ void gather_kernel(const float* __restrict__ kv,
                              const int* __restrict__ keys,
                              float* __restrict__ ksp, float* __restrict__ vsp) {
    int j = blockIdx.x;
    int h = j / NKEYP;
    int d = threadIdx.x;
    int key = keys[j];
    int kvh = h >> 2;
    float kvv = 0.f, vvv = 0.f;
    if (key < SEQ) {
        kvv = kv[(size_t)key * KVW + kvh * HD + d];
        vvv = kv[(size_t)key * KVW + 512 + kvh * HD + d];
    }
    ksp[(size_t)j * HD + d] = kvv;
    vsp[(size_t)j * HD + d] = vvv;
}

// ---------------- sparse attention (TC QK 3xTF32 + SIMT PV, fused mask) ----------
#define QHL_ST 132
#define SP_WORDS (64 * 132 + 32 * 132 + 32 * 68 + 64 * 36 + 32)

__global__ __launch_bounds__(256) void spattn_kernel(const float* __restrict__ q,
                                                     const float* __restrict__ ksp,
                                                     const float* __restrict__ vsp,
                                                     const int* __restrict__ keys,
                                                     float* __restrict__ attout) {
    extern __shared__ uint32_t smem[];
    uint32_t* qhl = smem;
    uint32_t* khl = qhl + 64 * 132;
    float* vs = (float*)(khl + 32 * 132);
    float* ss = vs + 32 * 68;
    int* kid = (int*)(ss + 64 * 36);

    int qb = blockIdx.x;
    int h = blockIdx.y;
    int tid = threadIdx.x;
    int lane = tid & 31;
    int warp = tid >> 5;
    int lr = lane >> 2;
    int lc = lane & 3;
    int wm = warp & 3;
    int wn = warp >> 2;
    int qp = tid >> 3;
    int g = tid & 7;
    int qi0 = qp, qi1 = qp + 32;
    int sglob0 = qb * 64 + qi0;
    int sglob1 = qb * 64 + qi1;
    int qbmax = qb * 64 + 63;

    for (int l = tid; l < 64 * 16; l += 256) {
        int r = l >> 4, c4 = (l & 15) * 4;
        float4 v = *(const float4*)&q[(size_t)(qb * 64 + r) * DIM + h * HD + c4];
        uint32_t* dh = &qhl[r * QHL_ST + c4];
        uint32_t h0 = f2tf32(v.x), h1 = f2tf32(v.y), h2 = f2tf32(v.z), h3 = f2tf32(v.w);
        dh[0] = h0; dh[1] = h1; dh[2] = h2; dh[3] = h3;
        dh[64] = f2tf32(v.x - __uint_as_float(h0));
        dh[65] = f2tf32(v.y - __uint_as_float(h1));
        dh[66] = f2tf32(v.z - __uint_as_float(h2));
        dh[67] = f2tf32(v.w - __uint_as_float(h3));
    }

    float m0 = -INFINITY, m1 = -INFINITY, lsum0 = 0.f, lsum1 = 0.f;
    float out0[8], out1[8];
#pragma unroll
    for (int i = 0; i < 8; i++) { out0[i] = 0.f; out1[i] = 0.f; }

    for (int t = 0; t < NKEYP / 32; t++) {
        __syncthreads();
        if (tid < 32) kid[tid] = keys[h * NKEYP + t * 32 + tid];
        __syncthreads();
        if (kid[0] > qbmax) continue;

        for (int l = tid; l < 32 * 16; l += 256) {
            int r = l >> 4, c4 = (l & 15) * 4;
            float4 kv = *(const float4*)&ksp[((size_t)h * NKEYP + t * 32 + r) * HD + c4];
            uint32_t* dh = &khl[r * QHL_ST + c4];
            uint32_t h0 = f2tf32(kv.x), h1 = f2tf32(kv.y), h2 = f2tf32(kv.z), h3 = f2tf32(kv.w);
            dh[0] = h0; dh[1] = h1; dh[2] = h2; dh[3] = h3;
            dh[64] = f2tf32(kv.x - __uint_as_float(h0));
            dh[65] = f2tf32(kv.y - __uint_as_float(h1));
            dh[66] = f2tf32(kv.z - __uint_as_float(h2));
            dh[67] = f2tf32(kv.w - __uint_as_float(h3));
            *(float4*)&vs[r * 68 + c4] =
                *(const float4*)&vsp[((size_t)h * NKEYP + t * 32 + r) * HD + c4];
        }
        __syncthreads();

        // QK via tensor cores + fused mask/scale in epilogue
        {
            float acc[2][4];
#pragma unroll
            for (int nt = 0; nt < 2; nt++)
#pragma unroll
                for (int e = 0; e < 4; e++) acc[nt][e] = 0.f;
#pragma unroll
            for (int ksI = 0; ksI < 8; ksI++) {
                int kb = ksI * 8;
                int ra = wm * 16 + lr;
                uint32_t aH[4], aL[4];
                aH[0] = qhl[ra * QHL_ST + kb + lc];
                aH[1] = qhl[(ra + 8) * QHL_ST + kb + lc];
                aH[2] = qhl[ra * QHL_ST + kb + lc + 4];
                aH[3] = qhl[(ra + 8) * QHL_ST + kb + lc + 4];
                aL[0] = qhl[ra * QHL_ST + 64 + kb + lc];
                aL[1] = qhl[(ra + 8) * QHL_ST + 64 + kb + lc];
                aL[2] = qhl[ra * QHL_ST + 64 + kb + lc + 4];
                aL[3] = qhl[(ra + 8) * QHL_ST + 64 + kb + lc + 4];
#pragma unroll
                for (int nt = 0; nt < 2; nt++) {
                    int n0 = wn * 16 + nt * 8;
                    uint32_t b0h = khl[(n0 + lr) * QHL_ST + kb + lc];
                    uint32_t b1h = khl[(n0 + lr) * QHL_ST + kb + lc + 4];
                    uint32_t b0l = khl[(n0 + lr) * QHL_ST + 64 + kb + lc];
                    uint32_t b1l = khl[(n0 + lr) * QHL_ST + 64 + kb + lc + 4];
                    mma_tf32(acc[nt], aH, b0h, b1h);
                    mma_tf32(acc[nt], aH, b0l, b1l);
                    mma_tf32(acc[nt], aL, b0h, b1h);
                }
            }
#pragma unroll
            for (int nt = 0; nt < 2; nt++) {
                int row = wm * 16 + lr;
                int col = wn * 16 + nt * 8 + 2 * lc;
#pragma unroll
                for (int e = 0; e < 4; e++) {
                    int rr = row + (e >> 1) * 8;
                    int cc = col + (e & 1);
                    int key = kid[cc];
                    int sg = qb * 64 + rr;
                    float val;
                    if (key >= SEQ) val = -INFINITY;
                    else val = (key <= sg) ? acc[nt][e] * SCALE : -1e30f;
                    ss[rr * 36 + cc] = val;
                }
            }
        }
        __syncthreads();

        float tm0 = m0, tm1 = m1;
#pragma unroll
        for (int j = 0; j < 32; j++) {
            tm0 = fmaxf(tm0, ss[qi0 * 36 + j]);
            tm1 = fmaxf(tm1, ss[qi1 * 36 + j]);
        }
        float c0 = expf(m0 - tm0);
        float c1 = expf(m1 - tm1);
        m0 = tm0; m1 = tm1;
        lsum0 *= c0; lsum1 *= c1;
#pragma unroll
        for (int i = 0; i < 8; i++) { out0[i] *= c0; out1[i] *= c1; }
        __syncthreads();

#pragma unroll
        for (int j = 0; j < 4; j++) {
            int jj = g * 4 + j;
            ss[qi0 * 36 + jj] = expf(ss[qi0 * 36 + jj] - m0);
            ss[qi1 * 36 + jj] = expf(ss[qi1 * 36 + jj] - m1);
        }
        __syncthreads();

        float ps0 = 0.f, ps1 = 0.f;
#pragma unroll
        for (int j = 0; j < 32; j++) {
            float p0 = ss[qi0 * 36 + j];
            float p1 = ss[qi1 * 36 + j];
            ps0 += p0; ps1 += p1;
            float4 va = *(float4*)&vs[j * 68 + g * 8];
            float4 vb = *(float4*)&vs[j * 68 + g * 8 + 4];
            out0[0] += p0 * va.x; out0[1] += p0 * va.y; out0[2] += p0 * va.z; out0[3] += p0 * va.w;
            out0[4] += p0 * vb.x; out0[5] += p0 * vb.y; out0[6] += p0 * vb.z; out0[7] += p0 * vb.w;
            out1[0] += p1 * va.x; out1[1] += p1 * va.y; out1[2] += p1 * va.z; out1[3] += p1 * va.w;
            out1[4] += p1 * vb.x; out1[5] += p1 * vb.y; out1[6] += p1 * vb.z; out1[7] += p1 * vb.w;
        }
        lsum0 += ps0;
        lsum1 += ps1;
    }

    if (m0 < -5e29f) {
        lsum0 = (float)NKEY;
#pragma unroll
        for (int i = 0; i < 8; i++) out0[i] = 0.f;
        for (int j = 0; j < NKEYP; j++) {
            if (keys[h * NKEYP + j] < SEQ) {
                const float* vr = &vsp[((size_t)h * NKEYP + j) * HD + g * 8];
#pragma unroll
                for (int i = 0; i < 8; i++) out0[i] += vr[i];
            }
        }
    }
    if (m1 < -5e29f) {
        lsum1 = (float)NKEY;
#pragma unroll
        for (int i = 0; i < 8; i++) out1[i] = 0.f;
        for (int j = 0; j < NKEYP; j++) {
            if (keys[h * NKEYP + j] < SEQ) {
                const float* vr = &vsp[((size_t)h * NKEYP + j) * HD + g * 8];
#pragma unroll
                for (int i = 0; i < 8; i++) out1[i] += vr[i];
            }
        }
    }

    float inv0 = 1.f / lsum0;
    float inv1 = 1.f / lsum1;
#pragma unroll
    for (int i = 0; i < 8; i++) {
        attout[(size_t)sglob0 * DIM + h * HD + g * 8 + i] = out0[i] * inv0;
        attout[(size_t)sglob1 * DIM + h * HD + g * 8 + i] = out1[i] * inv1;
    }
}

// --------------------------------- launch --------------------------------
extern "C" void kernel_launch(void* const* d_in, const int* in_sizes, int n_in,
                              void* d_out, int out_size) {
    const float* x    = (const float*)d_in[0];
    const float* fcos = (const float*)d_in[1];
    const float* fsin = (const float*)d_in[2];
    const float* wq   = (const float*)d_in[3];
    const float* wk   = (const float*)d_in[4];
    const float* wv   = (const float*)d_in[5];
    const float* wo   = (const float*)d_in[6];
    float* out = (float*)d_out;

    float *q, *q64, *q64p, *wkv, *kv, *probs, *vert, *dgp, *ksp, *vsp, *att;
    int* keys;
    __half *wqt, *wot;
    cudaGetSymbolAddress((void**)&q, g_q);
    cudaGetSymbolAddress((void**)&q64, g_q64);
    cudaGetSymbolAddress((void**)&q64p, g_q64p);
    cudaGetSymbolAddress((void**)&wkv, g_wkv);
    cudaGetSymbolAddress((void**)&kv, g_kv);
    cudaGetSymbolAddress((void**)&probs, g_probs);
    cudaGetSymbolAddress((void**)&vert, g_vert);
    cudaGetSymbolAddress((void**)&dgp, g_diag);
    cudaGetSymbolAddress((void**)&keys, g_keys);
    cudaGetSymbolAddress((void**)&ksp, g_ksp);
    cudaGetSymbolAddress((void**)&vsp, g_vsp);
    cudaGetSymbolAddress((void**)&att, g_att);
    cudaGetSymbolAddress((void**)&wqt, g_wqt);
    cudaGetSymbolAddress((void**)&wot, g_wot);

    // weight prep
    transp_half<<<dim3(DIM / 32, DIM / 32), dim3(32, 8)>>>(wq, wqt);
    transp_half<<<dim3(DIM / 32, DIM / 32), dim3(32, 8)>>>(wo, wot);
    concat_wkv<<<DIM, 256>>>(wk, wv, wkv);

    // projections: q fp16 TC, kv fused 3xTF32
    gemm_f16<<<dim3(DIM / 128, SEQ / 128), 256>>>(x, wqt, q, SEQ, DIM, DIM);
    gemm_tf32x3<<<dim3(KVW / 128, SEQ / 128), 256>>>(x, wkv, kv, SEQ, KVW, DIM);

    // exact fp32 q rows 0..63
    qproj_part<<<dim3(16, 8, 8), 128>>>(x, wq, q64p);
    qproj_red<<<(ESTQ * DIM + 255) / 256, 256>>>(q64p, q64);

    // RoPE
    {
        int tq = SEQ * NH * 32;
        rope_kernel<<<(tq + 255) / 256, 256>>>(q, fcos, fsin, NH, DIM, tq);
        int tk = SEQ * NKV * 32;
        rope_kernel<<<(tk + 255) / 256, 256>>>(kv, fcos, fsin, NKV, KVW, tk);
        int tq64 = ESTQ * NH * 32;
        rope_kernel<<<(tq64 + 255) / 256, 256>>>(q64, fcos, fsin, NH, DIM, tq64);
    }

    // estimation
    est_score<<<dim3(SEQ / 64, NH), 256>>>(q64, kv, probs);
    est_norm<<<dim3(ESTQ, NH), 256>>>(probs);

    vertical_kernel<<<(NH * SEQ) / 256, 256>>>(probs, vert);
    diag_kernel<<<(NH * SEQ) / 256, 256>>>(probs, dgp);

    // merged top-k (both selections in one launch)
    topk2_kernel<<<64, 512>>>(vert, dgp, keys);
    sortkeys_kernel<<<NH, 256>>>(keys);

    gather_kernel<<<NH * NKEYP, 64>>>(kv, keys, ksp, vsp);

    {
        size_t spbytes = (size_t)SP_WORDS * 4;
        cudaFuncSetAttribute(spattn_kernel,
                             cudaFuncAttributeMaxDynamicSharedMemorySize, (int)spbytes);
        spattn_kernel<<<dim3(SEQ / 64, NH), 256, spbytes>>>(q, ksp, vsp, keys, att);
    }

    // output projection: fp16 TC
    gemm_f16<<<dim3(DIM / 128, SEQ / 128), 256>>>(att, wot, out, SEQ, DIM, DIM);
}

// round 10
// speedup vs baseline: 2.9887x; 1.0368x over previous
#include <cuda_runtime.h>
#include <cuda_fp16.h>
#include <math.h>
#include <stdint.h>

#define SEQ   4096
#define DIM   2048
#define NH    32
#define NKV   8
#define HD    64
#define ESTQ  64
#define VSZ   300
#define SSZ   800
#define NKEY  1100
#define NKEYP 1152
#define SCALE 0.125f
#define PADKEY 0x3FFFFFFF
#define KVW   1024

// ---------------- device scratch ----------------
__device__ float g_q[SEQ * DIM];
__device__ float g_q64[ESTQ * DIM];
__device__ float g_q64p[8 * ESTQ * DIM];
__device__ float g_wkv[DIM * KVW];
__device__ float g_kv[SEQ * KVW];
__device__ float g_probs[NH * ESTQ * SEQ];
__device__ float g_vert[NH * SEQ];
__device__ float g_diag[NH * SEQ];
__device__ int   g_keys[NH * NKEYP];
__device__ float g_ksp[NH * NKEYP * HD];
__device__ float g_vsp[NH * NKEYP * HD];
__device__ __half g_xh[SEQ * DIM];    // x in fp16
__device__ __half g_atth[SEQ * DIM];  // attention output in fp16
__device__ __half g_wqt[DIM * DIM];   // wq transposed [n][k] fp16
__device__ __half g_wot[DIM * DIM];   // wo transposed [n][k] fp16

// ---------------- helpers ------------------------------------------------
__device__ __forceinline__ uint32_t f2tf32(float f) {
    uint32_t r;
    asm("cvt.rna.tf32.f32 %0, %1;" : "=r"(r) : "f"(f));
    return r;
}

__device__ __forceinline__ void mma_tf32(float c[4], const uint32_t a[4],
                                         uint32_t b0, uint32_t b1) {
    asm volatile(
        "mma.sync.aligned.m16n8k8.row.col.f32.tf32.tf32.f32 "
        "{%0,%1,%2,%3}, {%4,%5,%6,%7}, {%8,%9}, {%0,%1,%2,%3};\n"
        : "+f"(c[0]), "+f"(c[1]), "+f"(c[2]), "+f"(c[3])
        : "r"(a[0]), "r"(a[1]), "r"(a[2]), "r"(a[3]), "r"(b0), "r"(b1));
}

__device__ __forceinline__ void mma_f16(float c[4], const uint32_t a[4],
                                        uint32_t b0, uint32_t b1) {
    asm volatile(
        "mma.sync.aligned.m16n8k16.row.col.f32.f16.f16.f32 "
        "{%0,%1,%2,%3}, {%4,%5,%6,%7}, {%8,%9}, {%0,%1,%2,%3};\n"
        : "+f"(c[0]), "+f"(c[1]), "+f"(c[2]), "+f"(c[3])
        : "r"(a[0]), "r"(a[1]), "r"(a[2]), "r"(a[3]), "r"(b0), "r"(b1));
}

__device__ __forceinline__ uint32_t smem_u32(const void* p) {
    uint32_t a;
    asm("{ .reg .u64 t; cvta.to.shared.u64 t, %1; cvt.u32.u64 %0, t; }" : "=r"(a) : "l"(p));
    return a;
}

// ================= fp16 k16 GEMM with cp.async double buffering ===========
// A fp16 [M][K]; Bt fp16 [N][K]; C fp32. 128x128 tile, BK=32, 256 thr.
#define AF_ST 20

__global__ __launch_bounds__(256) void gemm_f16(const __half* __restrict__ A,
                                                const __half* __restrict__ Bt,
                                                float* __restrict__ C,
                                                int M, int N, int K) {
    __shared__ uint32_t As[2][128 * AF_ST];
    __shared__ uint32_t Bs[2][128 * AF_ST];
    int tid = threadIdx.x;
    int lane = tid & 31;
    int warp = tid >> 5;
    int wm = warp & 3;
    int wn = warp >> 2;
    int row0 = blockIdx.y * 128;
    int col0 = blockIdx.x * 128;
    int lr = lane >> 2;
    int lc = lane & 3;

    uint32_t asb[2], bsb[2];
    asb[0] = smem_u32(&As[0][0]);
    asb[1] = smem_u32(&As[1][0]);
    bsb[0] = smem_u32(&Bs[0][0]);
    bsb[1] = smem_u32(&Bs[1][0]);

    float acc[2][8][4];
#pragma unroll
    for (int mi = 0; mi < 2; mi++)
#pragma unroll
        for (int nj = 0; nj < 8; nj++)
#pragma unroll
            for (int e = 0; e < 4; e++) acc[mi][nj][e] = 0.f;

    int r_ld = tid >> 2;            // row 0..127 (for i=0,1: r, r+64)
    int j_ld = tid & 3;             // 16B chunk 0..3 within 64B row

    // issue tile 0 into buf 0
    {
#pragma unroll
        for (int i = 0; i < 2; i++) {
            int r = r_ld + i * 64;
            uint32_t da = asb[0] + (uint32_t)(r * AF_ST + j_ld * 4) * 4;
            const __half* sa = A + (size_t)(row0 + r) * K + j_ld * 8;
            asm volatile("cp.async.ca.shared.global [%0], [%1], 16;" :: "r"(da), "l"(sa));
            uint32_t db = bsb[0] + (uint32_t)(r * AF_ST + j_ld * 4) * 4;
            const __half* sb = Bt + (size_t)(col0 + r) * K + j_ld * 8;
            asm volatile("cp.async.ca.shared.global [%0], [%1], 16;" :: "r"(db), "l"(sb));
        }
        asm volatile("cp.async.commit_group;");
    }

    int KC = K >> 5;
    for (int c = 0; c < KC; c++) {
        int buf = c & 1;
        if (c + 1 < KC) {
            int k0 = (c + 1) << 5;
            int nb = buf ^ 1;
#pragma unroll
            for (int i = 0; i < 2; i++) {
                int r = r_ld + i * 64;
                uint32_t da = asb[nb] + (uint32_t)(r * AF_ST + j_ld * 4) * 4;
                const __half* sa = A + (size_t)(row0 + r) * K + k0 + j_ld * 8;
                asm volatile("cp.async.ca.shared.global [%0], [%1], 16;" :: "r"(da), "l"(sa));
                uint32_t db = bsb[nb] + (uint32_t)(r * AF_ST + j_ld * 4) * 4;
                const __half* sb = Bt + (size_t)(col0 + r) * K + k0 + j_ld * 8;
                asm volatile("cp.async.ca.shared.global [%0], [%1], 16;" :: "r"(db), "l"(sb));
            }
            asm volatile("cp.async.commit_group;");
            asm volatile("cp.async.wait_group 1;");
        } else {
            asm volatile("cp.async.wait_group 0;");
        }
        __syncthreads();

        const uint32_t* Ab = As[buf];
        const uint32_t* Bb = Bs[buf];
#pragma unroll
        for (int ks = 0; ks < 2; ks++) {
            int kb = ks * 8;
            uint32_t a[2][4];
#pragma unroll
            for (int mi = 0; mi < 2; mi++) {
                int ra = wm * 32 + mi * 16 + lr;
                a[mi][0] = Ab[ra * AF_ST + kb + lc];
                a[mi][1] = Ab[(ra + 8) * AF_ST + kb + lc];
                a[mi][2] = Ab[ra * AF_ST + kb + lc + 4];
                a[mi][3] = Ab[(ra + 8) * AF_ST + kb + lc + 4];
            }
#pragma unroll
            for (int nj = 0; nj < 8; nj++) {
                int col = wn * 64 + nj * 8 + lr;
                uint32_t b0 = Bb[col * AF_ST + kb + lc];
                uint32_t b1 = Bb[col * AF_ST + kb + lc + 4];
                mma_f16(acc[0][nj], a[0], b0, b1);
                mma_f16(acc[1][nj], a[1], b0, b1);
            }
        }
        __syncthreads();
    }

#pragma unroll
    for (int mi = 0; mi < 2; mi++) {
        int row = row0 + wm * 32 + mi * 16 + lr;
#pragma unroll
        for (int nj = 0; nj < 8; nj++) {
            int col = col0 + wn * 64 + nj * 8 + 2 * lc;
            float* cp0 = C + (size_t)row * N + col;
            cp0[0] = acc[mi][nj][0];
            cp0[1] = acc[mi][nj][1];
            float* cp1 = C + (size_t)(row + 8) * N + col;
            cp1[0] = acc[mi][nj][2];
            cp1[1] = acc[mi][nj][3];
        }
    }
}

// ---------------- fp32 -> fp16 elementwise ---------------------------------
__global__ void f2h_kernel(const float* __restrict__ a, __half* __restrict__ h, int n4) {
    int i = blockIdx.x * 256 + threadIdx.x;
    if (i >= n4) return;
    float4 v = ((const float4*)a)[i];
    __half2 h0 = __floats2half2_rn(v.x, v.y);
    __half2 h1 = __floats2half2_rn(v.z, v.w);
    ((uint2*)h)[i] = make_uint2(*(uint32_t*)&h0, *(uint32_t*)&h1);
}

// ---------------- transpose fp32 [k][n] -> fp16 [n][k] ----------------------
__global__ void transp_half(const float* __restrict__ w, __half* __restrict__ t) {
    __shared__ float tile[32][33];
    int bx = blockIdx.x * 32;
    int by = blockIdx.y * 32;
    int tx = threadIdx.x, ty = threadIdx.y;
    for (int i = 0; i < 32; i += 8)
        tile[ty + i][tx] = w[(size_t)(by + ty + i) * DIM + bx + tx];
    __syncthreads();
    for (int i = 0; i < 32; i += 8)
        t[(size_t)(bx + ty + i) * DIM + by + tx] = __float2half_rn(tile[tx][ty + i]);
}

// ================= 3xTF32 GEMM (BK=16) — kv projection ====================
#define AS_ST 20
#define BS_ST 132

__global__ __launch_bounds__(256) void gemm_tf32x3(const float* __restrict__ A,
                                                   const float* __restrict__ B,
                                                   float* __restrict__ C,
                                                   int M, int N, int K) {
    __shared__ uint32_t AsH[128 * AS_ST];
    __shared__ uint32_t AsL[128 * AS_ST];
    __shared__ uint32_t BsH[16 * BS_ST];
    __shared__ uint32_t BsL[16 * BS_ST];
    int tid = threadIdx.x;
    int lane = tid & 31;
    int warp = tid >> 5;
    int wm = warp & 3;
    int wn = warp >> 2;
    int row0 = blockIdx.y * 128;
    int col0 = blockIdx.x * 128;

    float acc[2][8][4];
#pragma unroll
    for (int mi = 0; mi < 2; mi++)
#pragma unroll
        for (int nj = 0; nj < 8; nj++)
#pragma unroll
            for (int e = 0; e < 4; e++) acc[mi][nj][e] = 0.f;

    int lr = lane >> 2;
    int lc = lane & 3;

    for (int k0 = 0; k0 < K; k0 += 16) {
#pragma unroll
        for (int i = 0; i < 2; i++) {
            int f = i * 256 + tid;
            int ra = f >> 2, ca = (f & 3) << 2;
            float4 v = *(const float4*)(A + (size_t)(row0 + ra) * K + k0 + ca);
            uint32_t* dh = &AsH[ra * AS_ST + ca];
            uint32_t* dl = &AsL[ra * AS_ST + ca];
            uint32_t h0 = f2tf32(v.x), h1 = f2tf32(v.y), h2 = f2tf32(v.z), h3 = f2tf32(v.w);
            dh[0] = h0; dh[1] = h1; dh[2] = h2; dh[3] = h3;
            dl[0] = f2tf32(v.x - __uint_as_float(h0));
            dl[1] = f2tf32(v.y - __uint_as_float(h1));
            dl[2] = f2tf32(v.z - __uint_as_float(h2));
            dl[3] = f2tf32(v.w - __uint_as_float(h3));
            int rb = f >> 5, cb = (f & 31) << 2;
            float4 bv = *(const float4*)(B + (size_t)(k0 + rb) * N + col0 + cb);
            uint32_t* eh = &BsH[rb * BS_ST + cb];
            uint32_t* el = &BsL[rb * BS_ST + cb];
            uint32_t g0 = f2tf32(bv.x), g1 = f2tf32(bv.y), g2 = f2tf32(bv.z), g3 = f2tf32(bv.w);
            eh[0] = g0; eh[1] = g1; eh[2] = g2; eh[3] = g3;
            el[0] = f2tf32(bv.x - __uint_as_float(g0));
            el[1] = f2tf32(bv.y - __uint_as_float(g1));
            el[2] = f2tf32(bv.z - __uint_as_float(g2));
            el[3] = f2tf32(bv.w - __uint_as_float(g3));
        }
        __syncthreads();

#pragma unroll
        for (int ks = 0; ks < 2; ks++) {
            int kb = ks * 8;
            uint32_t aH[2][4], aL[2][4];
#pragma unroll
            for (int mi = 0; mi < 2; mi++) {
                int r = wm * 32 + mi * 16 + lr;
                aH[mi][0] = AsH[r * AS_ST + kb + lc];
                aH[mi][1] = AsH[(r + 8) * AS_ST + kb + lc];
                aH[mi][2] = AsH[r * AS_ST + kb + lc + 4];
                aH[mi][3] = AsH[(r + 8) * AS_ST + kb + lc + 4];
                aL[mi][0] = AsL[r * AS_ST + kb + lc];
                aL[mi][1] = AsL[(r + 8) * AS_ST + kb + lc];
                aL[mi][2] = AsL[r * AS_ST + kb + lc + 4];
                aL[mi][3] = AsL[(r + 8) * AS_ST + kb + lc + 4];
            }
#pragma unroll
            for (int nj = 0; nj < 8; nj++) {
                int c = wn * 64 + nj * 8 + lr;
                uint32_t b0h = BsH[(kb + lc) * BS_ST + c];
                uint32_t b1h = BsH[(kb + lc + 4) * BS_ST + c];
                uint32_t b0l = BsL[(kb + lc) * BS_ST + c];
                uint32_t b1l = BsL[(kb + lc + 4) * BS_ST + c];
#pragma unroll
                for (int mi = 0; mi < 2; mi++) {
                    mma_tf32(acc[mi][nj], aH[mi], b0h, b1h);
                    mma_tf32(acc[mi][nj], aH[mi], b0l, b1l);
                    mma_tf32(acc[mi][nj], aL[mi], b0h, b1h);
                }
            }
        }
        __syncthreads();
    }

#pragma unroll
    for (int mi = 0; mi < 2; mi++) {
        int row = row0 + wm * 32 + mi * 16 + lr;
#pragma unroll
        for (int nj = 0; nj < 8; nj++) {
            int col = col0 + wn * 64 + nj * 8 + 2 * lc;
            float* cp0 = C + (size_t)row * N + col;
            cp0[0] = acc[mi][nj][0];
            cp0[1] = acc[mi][nj][1];
            float* cp1 = C + (size_t)(row + 8) * N + col;
            cp1[0] = acc[mi][nj][2];
            cp1[1] = acc[mi][nj][3];
        }
    }
}

// ---------------- concat wk|wv ---------------------------------------------
__global__ void concat_wkv(const float* __restrict__ wk, const float* __restrict__ wv,
                           float* __restrict__ wkv) {
    int idx = blockIdx.x * 256 + threadIdx.x;
    int r = idx >> 8;
    int c4 = idx & 255;
    float4 val = (c4 < 128) ? ((const float4*)wk)[r * 128 + c4]
                            : ((const float4*)wv)[r * 128 + (c4 - 128)];
    ((float4*)wkv)[r * 256 + c4] = val;
}

// ---------------- exact fp32 q rows 0..63: split-K ---------------------------
__global__ __launch_bounds__(128) void qproj_part(const float* __restrict__ x,
                                                  const float* __restrict__ wq,
                                                  float* __restrict__ part) {
    __shared__ float xs[8][256];
    int tid = threadIdx.x;
    int col = blockIdx.x * 128 + tid;
    int r0 = blockIdx.y * 8;
    int k0 = blockIdx.z * 256;
    float acc[8];
#pragma unroll
    for (int rr = 0; rr < 8; rr++) acc[rr] = 0.f;

    for (int i = tid; i < 8 * 256; i += 128) {
        int rr = i >> 8, kk = i & 255;
        xs[rr][kk] = x[(size_t)(r0 + rr) * DIM + k0 + kk];
    }
    __syncthreads();
    for (int kk = 0; kk < 256; kk++) {
        float w = wq[(size_t)(k0 + kk) * DIM + col];
#pragma unroll
        for (int rr = 0; rr < 8; rr++) acc[rr] += xs[rr][kk] * w;
    }
#pragma unroll
    for (int rr = 0; rr < 8; rr++)
        part[(size_t)blockIdx.z * ESTQ * DIM + (size_t)(r0 + rr) * DIM + col] = acc[rr];
}

__global__ void qproj_red(const float* __restrict__ part, float* __restrict__ q64) {
    int idx = blockIdx.x * 256 + threadIdx.x;
    if (idx >= ESTQ * DIM) return;
    float s = 0.f;
#pragma unroll
    for (int ks = 0; ks < 8; ks++) s += part[(size_t)ks * ESTQ * DIM + idx];
    q64[idx] = s;
}

// ---------------- RoPE -------------------------------------------------------
__global__ void rope_kernel(float* t, const float* __restrict__ cosb,
                            const float* __restrict__ sinb, int H, int stride, int total) {
    int idx = blockIdx.x * blockDim.x + threadIdx.x;
    if (idx >= total) return;
    int d2 = idx & 31;
    int h = (idx >> 5) % H;
    int s = idx / (32 * H);
    float c = cosb[s * 32 + d2];
    float sn = sinb[s * 32 + d2];
    float* p = t + (size_t)s * stride + h * 64 + 2 * d2;
    float xr = p[0], xi = p[1];
    p[0] = xr * c - xi * sn;
    p[1] = xr * sn + xi * c;
}

// ---------------- est phase A -----------------------------------------------
__global__ __launch_bounds__(256) void est_score(const float* __restrict__ q64,
                                                 const float* __restrict__ kv,
                                                 float* __restrict__ probs) {
    __shared__ float qs[64][68];
    __shared__ float ksm[64][68];
    int tid = threadIdx.x;
    int h = blockIdx.y;
    int c0 = blockIdx.x * 64;
    int kvh = h >> 2;
    int qi = tid >> 2;
    int kg = tid & 3;

    for (int l = tid; l < 64 * 64; l += 256) {
        int r = l >> 6, d = l & 63;
        qs[r][d] = q64[(size_t)r * DIM + h * HD + d];
        ksm[r][d] = kv[(size_t)(c0 + r) * KVW + kvh * HD + d];
    }
    __syncthreads();

    float s16[16];
#pragma unroll
    for (int j = 0; j < 16; j++) s16[j] = 0.f;
#pragma unroll
    for (int d4 = 0; d4 < 16; d4++) {
        float4 q4 = *(float4*)&qs[qi][d4 * 4];
#pragma unroll
        for (int j = 0; j < 16; j++) {
            float4 k4 = *(float4*)&ksm[kg * 16 + j][d4 * 4];
            s16[j] += q4.x * k4.x + q4.y * k4.y + q4.z * k4.z + q4.w * k4.w;
        }
    }
    float* pr = probs + ((size_t)h * ESTQ + qi) * SEQ + c0 + kg * 16;
#pragma unroll
    for (int j = 0; j < 16; j++) {
        int kk = c0 + kg * 16 + j;
        float val = s16[j] * SCALE;
        if (kk >= SEQ - ESTQ && qi < kk - (SEQ - ESTQ)) val = -INFINITY;
        pr[j] = val;
    }
}

// ---------------- est phase B -------------------------------------------------
__global__ __launch_bounds__(256) void est_norm(float* __restrict__ probs) {
    int qi = blockIdx.x;
    int h = blockIdx.y;
    __shared__ float sc[SEQ];
    __shared__ float red[8];
    int tid = threadIdx.x;
    float* pr = probs + ((size_t)h * ESTQ + qi) * SEQ;

    for (int l = tid; l < SEQ / 4; l += 256)
        *(float4*)&sc[l * 4] = *(const float4*)&pr[l * 4];
    __syncthreads();

    float m = -INFINITY;
    for (int kk = tid; kk < SEQ; kk += 256) m = fmaxf(m, sc[kk]);
#pragma unroll
    for (int o = 16; o; o >>= 1) m = fmaxf(m, __shfl_xor_sync(0xFFFFFFFFu, m, o));
    if ((tid & 31) == 0) red[tid >> 5] = m;
    __syncthreads();
    if (tid == 0) {
        float mm = red[0];
#pragma unroll
        for (int i = 1; i < 8; i++) mm = fmaxf(mm, red[i]);
        red[0] = mm;
    }
    __syncthreads();
    m = red[0];
    __syncthreads();

    float s = 0.f;
    for (int kk = tid; kk < SEQ; kk += 256) {
        float e = expf(sc[kk] - m);
        sc[kk] = e;
        s += e;
    }
#pragma unroll
    for (int o = 16; o; o >>= 1) s += __shfl_xor_sync(0xFFFFFFFFu, s, o);
    if ((tid & 31) == 0) red[tid >> 5] = s;
    __syncthreads();
    if (tid == 0) {
        float ss = 0.f;
#pragma unroll
        for (int i = 0; i < 8; i++) ss += red[i];
        red[0] = ss;
    }
    __syncthreads();
    float inv = 1.f / red[0];
    for (int kk = tid; kk < SEQ; kk += 256) pr[kk] = sc[kk] * inv;
}

// ---------------- vertical / diagonal ------------------------------------------
__global__ void vertical_kernel(const float* __restrict__ probs, float* __restrict__ vert) {
    int idx = blockIdx.x * 256 + threadIdx.x;
    int h = idx >> 12;
    int kk = idx & (SEQ - 1);
    float s = 0.f;
    const float* base = probs + (size_t)h * ESTQ * SEQ + kk;
    for (int i = 0; i < ESTQ; i++) s += base[(size_t)i * SEQ];
    vert[idx] = s;
}

__global__ void diag_kernel(const float* __restrict__ probs, float* __restrict__ dg) {
    int idx = blockIdx.x * 256 + threadIdx.x;
    int h = idx >> 12;
    int jp = idx & (SEQ - 1);
    float s = 0.f;
    const float* base = probs + (size_t)h * ESTQ * SEQ;
    for (int i = 0; i < ESTQ; i++) {
        int col = i + jp - 63;
        if (col >= 0 && col < SEQ) s += base[(size_t)i * SEQ + col];
    }
    dg[idx] = s;
}

// ---------------- merged top-k ---------------------------------------------------
__global__ void topk2_kernel(const float* __restrict__ vert, const float* __restrict__ dg,
                             int* __restrict__ keys) {
    int b = blockIdx.x;
    int mode = b >> 5;
    int h = b & 31;
    const float* vals = mode ? dg : vert;
    int kcount = mode ? SSZ : VSZ;
    __shared__ unsigned long long a[SEQ];
    int tid = threadIdx.x;
    for (int i = tid; i < SEQ; i += 512) {
        unsigned u = __float_as_uint(vals[h * SEQ + i]);
        u = (u & 0x80000000u) ? ~u : (u | 0x80000000u);
        a[i] = ((unsigned long long)(~u) << 32) | (unsigned)i;
    }
    __syncthreads();
    for (int k = 2; k <= SEQ; k <<= 1) {
        for (int j = k >> 1; j > 0; j >>= 1) {
            for (int i = tid; i < SEQ; i += 512) {
                int ixj = i ^ j;
                if (ixj > i) {
                    bool up = ((i & k) == 0);
                    unsigned long long x = a[i], y = a[ixj];
                    if (up ? (x > y) : (x < y)) { a[i] = y; a[ixj] = x; }
                }
            }
            __syncthreads();
        }
    }
    if (mode == 0) {
        for (int t = tid; t < kcount; t += 512)
            keys[h * NKEYP + t] = (int)(a[t] & 0xFFFFFFFFull);
    } else {
        for (int t = tid; t < kcount; t += 512)
            keys[h * NKEYP + VSZ + t] = (SEQ - 1) - (int)(a[t] & 0xFFFFFFFFull);
        for (int t = NKEY + tid; t < NKEYP; t += 512) keys[h * NKEYP + t] = PADKEY;
    }
}

// ---------------- sort keys ascending per head ----------------------------------
__global__ __launch_bounds__(256) void sortkeys_kernel(int* __restrict__ keys) {
    int h = blockIdx.x;
    __shared__ int a[2048];
    int tid = threadIdx.x;
    for (int i = tid; i < 2048; i += 256)
        a[i] = (i < NKEYP) ? keys[h * NKEYP + i] : PADKEY;
    __syncthreads();
    for (int k = 2; k <= 2048; k <<= 1) {
        for (int j = k >> 1; j > 0; j >>= 1) {
            for (int i = tid; i < 2048; i += 256) {
                int ixj = i ^ j;
                if (ixj > i) {
                    bool up = ((i & k) == 0);
                    int x = a[i], y = a[ixj];
                    if (up ? (x > y) : (x < y)) { a[i] = y; a[ixj] = x; }
                }
            }
            __syncthreads();
        }
    }
    for (int i = tid; i < NKEYP; i += 256) keys[h * NKEYP + i] = a[i];
}

// ---------------- gather ----------------------------------------------------------
__global__ void gather_kernel(const float* __restrict__ kv,
                              const int* __restrict__ keys,
                              float* __restrict__ ksp, float* __restrict__ vsp) {
    int j = blockIdx.x;
    int h = j / NKEYP;
    int d = threadIdx.x;
    int key = keys[j];
    int kvh = h >> 2;
    float kvv = 0.f, vvv = 0.f;
    if (key < SEQ) {
        kvv = kv[(size_t)key * KVW + kvh * HD + d];
        vvv = kv[(size_t)key * KVW + 512 + kvh * HD + d];
    }
    ksp[(size_t)j * HD + d] = kvv;
    vsp[(size_t)j * HD + d] = vvv;
}

// ---------------- sparse attention (TC QK 3xTF32 + SIMT PV, fp16 out) ------------
#define QHL_ST 132
#define SP_WORDS (64 * 132 + 32 * 132 + 32 * 68 + 64 * 36 + 32)

__global__ __launch_bounds__(256) void spattn_kernel(const float* __restrict__ q,
                                                     const float* __restrict__ ksp,
                                                     const float* __restrict__ vsp,
                                                     const int* __restrict__ keys,
                                                     __half* __restrict__ attout) {
    extern __shared__ uint32_t smem[];
    uint32_t* qhl = smem;
    uint32_t* khl = qhl + 64 * 132;
    float* vs = (float*)(khl + 32 * 132);
    float* ss = vs + 32 * 68;
    int* kid = (int*)(ss + 64 * 36);

    int qb = blockIdx.x;
    int h = blockIdx.y;
    int tid = threadIdx.x;
    int lane = tid & 31;
    int warp = tid >> 5;
    int lr = lane >> 2;
    int lc = lane & 3;
    int wm = warp & 3;
    int wn = warp >> 2;
    int qp = tid >> 3;
    int g = tid & 7;
    int qi0 = qp, qi1 = qp + 32;
    int sglob0 = qb * 64 + qi0;
    int sglob1 = qb * 64 + qi1;
    int qbmax = qb * 64 + 63;

    for (int l = tid; l < 64 * 16; l += 256) {
        int r = l >> 4, c4 = (l & 15) * 4;
        float4 v = *(const float4*)&q[(size_t)(qb * 64 + r) * DIM + h * HD + c4];
        uint32_t* dh = &qhl[r * QHL_ST + c4];
        uint32_t h0 = f2tf32(v.x), h1 = f2tf32(v.y), h2 = f2tf32(v.z), h3 = f2tf32(v.w);
        dh[0] = h0; dh[1] = h1; dh[2] = h2; dh[3] = h3;
        dh[64] = f2tf32(v.x - __uint_as_float(h0));
        dh[65] = f2tf32(v.y - __uint_as_float(h1));
        dh[66] = f2tf32(v.z - __uint_as_float(h2));
        dh[67] = f2tf32(v.w - __uint_as_float(h3));
    }

    float m0 = -INFINITY, m1 = -INFINITY, lsum0 = 0.f, lsum1 = 0.f;
    float out0[8], out1[8];
#pragma unroll
    for (int i = 0; i < 8; i++) { out0[i] = 0.f; out1[i] = 0.f; }

    for (int t = 0; t < NKEYP / 32; t++) {
        __syncthreads();
        if (tid < 32) kid[tid] = keys[h * NKEYP + t * 32 + tid];
        __syncthreads();
        if (kid[0] > qbmax) continue;

        for (int l = tid; l < 32 * 16; l += 256) {
            int r = l >> 4, c4 = (l & 15) * 4;
            float4 kv = *(const float4*)&ksp[((size_t)h * NKEYP + t * 32 + r) * HD + c4];
            uint32_t* dh = &khl[r * QHL_ST + c4];
            uint32_t h0 = f2tf32(kv.x), h1 = f2tf32(kv.y), h2 = f2tf32(kv.z), h3 = f2tf32(kv.w);
            dh[0] = h0; dh[1] = h1; dh[2] = h2; dh[3] = h3;
            dh[64] = f2tf32(kv.x - __uint_as_float(h0));
            dh[65] = f2tf32(kv.y - __uint_as_float(h1));
            dh[66] = f2tf32(kv.z - __uint_as_float(h2));
            dh[67] = f2tf32(kv.w - __uint_as_float(h3));
            *(float4*)&vs[r * 68 + c4] =
                *(const float4*)&vsp[((size_t)h * NKEYP + t * 32 + r) * HD + c4];
        }
        __syncthreads();

        {
            float acc[2][4];
#pragma unroll
            for (int nt = 0; nt < 2; nt++)
#pragma unroll
                for (int e = 0; e < 4; e++) acc[nt][e] = 0.f;
#pragma unroll
            for (int ksI = 0; ksI < 8; ksI++) {
                int kb = ksI * 8;
                int ra = wm * 16 + lr;
                uint32_t aH[4], aL[4];
                aH[0] = qhl[ra * QHL_ST + kb + lc];
                aH[1] = qhl[(ra + 8) * QHL_ST + kb + lc];
                aH[2] = qhl[ra * QHL_ST + kb + lc + 4];
                aH[3] = qhl[(ra + 8) * QHL_ST + kb + lc + 4];
                aL[0] = qhl[ra * QHL_ST + 64 + kb + lc];
                aL[1] = qhl[(ra + 8) * QHL_ST + 64 + kb + lc];
                aL[2] = qhl[ra * QHL_ST + 64 + kb + lc + 4];
                aL[3] = qhl[(ra + 8) * QHL_ST + 64 + kb + lc + 4];
#pragma unroll
                for (int nt = 0; nt < 2; nt++) {
                    int n0 = wn * 16 + nt * 8;
                    uint32_t b0h = khl[(n0 + lr) * QHL_ST + kb + lc];
                    uint32_t b1h = khl[(n0 + lr) * QHL_ST + kb + lc + 4];
                    uint32_t b0l = khl[(n0 + lr) * QHL_ST + 64 + kb + lc];
                    uint32_t b1l = khl[(n0 + lr) * QHL_ST + 64 + kb + lc + 4];
                    mma_tf32(acc[nt], aH, b0h, b1h);
                    mma_tf32(acc[nt], aH, b0l, b1l);
                    mma_tf32(acc[nt], aL, b0h, b1h);
                }
            }
#pragma unroll
            for (int nt = 0; nt < 2; nt++) {
                int row = wm * 16 + lr;
                int col = wn * 16 + nt * 8 + 2 * lc;
#pragma unroll
                for (int e = 0; e < 4; e++) {
                    int rr = row + (e >> 1) * 8;
                    int cc = col + (e & 1);
                    int key = kid[cc];
                    int sg = qb * 64 + rr;
                    float val;
                    if (key >= SEQ) val = -INFINITY;
                    else val = (key <= sg) ? acc[nt][e] * SCALE : -1e30f;
                    ss[rr * 36 + cc] = val;
                }
            }
        }
        __syncthreads();

        float tm0 = m0, tm1 = m1;
#pragma unroll
        for (int j = 0; j < 32; j++) {
            tm0 = fmaxf(tm0, ss[qi0 * 36 + j]);
            tm1 = fmaxf(tm1, ss[qi1 * 36 + j]);
        }
        float c0 = expf(m0 - tm0);
        float c1 = expf(m1 - tm1);
        m0 = tm0; m1 = tm1;
        lsum0 *= c0; lsum1 *= c1;
#pragma unroll
        for (int i = 0; i < 8; i++) { out0[i] *= c0; out1[i] *= c1; }
        __syncthreads();

#pragma unroll
        for (int j = 0; j < 4; j++) {
            int jj = g * 4 + j;
            ss[qi0 * 36 + jj] = expf(ss[qi0 * 36 + jj] - m0);
            ss[qi1 * 36 + jj] = expf(ss[qi1 * 36 + jj] - m1);
        }
        __syncthreads();

        float ps0 = 0.f, ps1 = 0.f;
#pragma unroll
        for (int j = 0; j < 32; j++) {
            float p0 = ss[qi0 * 36 + j];
            float p1 = ss[qi1 * 36 + j];
            ps0 += p0; ps1 += p1;
            float4 va = *(float4*)&vs[j * 68 + g * 8];
            float4 vb = *(float4*)&vs[j * 68 + g * 8 + 4];
            out0[0] += p0 * va.x; out0[1] += p0 * va.y; out0[2] += p0 * va.z; out0[3] += p0 * va.w;
            out0[4] += p0 * vb.x; out0[5] += p0 * vb.y; out0[6] += p0 * vb.z; out0[7] += p0 * vb.w;
            out1[0] += p1 * va.x; out1[1] += p1 * va.y; out1[2] += p1 * va.z; out1[3] += p1 * va.w;
            out1[4] += p1 * vb.x; out1[5] += p1 * vb.y; out1[6] += p1 * vb.z; out1[7] += p1 * vb.w;
        }
        lsum0 += ps0;
        lsum1 += ps1;
    }

    if (m0 < -5e29f) {
        lsum0 = (float)NKEY;
#pragma unroll
        for (int i = 0; i < 8; i++) out0[i] = 0.f;
        for (int j = 0; j < NKEYP; j++) {
            if (keys[h * NKEYP + j] < SEQ) {
                const float* vr = &vsp[((size_t)h * NKEYP + j) * HD + g * 8];
#pragma unroll
                for (int i = 0; i < 8; i++) out0[i] += vr[i];
            }
        }
    }
    if (m1 < -5e29f) {
        lsum1 = (float)NKEY;
#pragma unroll
        for (int i = 0; i < 8; i++) out1[i] = 0.f;
        for (int j = 0; j < NKEYP; j++) {
            if (keys[h * NKEYP + j] < SEQ) {
                const float* vr = &vsp[((size_t)h * NKEYP + j) * HD + g * 8];
#pragma unroll
                for (int i = 0; i < 8; i++) out1[i] += vr[i];
            }
        }
    }

    float inv0 = 1.f / lsum0;
    float inv1 = 1.f / lsum1;
#pragma unroll
    for (int i = 0; i < 8; i++) {
        attout[(size_t)sglob0 * DIM + h * HD + g * 8 + i] = __float2half_rn(out0[i] * inv0);
        attout[(size_t)sglob1 * DIM + h * HD + g * 8 + i] = __float2half_rn(out1[i] * inv1);
    }
}

// --------------------------------- launch --------------------------------
extern "C" void kernel_launch(void* const* d_in, const int* in_sizes, int n_in,
                              void* d_out, int out_size) {
    const float* x    = (const float*)d_in[0];
    const float* fcos = (const float*)d_in[1];
    const float* fsin = (const float*)d_in[2];
    const float* wq   = (const float*)d_in[3];
    const float* wk   = (const float*)d_in[4];
    const float* wv   = (const float*)d_in[5];
    const float* wo   = (const float*)d_in[6];
    float* out = (float*)d_out;

    float *q, *q64, *q64p, *wkv, *kv, *probs, *vert, *dgp, *ksp, *vsp;
    int* keys;
    __half *xh, *atth, *wqt, *wot;
    cudaGetSymbolAddress((void**)&q, g_q);
    cudaGetSymbolAddress((void**)&q64, g_q64);
    cudaGetSymbolAddress((void**)&q64p, g_q64p);
    cudaGetSymbolAddress((void**)&wkv, g_wkv);
    cudaGetSymbolAddress((void**)&kv, g_kv);
    cudaGetSymbolAddress((void**)&probs, g_probs);
    cudaGetSymbolAddress((void**)&vert, g_vert);
    cudaGetSymbolAddress((void**)&dgp, g_diag);
    cudaGetSymbolAddress((void**)&keys, g_keys);
    cudaGetSymbolAddress((void**)&ksp, g_ksp);
    cudaGetSymbolAddress((void**)&vsp, g_vsp);
    cudaGetSymbolAddress((void**)&xh, g_xh);
    cudaGetSymbolAddress((void**)&atth, g_atth);
    cudaGetSymbolAddress((void**)&wqt, g_wqt);
    cudaGetSymbolAddress((void**)&wot, g_wot);

    // prep: fp16 conversions + weight transposes
    f2h_kernel<<<(SEQ * DIM / 4 + 255) / 256, 256>>>(x, xh, SEQ * DIM / 4);
    transp_half<<<dim3(DIM / 32, DIM / 32), dim3(32, 8)>>>(wq, wqt);
    transp_half<<<dim3(DIM / 32, DIM / 32), dim3(32, 8)>>>(wo, wot);
    concat_wkv<<<DIM, 256>>>(wk, wv, wkv);

    // projections: q fp16 TC (cp.async pipelined), kv fused 3xTF32
    gemm_f16<<<dim3(DIM / 128, SEQ / 128), 256>>>(xh, wqt, q, SEQ, DIM, DIM);
    gemm_tf32x3<<<dim3(KVW / 128, SEQ / 128), 256>>>(x, wkv, kv, SEQ, KVW, DIM);

    // exact fp32 q rows 0..63
    qproj_part<<<dim3(16, 8, 8), 128>>>(x, wq, q64p);
    qproj_red<<<(ESTQ * DIM + 255) / 256, 256>>>(q64p, q64);

    // RoPE
    {
        int tq = SEQ * NH * 32;
        rope_kernel<<<(tq + 255) / 256, 256>>>(q, fcos, fsin, NH, DIM, tq);
        int tk = SEQ * NKV * 32;
        rope_kernel<<<(tk + 255) / 256, 256>>>(kv, fcos, fsin, NKV, KVW, tk);
        int tq64 = ESTQ * NH * 32;
        rope_kernel<<<(tq64 + 255) / 256, 256>>>(q64, fcos, fsin, NH, DIM, tq64);
    }

    // estimation
    est_score<<<dim3(SEQ / 64, NH), 256>>>(q64, kv, probs);
    est_norm<<<dim3(ESTQ, NH), 256>>>(probs);

    vertical_kernel<<<(NH * SEQ) / 256, 256>>>(probs, vert);
    diag_kernel<<<(NH * SEQ) / 256, 256>>>(probs, dgp);

    topk2_kernel<<<64, 512>>>(vert, dgp, keys);
    sortkeys_kernel<<<NH, 256>>>(keys);

    gather_kernel<<<NH * NKEYP, 64>>>(kv, keys, ksp, vsp);

    {
        size_t spbytes = (size_t)SP_WORDS * 4;
        cudaFuncSetAttribute(spattn_kernel,
                             cudaFuncAttributeMaxDynamicSharedMemorySize, (int)spbytes);
        spattn_kernel<<<dim3(SEQ / 64, NH), 256, spbytes>>>(q, ksp, vsp, keys, atth);
    }

    // output projection: fp16 TC (cp.async pipelined)
    gemm_f16<<<dim3(DIM / 128, SEQ / 128), 256>>>(atth, wot, out, SEQ, DIM, DIM);
}

// round 11
// speedup vs baseline: 2.9924x; 1.0012x over previous
#include <cuda_runtime.h>
#include <cuda_fp16.h>
#include <math.h>
#include <stdint.h>

#define SEQ   4096
#define DIM   2048
#define NH    32
#define NKV   8
#define HD    64
#define ESTQ  64
#define VSZ   300
#define SSZ   800
#define NKEY  1100
#define NKEYP 1152
#define SCALE 0.125f
#define PADKEY 0x3FFFFFFF
#define KVW   1024

// ---------------- device scratch ----------------
__device__ float g_q[SEQ * DIM];
__device__ float g_q64[ESTQ * DIM];
__device__ float g_q64p[8 * ESTQ * DIM];
__device__ float g_kv[SEQ * KVW];
__device__ float g_probs[NH * ESTQ * SEQ];
__device__ float g_vert[NH * SEQ];
__device__ float g_diag[NH * SEQ];
__device__ int   g_keys[NH * NKEYP];
__device__ float g_ksp[NH * NKEYP * HD];
__device__ float g_vsp[NH * NKEYP * HD];
__device__ __half g_xh[SEQ * DIM];      // x in fp16
__device__ __half g_atth[SEQ * DIM];    // attention output in fp16
__device__ __half g_wqt[DIM * DIM];     // wq transposed [n][k] fp16
__device__ __half g_wot[DIM * DIM];     // wo transposed [n][k] fp16
__device__ uint32_t g_xtH[SEQ * DIM];   // x tf32 hi
__device__ uint32_t g_xtL[SEQ * DIM];   // x tf32 lo
__device__ uint32_t g_wkvH[DIM * KVW];  // [wk|wv] tf32 hi  [k][n]
__device__ uint32_t g_wkvL[DIM * KVW];  // [wk|wv] tf32 lo

// ---------------- helpers ------------------------------------------------
__device__ __forceinline__ uint32_t f2tf32(float f) {
    uint32_t r;
    asm("cvt.rna.tf32.f32 %0, %1;" : "=r"(r) : "f"(f));
    return r;
}

__device__ __forceinline__ void mma_tf32(float c[4], const uint32_t a[4],
                                         uint32_t b0, uint32_t b1) {
    asm volatile(
        "mma.sync.aligned.m16n8k8.row.col.f32.tf32.tf32.f32 "
        "{%0,%1,%2,%3}, {%4,%5,%6,%7}, {%8,%9}, {%0,%1,%2,%3};\n"
        : "+f"(c[0]), "+f"(c[1]), "+f"(c[2]), "+f"(c[3])
        : "r"(a[0]), "r"(a[1]), "r"(a[2]), "r"(a[3]), "r"(b0), "r"(b1));
}

__device__ __forceinline__ void mma_f16(float c[4], const uint32_t a[4],
                                        uint32_t b0, uint32_t b1) {
    asm volatile(
        "mma.sync.aligned.m16n8k16.row.col.f32.f16.f16.f32 "
        "{%0,%1,%2,%3}, {%4,%5,%6,%7}, {%8,%9}, {%0,%1,%2,%3};\n"
        : "+f"(c[0]), "+f"(c[1]), "+f"(c[2]), "+f"(c[3])
        : "r"(a[0]), "r"(a[1]), "r"(a[2]), "r"(a[3]), "r"(b0), "r"(b1));
}

__device__ __forceinline__ uint32_t smem_u32(const void* p) {
    uint32_t a;
    asm("{ .reg .u64 t; cvta.to.shared.u64 t, %1; cvt.u32.u64 %0, t; }" : "=r"(a) : "l"(p));
    return a;
}

// ================= fp16 k16 GEMM with cp.async double buffering ===========
#define AF_ST 20

__global__ __launch_bounds__(256) void gemm_f16(const __half* __restrict__ A,
                                                const __half* __restrict__ Bt,
                                                float* __restrict__ C,
                                                int M, int N, int K) {
    __shared__ uint32_t As[2][128 * AF_ST];
    __shared__ uint32_t Bs[2][128 * AF_ST];
    int tid = threadIdx.x;
    int lane = tid & 31;
    int warp = tid >> 5;
    int wm = warp & 3;
    int wn = warp >> 2;
    int row0 = blockIdx.y * 128;
    int col0 = blockIdx.x * 128;
    int lr = lane >> 2;
    int lc = lane & 3;

    uint32_t asb[2], bsb[2];
    asb[0] = smem_u32(&As[0][0]);
    asb[1] = smem_u32(&As[1][0]);
    bsb[0] = smem_u32(&Bs[0][0]);
    bsb[1] = smem_u32(&Bs[1][0]);

    float acc[2][8][4];
#pragma unroll
    for (int mi = 0; mi < 2; mi++)
#pragma unroll
        for (int nj = 0; nj < 8; nj++)
#pragma unroll
            for (int e = 0; e < 4; e++) acc[mi][nj][e] = 0.f;

    int r_ld = tid >> 2;
    int j_ld = tid & 3;

    {
#pragma unroll
        for (int i = 0; i < 2; i++) {
            int r = r_ld + i * 64;
            uint32_t da = asb[0] + (uint32_t)(r * AF_ST + j_ld * 4) * 4;
            const __half* sa = A + (size_t)(row0 + r) * K + j_ld * 8;
            asm volatile("cp.async.ca.shared.global [%0], [%1], 16;" :: "r"(da), "l"(sa));
            uint32_t db = bsb[0] + (uint32_t)(r * AF_ST + j_ld * 4) * 4;
            const __half* sb = Bt + (size_t)(col0 + r) * K + j_ld * 8;
            asm volatile("cp.async.ca.shared.global [%0], [%1], 16;" :: "r"(db), "l"(sb));
        }
        asm volatile("cp.async.commit_group;");
    }

    int KC = K >> 5;
    for (int c = 0; c < KC; c++) {
        int buf = c & 1;
        if (c + 1 < KC) {
            int k0 = (c + 1) << 5;
            int nb = buf ^ 1;
#pragma unroll
            for (int i = 0; i < 2; i++) {
                int r = r_ld + i * 64;
                uint32_t da = asb[nb] + (uint32_t)(r * AF_ST + j_ld * 4) * 4;
                const __half* sa = A + (size_t)(row0 + r) * K + k0 + j_ld * 8;
                asm volatile("cp.async.ca.shared.global [%0], [%1], 16;" :: "r"(da), "l"(sa));
                uint32_t db = bsb[nb] + (uint32_t)(r * AF_ST + j_ld * 4) * 4;
                const __half* sb = Bt + (size_t)(col0 + r) * K + k0 + j_ld * 8;
                asm volatile("cp.async.ca.shared.global [%0], [%1], 16;" :: "r"(db), "l"(sb));
            }
            asm volatile("cp.async.commit_group;");
            asm volatile("cp.async.wait_group 1;");
        } else {
            asm volatile("cp.async.wait_group 0;");
        }
        __syncthreads();

        const uint32_t* Ab = As[buf];
        const uint32_t* Bb = Bs[buf];
#pragma unroll
        for (int ks = 0; ks < 2; ks++) {
            int kb = ks * 8;
            uint32_t a[2][4];
#pragma unroll
            for (int mi = 0; mi < 2; mi++) {
                int ra = wm * 32 + mi * 16 + lr;
                a[mi][0] = Ab[ra * AF_ST + kb + lc];
                a[mi][1] = Ab[(ra + 8) * AF_ST + kb + lc];
                a[mi][2] = Ab[ra * AF_ST + kb + lc + 4];
                a[mi][3] = Ab[(ra + 8) * AF_ST + kb + lc + 4];
            }
#pragma unroll
            for (int nj = 0; nj < 8; nj++) {
                int col = wn * 64 + nj * 8 + lr;
                uint32_t b0 = Bb[col * AF_ST + kb + lc];
                uint32_t b1 = Bb[col * AF_ST + kb + lc + 4];
                mma_f16(acc[0][nj], a[0], b0, b1);
                mma_f16(acc[1][nj], a[1], b0, b1);
            }
        }
        __syncthreads();
    }

#pragma unroll
    for (int mi = 0; mi < 2; mi++) {
        int row = row0 + wm * 32 + mi * 16 + lr;
#pragma unroll
        for (int nj = 0; nj < 8; nj++) {
            int col = col0 + wn * 64 + nj * 8 + 2 * lc;
            float* cp0 = C + (size_t)row * N + col;
            cp0[0] = acc[mi][nj][0];
            cp0[1] = acc[mi][nj][1];
            float* cp1 = C + (size_t)(row + 8) * N + col;
            cp1[0] = acc[mi][nj][2];
            cp1[1] = acc[mi][nj][3];
        }
    }
}

// ================= pipelined 3xTF32 GEMM (pre-split hi/lo inputs) ==========
// AH/AL: u32 tf32 [M][K]; BH/BL: u32 tf32 [K][N]; C fp32. BK=16.
#define AS_ST 20
#define BS_ST 132
#define STG_A (128 * AS_ST)
#define STG_B (16 * BS_ST)
#define STG_WORDS (2 * STG_A + 2 * STG_B)

__global__ __launch_bounds__(256) void gemm_tf32x3p(const uint32_t* __restrict__ AH,
                                                    const uint32_t* __restrict__ AL,
                                                    const uint32_t* __restrict__ BH,
                                                    const uint32_t* __restrict__ BL,
                                                    float* __restrict__ C,
                                                    int M, int N, int K) {
    extern __shared__ uint32_t sm[];
    uint32_t base = smem_u32(sm);
    int tid = threadIdx.x;
    int lane = tid & 31;
    int warp = tid >> 5;
    int wm = warp & 3;
    int wn = warp >> 2;
    int row0 = blockIdx.y * 128;
    int col0 = blockIdx.x * 128;
    int lr = lane >> 2;
    int lc = lane & 3;

    float acc[2][8][4];
#pragma unroll
    for (int mi = 0; mi < 2; mi++)
#pragma unroll
        for (int nj = 0; nj < 8; nj++)
#pragma unroll
            for (int e = 0; e < 4; e++) acc[mi][nj][e] = 0.f;

    // issue one stage's loads: A (hi+lo) 2 chunks each, B (hi+lo) 2 chunks each
    auto issue = [&](int stage, int k0) {
        uint32_t sb = base + (uint32_t)stage * STG_WORDS * 4;
#pragma unroll
        for (int i = 0; i < 2; i++) {
            int f = tid * 2 + i;        // 0..511
            int r = f >> 2, c4 = (f & 3) * 4;
            uint32_t off = (uint32_t)(r * AS_ST + c4) * 4;
            const uint32_t* sa = AH + (size_t)(row0 + r) * K + k0 + c4;
            asm volatile("cp.async.ca.shared.global [%0], [%1], 16;" :: "r"(sb + off), "l"(sa));
            const uint32_t* sl = AL + (size_t)(row0 + r) * K + k0 + c4;
            asm volatile("cp.async.ca.shared.global [%0], [%1], 16;"
                         :: "r"(sb + (uint32_t)STG_A * 4 + off), "l"(sl));
            int rb = f >> 5, cb = (f & 31) * 4;
            uint32_t offb = (uint32_t)(rb * BS_ST + cb) * 4;
            const uint32_t* tb = BH + (size_t)(k0 + rb) * N + col0 + cb;
            asm volatile("cp.async.ca.shared.global [%0], [%1], 16;"
                         :: "r"(sb + (uint32_t)(2 * STG_A) * 4 + offb), "l"(tb));
            const uint32_t* tl = BL + (size_t)(k0 + rb) * N + col0 + cb;
            asm volatile("cp.async.ca.shared.global [%0], [%1], 16;"
                         :: "r"(sb + (uint32_t)(2 * STG_A + STG_B) * 4 + offb), "l"(tl));
        }
        asm volatile("cp.async.commit_group;");
    };

    issue(0, 0);

    int KC = K >> 4;
    for (int c = 0; c < KC; c++) {
        int buf = c & 1;
        if (c + 1 < KC) {
            issue(buf ^ 1, (c + 1) << 4);
            asm volatile("cp.async.wait_group 1;");
        } else {
            asm volatile("cp.async.wait_group 0;");
        }
        __syncthreads();

        const uint32_t* AsH = sm + (size_t)buf * STG_WORDS;
        const uint32_t* AsL = AsH + STG_A;
        const uint32_t* BsH = AsH + 2 * STG_A;
        const uint32_t* BsL = BsH + STG_B;
#pragma unroll
        for (int ks = 0; ks < 2; ks++) {
            int kb = ks * 8;
            uint32_t aH[2][4], aL[2][4];
#pragma unroll
            for (int mi = 0; mi < 2; mi++) {
                int r = wm * 32 + mi * 16 + lr;
                aH[mi][0] = AsH[r * AS_ST + kb + lc];
                aH[mi][1] = AsH[(r + 8) * AS_ST + kb + lc];
                aH[mi][2] = AsH[r * AS_ST + kb + lc + 4];
                aH[mi][3] = AsH[(r + 8) * AS_ST + kb + lc + 4];
                aL[mi][0] = AsL[r * AS_ST + kb + lc];
                aL[mi][1] = AsL[(r + 8) * AS_ST + kb + lc];
                aL[mi][2] = AsL[r * AS_ST + kb + lc + 4];
                aL[mi][3] = AsL[(r + 8) * AS_ST + kb + lc + 4];
            }
#pragma unroll
            for (int nj = 0; nj < 8; nj++) {
                int cc = wn * 64 + nj * 8 + lr;
                uint32_t b0h = BsH[(kb + lc) * BS_ST + cc];
                uint32_t b1h = BsH[(kb + lc + 4) * BS_ST + cc];
                uint32_t b0l = BsL[(kb + lc) * BS_ST + cc];
                uint32_t b1l = BsL[(kb + lc + 4) * BS_ST + cc];
#pragma unroll
                for (int mi = 0; mi < 2; mi++) {
                    mma_tf32(acc[mi][nj], aH[mi], b0h, b1h);
                    mma_tf32(acc[mi][nj], aH[mi], b0l, b1l);
                    mma_tf32(acc[mi][nj], aL[mi], b0h, b1h);
                }
            }
        }
        __syncthreads();
    }

#pragma unroll
    for (int mi = 0; mi < 2; mi++) {
        int row = row0 + wm * 32 + mi * 16 + lr;
#pragma unroll
        for (int nj = 0; nj < 8; nj++) {
            int col = col0 + wn * 64 + nj * 8 + 2 * lc;
            float* cp0 = C + (size_t)row * N + col;
            cp0[0] = acc[mi][nj][0];
            cp0[1] = acc[mi][nj][1];
            float* cp1 = C + (size_t)(row + 8) * N + col;
            cp1[0] = acc[mi][nj][2];
            cp1[1] = acc[mi][nj][3];
        }
    }
}

// ---------------- prep kernels ---------------------------------------------
__global__ void f2h_kernel(const float* __restrict__ a, __half* __restrict__ h, int n4) {
    int i = blockIdx.x * 256 + threadIdx.x;
    if (i >= n4) return;
    float4 v = ((const float4*)a)[i];
    __half2 h0 = __floats2half2_rn(v.x, v.y);
    __half2 h1 = __floats2half2_rn(v.z, v.w);
    ((uint2*)h)[i] = make_uint2(*(uint32_t*)&h0, *(uint32_t*)&h1);
}

// split fp32 -> tf32 hi/lo (identical math to the old in-GEMM conversion)
__global__ void split_tf32(const float* __restrict__ a, uint32_t* __restrict__ hi,
                           uint32_t* __restrict__ lo, int n4) {
    int i = blockIdx.x * 256 + threadIdx.x;
    if (i >= n4) return;
    float4 v = ((const float4*)a)[i];
    uint32_t h0 = f2tf32(v.x), h1 = f2tf32(v.y), h2 = f2tf32(v.z), h3 = f2tf32(v.w);
    uint4 hh = make_uint4(h0, h1, h2, h3);
    uint4 ll = make_uint4(f2tf32(v.x - __uint_as_float(h0)),
                          f2tf32(v.y - __uint_as_float(h1)),
                          f2tf32(v.z - __uint_as_float(h2)),
                          f2tf32(v.w - __uint_as_float(h3)));
    ((uint4*)hi)[i] = hh;
    ((uint4*)lo)[i] = ll;
}

// concat wk|wv and split to tf32 hi/lo in one pass
__global__ void concat_split_kernel(const float* __restrict__ wk, const float* __restrict__ wv,
                                    uint32_t* __restrict__ hi, uint32_t* __restrict__ lo) {
    int i = blockIdx.x * 256 + threadIdx.x;  // over DIM*KVW/4 float4s
    int r = i >> 8;          // k row
    int c4 = i & 255;        // float4 col within 1024
    float4 v = (c4 < 128) ? ((const float4*)wk)[r * 128 + c4]
                          : ((const float4*)wv)[r * 128 + (c4 - 128)];
    uint32_t h0 = f2tf32(v.x), h1 = f2tf32(v.y), h2 = f2tf32(v.z), h3 = f2tf32(v.w);
    ((uint4*)hi)[i] = make_uint4(h0, h1, h2, h3);
    ((uint4*)lo)[i] = make_uint4(f2tf32(v.x - __uint_as_float(h0)),
                                 f2tf32(v.y - __uint_as_float(h1)),
                                 f2tf32(v.z - __uint_as_float(h2)),
                                 f2tf32(v.w - __uint_as_float(h3)));
}

__global__ void transp_half(const float* __restrict__ w, __half* __restrict__ t) {
    __shared__ float tile[32][33];
    int bx = blockIdx.x * 32;
    int by = blockIdx.y * 32;
    int tx = threadIdx.x, ty = threadIdx.y;
    for (int i = 0; i < 32; i += 8)
        tile[ty + i][tx] = w[(size_t)(by + ty + i) * DIM + bx + tx];
    __syncthreads();
    for (int i = 0; i < 32; i += 8)
        t[(size_t)(bx + ty + i) * DIM + by + tx] = __float2half_rn(tile[tx][ty + i]);
}

// ---------------- exact fp32 q rows 0..63: split-K ---------------------------
__global__ __launch_bounds__(128) void qproj_part(const float* __restrict__ x,
                                                  const float* __restrict__ wq,
                                                  float* __restrict__ part) {
    __shared__ float xs[8][256];
    int tid = threadIdx.x;
    int col = blockIdx.x * 128 + tid;
    int r0 = blockIdx.y * 8;
    int k0 = blockIdx.z * 256;
    float acc[8];
#pragma unroll
    for (int rr = 0; rr < 8; rr++) acc[rr] = 0.f;

    for (int i = tid; i < 8 * 256; i += 128) {
        int rr = i >> 8, kk = i & 255;
        xs[rr][kk] = x[(size_t)(r0 + rr) * DIM + k0 + kk];
    }
    __syncthreads();
    for (int kk = 0; kk < 256; kk++) {
        float w = wq[(size_t)(k0 + kk) * DIM + col];
#pragma unroll
        for (int rr = 0; rr < 8; rr++) acc[rr] += xs[rr][kk] * w;
    }
#pragma unroll
    for (int rr = 0; rr < 8; rr++)
        part[(size_t)blockIdx.z * ESTQ * DIM + (size_t)(r0 + rr) * DIM + col] = acc[rr];
}

__global__ void qproj_red(const float* __restrict__ part, float* __restrict__ q64) {
    int idx = blockIdx.x * 256 + threadIdx.x;
    if (idx >= ESTQ * DIM) return;
    float s = 0.f;
#pragma unroll
    for (int ks = 0; ks < 8; ks++) s += part[(size_t)ks * ESTQ * DIM + idx];
    q64[idx] = s;
}

// ---------------- RoPE -------------------------------------------------------
__global__ void rope_kernel(float* t, const float* __restrict__ cosb,
                            const float* __restrict__ sinb, int H, int stride, int total) {
    int idx = blockIdx.x * blockDim.x + threadIdx.x;
    if (idx >= total) return;
    int d2 = idx & 31;
    int h = (idx >> 5) % H;
    int s = idx / (32 * H);
    float c = cosb[s * 32 + d2];
    float sn = sinb[s * 32 + d2];
    float* p = t + (size_t)s * stride + h * 64 + 2 * d2;
    float xr = p[0], xi = p[1];
    p[0] = xr * c - xi * sn;
    p[1] = xr * sn + xi * c;
}

// ---------------- est phase A -----------------------------------------------
__global__ __launch_bounds__(256) void est_score(const float* __restrict__ q64,
                                                 const float* __restrict__ kv,
                                                 float* __restrict__ probs) {
    __shared__ float qs[64][68];
    __shared__ float ksm[64][68];
    int tid = threadIdx.x;
    int h = blockIdx.y;
    int c0 = blockIdx.x * 64;
    int kvh = h >> 2;
    int qi = tid >> 2;
    int kg = tid & 3;

    for (int l = tid; l < 64 * 64; l += 256) {
        int r = l >> 6, d = l & 63;
        qs[r][d] = q64[(size_t)r * DIM + h * HD + d];
        ksm[r][d] = kv[(size_t)(c0 + r) * KVW + kvh * HD + d];
    }
    __syncthreads();

    float s16[16];
#pragma unroll
    for (int j = 0; j < 16; j++) s16[j] = 0.f;
#pragma unroll
    for (int d4 = 0; d4 < 16; d4++) {
        float4 q4 = *(float4*)&qs[qi][d4 * 4];
#pragma unroll
        for (int j = 0; j < 16; j++) {
            float4 k4 = *(float4*)&ksm[kg * 16 + j][d4 * 4];
            s16[j] += q4.x * k4.x + q4.y * k4.y + q4.z * k4.z + q4.w * k4.w;
        }
    }
    float* pr = probs + ((size_t)h * ESTQ + qi) * SEQ + c0 + kg * 16;
#pragma unroll
    for (int j = 0; j < 16; j++) {
        int kk = c0 + kg * 16 + j;
        float val = s16[j] * SCALE;
        if (kk >= SEQ - ESTQ && qi < kk - (SEQ - ESTQ)) val = -INFINITY;
        pr[j] = val;
    }
}

// ---------------- est phase B -------------------------------------------------
__global__ __launch_bounds__(256) void est_norm(float* __restrict__ probs) {
    int qi = blockIdx.x;
    int h = blockIdx.y;
    __shared__ float sc[SEQ];
    __shared__ float red[8];
    int tid = threadIdx.x;
    float* pr = probs + ((size_t)h * ESTQ + qi) * SEQ;

    for (int l = tid; l < SEQ / 4; l += 256)
        *(float4*)&sc[l * 4] = *(const float4*)&pr[l * 4];
    __syncthreads();

    float m = -INFINITY;
    for (int kk = tid; kk < SEQ; kk += 256) m = fmaxf(m, sc[kk]);
#pragma unroll
    for (int o = 16; o; o >>= 1) m = fmaxf(m, __shfl_xor_sync(0xFFFFFFFFu, m, o));
    if ((tid & 31) == 0) red[tid >> 5] = m;
    __syncthreads();
    if (tid == 0) {
        float mm = red[0];
#pragma unroll
        for (int i = 1; i < 8; i++) mm = fmaxf(mm, red[i]);
        red[0] = mm;
    }
    __syncthreads();
    m = red[0];
    __syncthreads();

    float s = 0.f;
    for (int kk = tid; kk < SEQ; kk += 256) {
        float e = expf(sc[kk] - m);
        sc[kk] = e;
        s += e;
    }
#pragma unroll
    for (int o = 16; o; o >>= 1) s += __shfl_xor_sync(0xFFFFFFFFu, s, o);
    if ((tid & 31) == 0) red[tid >> 5] = s;
    __syncthreads();
    if (tid == 0) {
        float ss = 0.f;
#pragma unroll
        for (int i = 0; i < 8; i++) ss += red[i];
        red[0] = ss;
    }
    __syncthreads();
    float inv = 1.f / red[0];
    for (int kk = tid; kk < SEQ; kk += 256) pr[kk] = sc[kk] * inv;
}

// ---------------- vertical / diagonal ------------------------------------------
__global__ void vertical_kernel(const float* __restrict__ probs, float* __restrict__ vert) {
    int idx = blockIdx.x * 256 + threadIdx.x;
    int h = idx >> 12;
    int kk = idx & (SEQ - 1);
    float s = 0.f;
    const float* base = probs + (size_t)h * ESTQ * SEQ + kk;
    for (int i = 0; i < ESTQ; i++) s += base[(size_t)i * SEQ];
    vert[idx] = s;
}

__global__ void diag_kernel(const float* __restrict__ probs, float* __restrict__ dg) {
    int idx = blockIdx.x * 256 + threadIdx.x;
    int h = idx >> 12;
    int jp = idx & (SEQ - 1);
    float s = 0.f;
    const float* base = probs + (size_t)h * ESTQ * SEQ;
    for (int i = 0; i < ESTQ; i++) {
        int col = i + jp - 63;
        if (col >= 0 && col < SEQ) s += base[(size_t)i * SEQ + col];
    }
    dg[idx] = s;
}

// ---------------- merged top-k ---------------------------------------------------
__global__ void topk2_kernel(const float* __restrict__ vert, const float* __restrict__ dg,
                             int* __restrict__ keys) {
    int b = blockIdx.x;
    int mode = b >> 5;
    int h = b & 31;
    const float* vals = mode ? dg : vert;
    int kcount = mode ? SSZ : VSZ;
    __shared__ unsigned long long a[SEQ];
    int tid = threadIdx.x;
    for (int i = tid; i < SEQ; i += 512) {
        unsigned u = __float_as_uint(vals[h * SEQ + i]);
        u = (u & 0x80000000u) ? ~u : (u | 0x80000000u);
        a[i] = ((unsigned long long)(~u) << 32) | (unsigned)i;
    }
    __syncthreads();
    for (int k = 2; k <= SEQ; k <<= 1) {
        for (int j = k >> 1; j > 0; j >>= 1) {
            for (int i = tid; i < SEQ; i += 512) {
                int ixj = i ^ j;
                if (ixj > i) {
                    bool up = ((i & k) == 0);
                    unsigned long long x = a[i], y = a[ixj];
                    if (up ? (x > y) : (x < y)) { a[i] = y; a[ixj] = x; }
                }
            }
            __syncthreads();
        }
    }
    if (mode == 0) {
        for (int t = tid; t < kcount; t += 512)
            keys[h * NKEYP + t] = (int)(a[t] & 0xFFFFFFFFull);
    } else {
        for (int t = tid; t < kcount; t += 512)
            keys[h * NKEYP + VSZ + t] = (SEQ - 1) - (int)(a[t] & 0xFFFFFFFFull);
        for (int t = NKEY + tid; t < NKEYP; t += 512) keys[h * NKEYP + t] = PADKEY;
    }
}

// ---------------- sort keys ascending per head ----------------------------------
__global__ __launch_bounds__(256) void sortkeys_kernel(int* __restrict__ keys) {
    int h = blockIdx.x;
    __shared__ int a[2048];
    int tid = threadIdx.x;
    for (int i = tid; i < 2048; i += 256)
        a[i] = (i < NKEYP) ? keys[h * NKEYP + i] : PADKEY;
    __syncthreads();
    for (int k = 2; k <= 2048; k <<= 1) {
        for (int j = k >> 1; j > 0; j >>= 1) {
            for (int i = tid; i < 2048; i += 256) {
                int ixj = i ^ j;
                if (ixj > i) {
                    bool up = ((i & k) == 0);
                    int x = a[i], y = a[ixj];
                    if (up ? (x > y) : (x < y)) { a[i] = y; a[ixj] = x; }
                }
            }
            __syncthreads();
        }
    }
    for (int i = tid; i < NKEYP; i += 256) keys[h * NKEYP + i] = a[i];
}

// ---------------- gather ----------------------------------------------------------
__global__ void gather_kernel(const float* __restrict__ kv,
                              const int* __restrict__ keys,
                              float* __restrict__ ksp, float* __restrict__ vsp) {
    int j = blockIdx.x;
    int h = j / NKEYP;
    int d = threadIdx.x;
    int key = keys[j];
    int kvh = h >> 2;
    float kvv = 0.f, vvv = 0.f;
    if (key < SEQ) {
        kvv = kv[(size_t)key * KVW + kvh * HD + d];
        vvv = kv[(size_t)key * KVW + 512 + kvh * HD + d];
    }
    ksp[(size_t)j * HD + d] = kvv;
    vsp[(size_t)j * HD + d] = vvv;
}

// ---------------- sparse attention (TC QK 3xTF32 + SIMT PV, fp16 out) ------------
#define QHL_ST 132
#define SP_WORDS (64 * 132 + 32 * 132 + 32 * 68 + 64 * 36 + 32)

__global__ __launch_bounds__(256) void spattn_kernel(const float* __restrict__ q,
                                                     const float* __restrict__ ksp,
                                                     const float* __restrict__ vsp,
                                                     const int* __restrict__ keys,
                                                     __half* __restrict__ attout) {
    extern __shared__ uint32_t smem[];
    uint32_t* qhl = smem;
    uint32_t* khl = qhl + 64 * 132;
    float* vs = (float*)(khl + 32 * 132);
    float* ss = vs + 32 * 68;
    int* kid = (int*)(ss + 64 * 36);

    int qb = blockIdx.x;
    int h = blockIdx.y;
    int tid = threadIdx.x;
    int lane = tid & 31;
    int warp = tid >> 5;
    int lr = lane >> 2;
    int lc = lane & 3;
    int wm = warp & 3;
    int wn = warp >> 2;
    int qp = tid >> 3;
    int g = tid & 7;
    int qi0 = qp, qi1 = qp + 32;
    int sglob0 = qb * 64 + qi0;
    int sglob1 = qb * 64 + qi1;
    int qbmax = qb * 64 + 63;

    for (int l = tid; l < 64 * 16; l += 256) {
        int r = l >> 4, c4 = (l & 15) * 4;
        float4 v = *(const float4*)&q[(size_t)(qb * 64 + r) * DIM + h * HD + c4];
        uint32_t* dh = &qhl[r * QHL_ST + c4];
        uint32_t h0 = f2tf32(v.x), h1 = f2tf32(v.y), h2 = f2tf32(v.z), h3 = f2tf32(v.w);
        dh[0] = h0; dh[1] = h1; dh[2] = h2; dh[3] = h3;
        dh[64] = f2tf32(v.x - __uint_as_float(h0));
        dh[65] = f2tf32(v.y - __uint_as_float(h1));
        dh[66] = f2tf32(v.z - __uint_as_float(h2));
        dh[67] = f2tf32(v.w - __uint_as_float(h3));
    }

    float m0 = -INFINITY, m1 = -INFINITY, lsum0 = 0.f, lsum1 = 0.f;
    float out0[8], out1[8];
#pragma unroll
    for (int i = 0; i < 8; i++) { out0[i] = 0.f; out1[i] = 0.f; }

    for (int t = 0; t < NKEYP / 32; t++) {
        __syncthreads();
        if (tid < 32) kid[tid] = keys[h * NKEYP + t * 32 + tid];
        __syncthreads();
        if (kid[0] > qbmax) continue;

        for (int l = tid; l < 32 * 16; l += 256) {
            int r = l >> 4, c4 = (l & 15) * 4;
            float4 kv = *(const float4*)&ksp[((size_t)h * NKEYP + t * 32 + r) * HD + c4];
            uint32_t* dh = &khl[r * QHL_ST + c4];
            uint32_t h0 = f2tf32(kv.x), h1 = f2tf32(kv.y), h2 = f2tf32(kv.z), h3 = f2tf32(kv.w);
            dh[0] = h0; dh[1] = h1; dh[2] = h2; dh[3] = h3;
            dh[64] = f2tf32(kv.x - __uint_as_float(h0));
            dh[65] = f2tf32(kv.y - __uint_as_float(h1));
            dh[66] = f2tf32(kv.z - __uint_as_float(h2));
            dh[67] = f2tf32(kv.w - __uint_as_float(h3));
            *(float4*)&vs[r * 68 + c4] =
                *(const float4*)&vsp[((size_t)h * NKEYP + t * 32 + r) * HD + c4];
        }
        __syncthreads();

        {
            float acc[2][4];
#pragma unroll
            for (int nt = 0; nt < 2; nt++)
#pragma unroll
                for (int e = 0; e < 4; e++) acc[nt][e] = 0.f;
#pragma unroll
            for (int ksI = 0; ksI < 8; ksI++) {
                int kb = ksI * 8;
                int ra = wm * 16 + lr;
                uint32_t aH[4], aL[4];
                aH[0] = qhl[ra * QHL_ST + kb + lc];
                aH[1] = qhl[(ra + 8) * QHL_ST + kb + lc];
                aH[2] = qhl[ra * QHL_ST + kb + lc + 4];
                aH[3] = qhl[(ra + 8) * QHL_ST + kb + lc + 4];
                aL[0] = qhl[ra * QHL_ST + 64 + kb + lc];
                aL[1] = qhl[(ra + 8) * QHL_ST + 64 + kb + lc];
                aL[2] = qhl[ra * QHL_ST + 64 + kb + lc + 4];
                aL[3] = qhl[(ra + 8) * QHL_ST + 64 + kb + lc + 4];
#pragma unroll
                for (int nt = 0; nt < 2; nt++) {
                    int n0 = wn * 16 + nt * 8;
                    uint32_t b0h = khl[(n0 + lr) * QHL_ST + kb + lc];
                    uint32_t b1h = khl[(n0 + lr) * QHL_ST + kb + lc + 4];
                    uint32_t b0l = khl[(n0 + lr) * QHL_ST + 64 + kb + lc];
                    uint32_t b1l = khl[(n0 + lr) * QHL_ST + 64 + kb + lc + 4];
                    mma_tf32(acc[nt], aH, b0h, b1h);
                    mma_tf32(acc[nt], aH, b0l, b1l);
                    mma_tf32(acc[nt], aL, b0h, b1h);
                }
            }
#pragma unroll
            for (int nt = 0; nt < 2; nt++) {
                int row = wm * 16 + lr;
                int col = wn * 16 + nt * 8 + 2 * lc;
#pragma unroll
                for (int e = 0; e < 4; e++) {
                    int rr = row + (e >> 1) * 8;
                    int cc = col + (e & 1);
                    int key = kid[cc];
                    int sg = qb * 64 + rr;
                    float val;
                    if (key >= SEQ) val = -INFINITY;
                    else val = (key <= sg) ? acc[nt][e] * SCALE : -1e30f;
                    ss[rr * 36 + cc] = val;
                }
            }
        }
        __syncthreads();

        float tm0 = m0, tm1 = m1;
#pragma unroll
        for (int j = 0; j < 32; j++) {
            tm0 = fmaxf(tm0, ss[qi0 * 36 + j]);
            tm1 = fmaxf(tm1, ss[qi1 * 36 + j]);
        }
        float c0 = expf(m0 - tm0);
        float c1 = expf(m1 - tm1);
        m0 = tm0; m1 = tm1;
        lsum0 *= c0; lsum1 *= c1;
#pragma unroll
        for (int i = 0; i < 8; i++) { out0[i] *= c0; out1[i] *= c1; }
        __syncthreads();

#pragma unroll
        for (int j = 0; j < 4; j++) {
            int jj = g * 4 + j;
            ss[qi0 * 36 + jj] = expf(ss[qi0 * 36 + jj] - m0);
            ss[qi1 * 36 + jj] = expf(ss[qi1 * 36 + jj] - m1);
        }
        __syncthreads();

        float ps0 = 0.f, ps1 = 0.f;
#pragma unroll
        for (int j = 0; j < 32; j++) {
            float p0 = ss[qi0 * 36 + j];
            float p1 = ss[qi1 * 36 + j];
            ps0 += p0; ps1 += p1;
            float4 va = *(float4*)&vs[j * 68 + g * 8];
            float4 vb = *(float4*)&vs[j * 68 + g * 8 + 4];
            out0[0] += p0 * va.x; out0[1] += p0 * va.y; out0[2] += p0 * va.z; out0[3] += p0 * va.w;
            out0[4] += p0 * vb.x; out0[5] += p0 * vb.y; out0[6] += p0 * vb.z; out0[7] += p0 * vb.w;
            out1[0] += p1 * va.x; out1[1] += p1 * va.y; out1[2] += p1 * va.z; out1[3] += p1 * va.w;
            out1[4] += p1 * vb.x; out1[5] += p1 * vb.y; out1[6] += p1 * vb.z; out1[7] += p1 * vb.w;
        }
        lsum0 += ps0;
        lsum1 += ps1;
    }

    if (m0 < -5e29f) {
        lsum0 = (float)NKEY;
#pragma unroll
        for (int i = 0; i < 8; i++) out0[i] = 0.f;
        for (int j = 0; j < NKEYP; j++) {
            if (keys[h * NKEYP + j] < SEQ) {
                const float* vr = &vsp[((size_t)h * NKEYP + j) * HD + g * 8];
#pragma unroll
                for (int i = 0; i < 8; i++) out0[i] += vr[i];
            }
        }
    }
    if (m1 < -5e29f) {
        lsum1 = (float)NKEY;
#pragma unroll
        for (int i = 0; i < 8; i++) out1[i] = 0.f;
        for (int j = 0; j < NKEYP; j++) {
            if (keys[h * NKEYP + j] < SEQ) {
                const float* vr = &vsp[((size_t)h * NKEYP + j) * HD + g * 8];
#pragma unroll
                for (int i = 0; i < 8; i++) out1[i] += vr[i];
            }
        }
    }

    float inv0 = 1.f / lsum0;
    float inv1 = 1.f / lsum1;
#pragma unroll
    for (int i = 0; i < 8; i++) {
        attout[(size_t)sglob0 * DIM + h * HD + g * 8 + i] = __float2half_rn(out0[i] * inv0);
        attout[(size_t)sglob1 * DIM + h * HD + g * 8 + i] = __float2half_rn(out1[i] * inv1);
    }
}

// --------------------------------- launch --------------------------------
extern "C" void kernel_launch(void* const* d_in, const int* in_sizes, int n_in,
                              void* d_out, int out_size) {
    const float* x    = (const float*)d_in[0];
    const float* fcos = (const float*)d_in[1];
    const float* fsin = (const float*)d_in[2];
    const float* wq   = (const float*)d_in[3];
    const float* wk   = (const float*)d_in[4];
    const float* wv   = (const float*)d_in[5];
    const float* wo   = (const float*)d_in[6];
    float* out = (float*)d_out;

    float *q, *q64, *q64p, *kv, *probs, *vert, *dgp, *ksp, *vsp;
    int* keys;
    __half *xh, *atth, *wqt, *wot;
    uint32_t *xtH, *xtL, *wkvH, *wkvL;
    cudaGetSymbolAddress((void**)&q, g_q);
    cudaGetSymbolAddress((void**)&q64, g_q64);
    cudaGetSymbolAddress((void**)&q64p, g_q64p);
    cudaGetSymbolAddress((void**)&kv, g_kv);
    cudaGetSymbolAddress((void**)&probs, g_probs);
    cudaGetSymbolAddress((void**)&vert, g_vert);
    cudaGetSymbolAddress((void**)&dgp, g_diag);
    cudaGetSymbolAddress((void**)&keys, g_keys);
    cudaGetSymbolAddress((void**)&ksp, g_ksp);
    cudaGetSymbolAddress((void**)&vsp, g_vsp);
    cudaGetSymbolAddress((void**)&xh, g_xh);
    cudaGetSymbolAddress((void**)&atth, g_atth);
    cudaGetSymbolAddress((void**)&wqt, g_wqt);
    cudaGetSymbolAddress((void**)&wot, g_wot);
    cudaGetSymbolAddress((void**)&xtH, g_xtH);
    cudaGetSymbolAddress((void**)&xtL, g_xtL);
    cudaGetSymbolAddress((void**)&wkvH, g_wkvH);
    cudaGetSymbolAddress((void**)&wkvL, g_wkvL);

    // prep
    f2h_kernel<<<(SEQ * DIM / 4 + 255) / 256, 256>>>(x, xh, SEQ * DIM / 4);
    split_tf32<<<(SEQ * DIM / 4 + 255) / 256, 256>>>(x, xtH, xtL, SEQ * DIM / 4);
    concat_split_kernel<<<(DIM * KVW / 4 + 255) / 256, 256>>>(wk, wv, wkvH, wkvL);
    transp_half<<<dim3(DIM / 32, DIM / 32), dim3(32, 8)>>>(wq, wqt);
    transp_half<<<dim3(DIM / 32, DIM / 32), dim3(32, 8)>>>(wo, wot);

    // projections: q fp16 TC (pipelined), kv pipelined 3xTF32 (bit-identical math)
    gemm_f16<<<dim3(DIM / 128, SEQ / 128), 256>>>(xh, wqt, q, SEQ, DIM, DIM);
    {
        size_t smb = (size_t)(2 * STG_WORDS) * 4;
        cudaFuncSetAttribute(gemm_tf32x3p, cudaFuncAttributeMaxDynamicSharedMemorySize,
                             (int)smb);
        gemm_tf32x3p<<<dim3(KVW / 128, SEQ / 128), 256, smb>>>(
            xtH, xtL, wkvH, wkvL, kv, SEQ, KVW, DIM);
    }

    // exact fp32 q rows 0..63
    qproj_part<<<dim3(16, 8, 8), 128>>>(x, wq, q64p);
    qproj_red<<<(ESTQ * DIM + 255) / 256, 256>>>(q64p, q64);

    // RoPE
    {
        int tq = SEQ * NH * 32;
        rope_kernel<<<(tq + 255) / 256, 256>>>(q, fcos, fsin, NH, DIM, tq);
        int tk = SEQ * NKV * 32;
        rope_kernel<<<(tk + 255) / 256, 256>>>(kv, fcos, fsin, NKV, KVW, tk);
        int tq64 = ESTQ * NH * 32;
        rope_kernel<<<(tq64 + 255) / 256, 256>>>(q64, fcos, fsin, NH, DIM, tq64);
    }

    // estimation
    est_score<<<dim3(SEQ / 64, NH), 256>>>(q64, kv, probs);
    est_norm<<<dim3(ESTQ, NH), 256>>>(probs);

    vertical_kernel<<<(NH * SEQ) / 256, 256>>>(probs, vert);
    diag_kernel<<<(NH * SEQ) / 256, 256>>>(probs, dgp);

    topk2_kernel<<<64, 512>>>(vert, dgp, keys);
    sortkeys_kernel<<<NH, 256>>>(keys);

    gather_kernel<<<NH * NKEYP, 64>>>(kv, keys, ksp, vsp);

    {
        size_t spbytes = (size_t)SP_WORDS * 4;
        cudaFuncSetAttribute(spattn_kernel,
                             cudaFuncAttributeMaxDynamicSharedMemorySize, (int)spbytes);
        spattn_kernel<<<dim3(SEQ / 64, NH), 256, spbytes>>>(q, ksp, vsp, keys, atth);
    }

    // output projection: fp16 TC (pipelined)
    gemm_f16<<<dim3(DIM / 128, SEQ / 128), 256>>>(atth, wot, out, SEQ, DIM, DIM);
}